// round 2
// baseline (speedup 1.0000x reference)
#include <cuda_runtime.h>
#include <math.h>
#include <float.h>

// ---------------------------------------------------------------------------
// SynGNNLayer: graph_norm -> GATv2(+self loops, edge attrs) -> residual ->
// graph_norm -> MLP(128->2048->128, relu) -> residual -> graph_norm ->
// classifier(128->64) -> graph_norm.  Outputs: src [N,64] then alpha [E+N,4].
// ---------------------------------------------------------------------------

#define NMAX 16384
#define EMAX 131072
#define TOTMAX (EMAX + NMAX)

// Scratch (static __device__ arrays: allocation-free, graph-capture safe)
static __device__ float g_h0 [NMAX * 128];
static __device__ float g_r1 [NMAX * 128];
static __device__ float g_n1 [NMAX * 128];
static __device__ float g_r2 [NMAX * 128];
static __device__ float g_n2 [NMAX * 128];
static __device__ float g_xl [NMAX * 512];
static __device__ float g_xr [NMAX * 512];
static __device__ float g_ea [TOTMAX * 32];
static __device__ float g_ef [(size_t)TOTMAX * 512];
static __device__ float g_hid[(size_t)NMAX * 2048];
static __device__ float g_easum[NMAX * 32];
static __device__ float g_deg [NMAX];
static __device__ float g_score[TOTMAX * 4];
static __device__ unsigned g_smax[NMAX * 4];
static __device__ float g_ssum[NMAX * 4];
static __device__ float g_agg [NMAX * 128];
static __device__ float g_cls [NMAX * 64];
static __device__ float g_stats[8];

// ---- monotone float <-> uint encoding for atomicMax on floats -------------
__device__ __forceinline__ unsigned f_enc(float f) {
    unsigned u = __float_as_uint(f);
    return (u & 0x80000000u) ? ~u : (u | 0x80000000u);
}
__device__ __forceinline__ float f_dec(unsigned k) {
    return (k & 0x80000000u) ? __uint_as_float(k ^ 0x80000000u)
                             : __uint_as_float(~k);
}

// ---------------------------------------------------------------------------
__global__ void k_zero(float* __restrict__ p, int n) {
    int i = blockIdx.x * blockDim.x + threadIdx.x;
    if (i < n) p[i] = 0.f;
}
__global__ void k_init_smax(unsigned* __restrict__ p, int n) {
    int i = blockIdx.x * blockDim.x + threadIdx.x;
    if (i < n) p[i] = 0x00800000u;   // f_enc(-FLT_MAX)
}

// sum + sumsq reduction (n4 = n/4 float4 elements)
__global__ void k_reduce(const float* __restrict__ x, int n4, float* __restrict__ out) {
    float s = 0.f, ss = 0.f;
    for (int i = blockIdx.x * blockDim.x + threadIdx.x; i < n4; i += gridDim.x * blockDim.x) {
        float4 v = reinterpret_cast<const float4*>(x)[i];
        s  += v.x + v.y + v.z + v.w;
        ss += v.x * v.x + v.y * v.y + v.z * v.z + v.w * v.w;
    }
    #pragma unroll
    for (int o = 16; o > 0; o >>= 1) {
        s  += __shfl_xor_sync(0xffffffffu, s,  o);
        ss += __shfl_xor_sync(0xffffffffu, ss, o);
    }
    __shared__ float shs[8], shss[8];
    int w = threadIdx.x >> 5;
    if ((threadIdx.x & 31) == 0) { shs[w] = s; shss[w] = ss; }
    __syncthreads();
    if (threadIdx.x < 8) {
        s = shs[threadIdx.x]; ss = shss[threadIdx.x];
        #pragma unroll
        for (int o = 4; o > 0; o >>= 1) {
            s  += __shfl_xor_sync(0xffu, s,  o);
            ss += __shfl_xor_sync(0xffu, ss, o);
        }
        if (threadIdx.x == 0) { atomicAdd(out, s); atomicAdd(out + 1, ss); }
    }
}

// graph_norm apply: y = (x - mu)/(std + 1e-5) * w[c] + b[c]
__global__ void k_norm(const float* __restrict__ x, float* __restrict__ y,
                       const float* __restrict__ w, const float* __restrict__ b,
                       const float* __restrict__ st, int Dmask, int n, float invn) {
    int i = blockIdx.x * blockDim.x + threadIdx.x;
    if (i >= n) return;
    float mu  = st[0] * invn;
    float var = st[1] * invn - mu * mu;
    float inv = 1.f / (sqrtf(fmaxf(var, 0.f)) + 1e-5f);
    int c = i & Dmask;
    y[i] = (x[i] - mu) * inv * w[c] + b[c];
}

// ---- tiled fp32 GEMM: C[M,Nn] = A[M,K] @ W[Nn,K]^T (+epilogue) ------------
// EPI: 0 none, 1 +bias, 2 +bias,relu, 3 +bias,+res
template <int EPI>
__global__ void k_gemm(const float* __restrict__ A, const float* __restrict__ W,
                       const float* __restrict__ bias, const float* __restrict__ res,
                       float* __restrict__ C, int M, int Nn, int K) {
    __shared__ float As[16][64];
    __shared__ float Bs[16][64];
    int tid = threadIdx.x;
    int tx = tid & 15, ty = tid >> 4;
    int m0 = blockIdx.y * 64, n0 = blockIdx.x * 64;
    float acc[4][4] = {};
    for (int kk = 0; kk < K; kk += 16) {
        #pragma unroll
        for (int t = 0; t < 4; t++) {
            int e = tid + t * 256;
            int m = e >> 4, k = e & 15;
            As[k][m] = A[(long)(m0 + m) * K + kk + k];
            Bs[k][m] = W[(long)(n0 + m) * K + kk + k];
        }
        __syncthreads();
        #pragma unroll
        for (int k = 0; k < 16; k++) {
            float a[4], bb[4];
            #pragma unroll
            for (int i = 0; i < 4; i++) a[i]  = As[k][ty * 4 + i];
            #pragma unroll
            for (int j = 0; j < 4; j++) bb[j] = Bs[k][tx * 4 + j];
            #pragma unroll
            for (int i = 0; i < 4; i++)
                #pragma unroll
                for (int j = 0; j < 4; j++) acc[i][j] += a[i] * bb[j];
        }
        __syncthreads();
    }
    #pragma unroll
    for (int i = 0; i < 4; i++) {
        long m = m0 + ty * 4 + i;
        #pragma unroll
        for (int j = 0; j < 4; j++) {
            int n = n0 + tx * 4 + j;
            float v = acc[i][j];
            if (EPI >= 1) v += bias[n];
            if (EPI == 2) v = fmaxf(v, 0.f);
            if (EPI == 3) v += res[m * Nn + n];
            C[m * Nn + n] = v;
        }
    }
}

// ---- edge-side kernels ----------------------------------------------------
__global__ void k_fill_ea(const float* __restrict__ edge_attr, int n) {
    int i = blockIdx.x * blockDim.x + threadIdx.x;
    if (i < n) g_ea[i] = edge_attr[i];
}

// deg + incoming edge_attr sums (warp per edge; lane == channel)
__global__ void k_degsum(const float* __restrict__ edge_attr,
                         const int* __restrict__ ei, int E) {
    int e = blockIdx.x * 8 + (threadIdx.x >> 5);
    if (e >= E) return;
    int l = threadIdx.x & 31;
    int dst = ei[E + e];
    atomicAdd(&g_easum[dst * 32 + l], edge_attr[e * 32 + l]);
    if (l == 0) atomicAdd(&g_deg[dst], 1.f);
}

// self-loop edge attrs = mean of incoming (0 for isolated)
__global__ void k_eamean(int E, int N) {
    int i = blockIdx.x * blockDim.x + threadIdx.x;
    if (i >= N * 32) return;
    int nid = i >> 5;
    float d = fmaxf(g_deg[nid], 1.f);
    g_ea[(long)(E + nid) * 32 + (i & 31)] = g_easum[i] / d;
}

// score[e,h] = sum_c att[h,c]*leaky(xl[src]+xr[dst]+ef[e]); + atomicMax per dst
__global__ void k_score(const int* __restrict__ ei, const float* __restrict__ att,
                        int E, int N) {
    int tot = E + N;
    int e = blockIdx.x * 8 + (threadIdx.x >> 5);
    if (e >= tot) return;
    int l = threadIdx.x & 31;
    int s = (e < E) ? ei[e]     : (e - E);
    int d = (e < E) ? ei[E + e] : (e - E);
    const float4* xl4 = reinterpret_cast<const float4*>(g_xl + (long)s * 512);
    const float4* xr4 = reinterpret_cast<const float4*>(g_xr + (long)d * 512);
    const float4* ef4 = reinterpret_cast<const float4*>(g_ef + (long)e * 512);
    const float4* at4 = reinterpret_cast<const float4*>(att);
    float sc[4];
    #pragma unroll
    for (int h = 0; h < 4; h++) {
        int idx = h * 32 + l;
        float4 a = xl4[idx], b = xr4[idx], c = ef4[idx], w = at4[idx];
        float zx = a.x + b.x + c.x; zx = zx > 0.f ? zx : 0.2f * zx;
        float zy = a.y + b.y + c.y; zy = zy > 0.f ? zy : 0.2f * zy;
        float zz = a.z + b.z + c.z; zz = zz > 0.f ? zz : 0.2f * zz;
        float zw = a.w + b.w + c.w; zw = zw > 0.f ? zw : 0.2f * zw;
        sc[h] = zx * w.x + zy * w.y + zz * w.z + zw * w.w;
    }
    #pragma unroll
    for (int h = 0; h < 4; h++)
        #pragma unroll
        for (int o = 16; o > 0; o >>= 1)
            sc[h] += __shfl_xor_sync(0xffffffffu, sc[h], o);
    if (l == 0) {
        #pragma unroll
        for (int h = 0; h < 4; h++) {
            g_score[(long)e * 4 + h] = sc[h];
            atomicMax(&g_smax[d * 4 + h], f_enc(sc[h]));
        }
    }
}

__global__ void k_exp(const int* __restrict__ ei, int E, int N) {
    int i = blockIdx.x * blockDim.x + threadIdx.x;
    int tot4 = (E + N) * 4;
    if (i >= tot4) return;
    int e = i >> 2, h = i & 3;
    int d = (e < E) ? ei[E + e] : (e - E);
    float m  = f_dec(g_smax[d * 4 + h]);
    float ex = expf(g_score[i] - m);
    g_score[i] = ex;
    atomicAdd(&g_ssum[d * 4 + h], ex);
}

__global__ void k_alpha(const int* __restrict__ ei, float* __restrict__ out_alpha,
                        int E, int N, int write_out) {
    int i = blockIdx.x * blockDim.x + threadIdx.x;
    int tot4 = (E + N) * 4;
    if (i >= tot4) return;
    int e = i >> 2, h = i & 3;
    int d = (e < E) ? ei[E + e] : (e - E);
    float a = g_score[i] / g_ssum[d * 4 + h];
    g_score[i] = a;
    if (write_out) out_alpha[i] = a;
}

// out[n,c] += (1/H) * sum_h alpha[e,h]*xl[src, h*128+c]   (warp per edge)
__global__ void k_agg(const int* __restrict__ ei, int E, int N) {
    int tot = E + N;
    int e = blockIdx.x * 8 + (threadIdx.x >> 5);
    if (e >= tot) return;
    int l = threadIdx.x & 31;
    int s = (e < E) ? ei[e]     : (e - E);
    int d = (e < E) ? ei[E + e] : (e - E);
    float a0 = g_score[(long)e * 4 + 0] * 0.25f;
    float a1 = g_score[(long)e * 4 + 1] * 0.25f;
    float a2 = g_score[(long)e * 4 + 2] * 0.25f;
    float a3 = g_score[(long)e * 4 + 3] * 0.25f;
    const float4* xl4 = reinterpret_cast<const float4*>(g_xl + (long)s * 512);
    float4 v0 = xl4[ 0 + l], v1 = xl4[32 + l], v2 = xl4[64 + l], v3 = xl4[96 + l];
    float rx = a0 * v0.x + a1 * v1.x + a2 * v2.x + a3 * v3.x;
    float ry = a0 * v0.y + a1 * v1.y + a2 * v2.y + a3 * v3.y;
    float rz = a0 * v0.z + a1 * v1.z + a2 * v2.z + a3 * v3.z;
    float rw = a0 * v0.w + a1 * v1.w + a2 * v2.w + a3 * v3.w;
    float* p = g_agg + d * 128 + 4 * l;
    atomicAdd(p + 0, rx); atomicAdd(p + 1, ry);
    atomicAdd(p + 2, rz); atomicAdd(p + 3, rw);
}

__global__ void k_res1(const float* __restrict__ gat_bias, int n) {
    int i = blockIdx.x * blockDim.x + threadIdx.x;
    if (i < n) g_r1[i] = g_h0[i] + g_agg[i] + gat_bias[i & 127];
}

// ---------------------------------------------------------------------------
static inline int G(int n) { return (n + 255) / 256; }

extern "C" void kernel_launch(void* const* d_in, const int* in_sizes, int n_in,
                              void* d_out, int out_size) {
    const float* x         = (const float*)d_in[0];
    const int*   ei        = (const int*)  d_in[1];
    const float* edge_attr = (const float*)d_in[2];
    const float* Wl  = (const float*)d_in[4];
    const float* bl  = (const float*)d_in[5];
    const float* Wr  = (const float*)d_in[6];
    const float* br  = (const float*)d_in[7];
    const float* We  = (const float*)d_in[8];
    const float* att = (const float*)d_in[9];
    const float* gbn = (const float*)d_in[10];
    const float* W1  = (const float*)d_in[11];
    const float* b1  = (const float*)d_in[12];
    const float* W2  = (const float*)d_in[13];
    const float* b2  = (const float*)d_in[14];
    const float* Wc  = (const float*)d_in[15];
    const float* bc  = (const float*)d_in[16];
    const float* nw0 = (const float*)d_in[17];
    const float* nb0 = (const float*)d_in[18];
    const float* nw1 = (const float*)d_in[19];
    const float* nb1 = (const float*)d_in[20];
    const float* nw2 = (const float*)d_in[21];
    const float* nb2 = (const float*)d_in[22];
    const float* nw3 = (const float*)d_in[23];
    const float* nb3 = (const float*)d_in[24];

    int N = in_sizes[0] / 128;
    int E = in_sizes[1] / 2;
    int TOT = E + N;
    float* out = (float*)d_out;
    int write_alpha = (out_size >= N * 64 + TOT * 4) ? 1 : 0;
    float* out_alpha = out + (size_t)N * 64;

    float *h0, *r1, *n1, *r2, *n2, *xl, *xr, *ea, *ef, *hid;
    float *easum, *deg, *score, *ssum, *agg, *cls, *stats;
    unsigned* smax;
    cudaGetSymbolAddress((void**)&h0,    g_h0);
    cudaGetSymbolAddress((void**)&r1,    g_r1);
    cudaGetSymbolAddress((void**)&n1,    g_n1);
    cudaGetSymbolAddress((void**)&r2,    g_r2);
    cudaGetSymbolAddress((void**)&n2,    g_n2);
    cudaGetSymbolAddress((void**)&xl,    g_xl);
    cudaGetSymbolAddress((void**)&xr,    g_xr);
    cudaGetSymbolAddress((void**)&ea,    g_ea);
    cudaGetSymbolAddress((void**)&ef,    g_ef);
    cudaGetSymbolAddress((void**)&hid,   g_hid);
    cudaGetSymbolAddress((void**)&easum, g_easum);
    cudaGetSymbolAddress((void**)&deg,   g_deg);
    cudaGetSymbolAddress((void**)&score, g_score);
    cudaGetSymbolAddress((void**)&smax,  g_smax);
    cudaGetSymbolAddress((void**)&ssum,  g_ssum);
    cudaGetSymbolAddress((void**)&agg,   g_agg);
    cudaGetSymbolAddress((void**)&cls,   g_cls);
    cudaGetSymbolAddress((void**)&stats, g_stats);

    // --- init atomics targets ---
    k_zero<<<1, 256>>>(stats, 8);
    k_zero<<<G(N), 256>>>(deg, N);
    k_zero<<<G(N * 32), 256>>>(easum, N * 32);
    k_zero<<<G(N * 4), 256>>>(ssum, N * 4);
    k_zero<<<G(N * 128), 256>>>(agg, N * 128);
    k_init_smax<<<G(N * 4), 256>>>(smax, N * 4);

    // --- graph_norm 0 ---
    k_reduce<<<1024, 256>>>(x, N * 128 / 4, stats + 0);
    k_norm<<<G(N * 128), 256>>>(x, h0, nw0, nb0, stats + 0, 127, N * 128,
                                1.f / (float)(N * 128));

    // --- GATv2 linear transforms ---
    k_gemm<1><<<dim3(512 / 64, N / 64), 256>>>(h0, Wl, bl, nullptr, xl, N, 512, 128);
    k_gemm<1><<<dim3(512 / 64, N / 64), 256>>>(h0, Wr, br, nullptr, xr, N, 512, 128);

    // --- self-loop edge attrs ---
    k_fill_ea<<<G(E * 32), 256>>>(edge_attr, E * 32);
    k_degsum<<<(E + 7) / 8, 256>>>(edge_attr, ei, E);
    k_eamean<<<G(N * 32), 256>>>(E, N);

    // --- edge features ---
    k_gemm<0><<<dim3(512 / 64, TOT / 64), 256>>>(ea, We, nullptr, nullptr, ef, TOT, 512, 32);

    // --- attention scores + segment softmax ---
    k_score<<<(TOT + 7) / 8, 256>>>(ei, att, E, N);
    k_exp<<<G(TOT * 4), 256>>>(ei, E, N);
    k_alpha<<<G(TOT * 4), 256>>>(ei, out_alpha, E, N, write_alpha);

    // --- weighted aggregation (head mean folded) + residual ---
    k_agg<<<(TOT + 7) / 8, 256>>>(ei, E, N);
    k_res1<<<G(N * 128), 256>>>(gbn, N * 128);

    // --- graph_norm 1 ---
    k_reduce<<<1024, 256>>>(r1, N * 128 / 4, stats + 2);
    k_norm<<<G(N * 128), 256>>>(r1, n1, nw1, nb1, stats + 2, 127, N * 128,
                                1.f / (float)(N * 128));

    // --- MLP ---
    k_gemm<2><<<dim3(2048 / 64, N / 64), 256>>>(n1, W1, b1, nullptr, hid, N, 2048, 128);
    k_gemm<3><<<dim3(128 / 64, N / 64), 256>>>(hid, W2, b2, n1, r2, N, 128, 2048);

    // --- graph_norm 2 ---
    k_reduce<<<1024, 256>>>(r2, N * 128 / 4, stats + 4);
    k_norm<<<G(N * 128), 256>>>(r2, n2, nw2, nb2, stats + 4, 127, N * 128,
                                1.f / (float)(N * 128));

    // --- classifier + graph_norm 3 (writes final output) ---
    k_gemm<1><<<dim3(64 / 64, N / 64), 256>>>(n2, Wc, bc, nullptr, cls, N, 64, 128);
    k_reduce<<<512, 256>>>(cls, N * 64 / 4, stats + 6);
    k_norm<<<G(N * 64), 256>>>(cls, out, nw3, nb3, stats + 6, 63, N * 64,
                               1.f / (float)(N * 64));
}

// round 3
// speedup vs baseline: 3.3689x; 3.3689x over previous
#include <cuda_runtime.h>
#include <math.h>
#include <float.h>

// ---------------------------------------------------------------------------
// SynGNNLayer: graph_norm -> GATv2(+self loops, edge attrs) -> residual ->
// graph_norm -> MLP(128->2048->128, relu) -> residual -> graph_norm ->
// classifier(128->64) -> graph_norm.  Outputs: src [N,64] then alpha [E+N,4].
// R2: all GEMMs on tensor cores (mma.sync tf32, fp32 accumulate).
// ---------------------------------------------------------------------------

#define NMAX 16384
#define EMAX 131072
#define TOTMAX (EMAX + NMAX)

static __device__ float g_h0 [NMAX * 128];
static __device__ float g_r1 [NMAX * 128];
static __device__ float g_n1 [NMAX * 128];
static __device__ float g_r2 [NMAX * 128];
static __device__ float g_n2 [NMAX * 128];
static __device__ float g_xl [NMAX * 512];
static __device__ float g_xr [NMAX * 512];
static __device__ float g_ea [NMAX * 32];           // self-loop edge attrs only
static __device__ float g_ef [(size_t)TOTMAX * 512];
static __device__ float g_hid[(size_t)NMAX * 2048];
static __device__ float g_easum[NMAX * 32];
static __device__ float g_deg [NMAX];
static __device__ float g_score[TOTMAX * 4];
static __device__ unsigned g_smax[NMAX * 4];
static __device__ float g_ssum[NMAX * 4];
static __device__ float g_agg [NMAX * 128];
static __device__ float g_cls [NMAX * 64];
static __device__ float g_stats[8];

// ---- monotone float <-> uint encoding for atomicMax on floats -------------
__device__ __forceinline__ unsigned f_enc(float f) {
    unsigned u = __float_as_uint(f);
    return (u & 0x80000000u) ? ~u : (u | 0x80000000u);
}
__device__ __forceinline__ float f_dec(unsigned k) {
    return (k & 0x80000000u) ? __uint_as_float(k ^ 0x80000000u)
                             : __uint_as_float(~k);
}
__device__ __forceinline__ unsigned tf32r(float f) {
    unsigned u; asm("cvt.rna.tf32.f32 %0, %1;" : "=r"(u) : "f"(f)); return u;
}

// ---------------------------------------------------------------------------
__global__ void k_zero(float* __restrict__ p, int n) {
    int i = blockIdx.x * blockDim.x + threadIdx.x;
    if (i < n) p[i] = 0.f;
}
__global__ void k_init_smax(unsigned* __restrict__ p, int n) {
    int i = blockIdx.x * blockDim.x + threadIdx.x;
    if (i < n) p[i] = 0x00800000u;   // f_enc(-FLT_MAX)
}

// sum + sumsq reduction (n4 = n/4 float4 elements)
__global__ void k_reduce(const float* __restrict__ x, int n4, float* __restrict__ out) {
    float s = 0.f, ss = 0.f;
    for (int i = blockIdx.x * blockDim.x + threadIdx.x; i < n4; i += gridDim.x * blockDim.x) {
        float4 v = reinterpret_cast<const float4*>(x)[i];
        s  += v.x + v.y + v.z + v.w;
        ss += v.x * v.x + v.y * v.y + v.z * v.z + v.w * v.w;
    }
    #pragma unroll
    for (int o = 16; o > 0; o >>= 1) {
        s  += __shfl_xor_sync(0xffffffffu, s,  o);
        ss += __shfl_xor_sync(0xffffffffu, ss, o);
    }
    __shared__ float shs[8], shss[8];
    int w = threadIdx.x >> 5;
    if ((threadIdx.x & 31) == 0) { shs[w] = s; shss[w] = ss; }
    __syncthreads();
    if (threadIdx.x < 8) {
        s = shs[threadIdx.x]; ss = shss[threadIdx.x];
        #pragma unroll
        for (int o = 4; o > 0; o >>= 1) {
            s  += __shfl_xor_sync(0xffu, s,  o);
            ss += __shfl_xor_sync(0xffu, ss, o);
        }
        if (threadIdx.x == 0) { atomicAdd(out, s); atomicAdd(out + 1, ss); }
    }
}

// graph_norm apply: y = (x - mu)/(std + 1e-5) * w[c] + b[c]
__global__ void k_norm(const float* __restrict__ x, float* __restrict__ y,
                       const float* __restrict__ w, const float* __restrict__ b,
                       const float* __restrict__ st, int Dmask, int n, float invn) {
    int i = blockIdx.x * blockDim.x + threadIdx.x;
    if (i >= n) return;
    float mu  = st[0] * invn;
    float var = st[1] * invn - mu * mu;
    float inv = 1.f / (sqrtf(fmaxf(var, 0.f)) + 1e-5f);
    int c = i & Dmask;
    y[i] = (x[i] - mu) * inv * w[c] + b[c];
}

// ---------------------------------------------------------------------------
// Tensor-core GEMM: C[M,Nn] = A[M,K] @ W[Nn,K]^T (+epilogue), tf32 mma.sync.
// Block tile BM=128 x BN, BK=32, double-buffered smem, 8 warps.
// EPI: 0 none, 1 +bias, 2 +bias,relu, 3 +bias,+res
// Requires M%128==0, Nn%BN==0, K%32==0.
// ---------------------------------------------------------------------------
template<int BN, int WROWS, int WCOLS, int EPI>
__global__ void __launch_bounds__(256)
k_tgemm(const float* __restrict__ A, const float* __restrict__ W,
        const float* __restrict__ bias, const float* __restrict__ res,
        float* __restrict__ C, int M, int Nn, int K)
{
    constexpr int BM = 128, BK = 32, LDA = BK + 4;     // stride 36: conflict-free
    constexpr int MF = BM / (WROWS * 16);
    constexpr int NF = BN / (WCOLS * 8);
    constexpr int A_LD = (BM * BK / 4) / 256;          // float4 loads per thread
    constexpr int B_LD = (BN * BK / 4) / 256;

    extern __shared__ unsigned sh[];
    unsigned* As = sh;                                 // [2][BM][LDA]
    unsigned* Bs = sh + 2 * BM * LDA;                  // [2][BN][LDA]

    const int tid = threadIdx.x;
    const int wid = tid >> 5, lane = tid & 31;
    const int wm = wid / WCOLS, wn = wid % WCOLS;
    const int g = lane >> 2, tg = lane & 3;
    const long m0 = (long)blockIdx.y * BM;
    const int  n0 = blockIdx.x * BN;

    float4 ar[A_LD], br[B_LD];

    auto load_tiles = [&](int kk) {
        #pragma unroll
        for (int i = 0; i < A_LD; i++) {
            int idx = tid + i * 256;
            int r = idx >> 3, c4 = idx & 7;
            ar[i] = reinterpret_cast<const float4*>(A + (m0 + r) * K + kk)[c4];
        }
        #pragma unroll
        for (int i = 0; i < B_LD; i++) {
            int idx = tid + i * 256;
            int r = idx >> 3, c4 = idx & 7;
            br[i] = reinterpret_cast<const float4*>(W + (long)(n0 + r) * K + kk)[c4];
        }
    };
    auto store_tiles = [&](int s) {
        #pragma unroll
        for (int i = 0; i < A_LD; i++) {
            int idx = tid + i * 256;
            int r = idx >> 3, c4 = idx & 7;
            uint4 u = { tf32r(ar[i].x), tf32r(ar[i].y), tf32r(ar[i].z), tf32r(ar[i].w) };
            reinterpret_cast<uint4*>(&As[s * BM * LDA + r * LDA + c4 * 4])[0] = u;
        }
        #pragma unroll
        for (int i = 0; i < B_LD; i++) {
            int idx = tid + i * 256;
            int r = idx >> 3, c4 = idx & 7;
            uint4 u = { tf32r(br[i].x), tf32r(br[i].y), tf32r(br[i].z), tf32r(br[i].w) };
            reinterpret_cast<uint4*>(&Bs[s * BN * LDA + r * LDA + c4 * 4])[0] = u;
        }
    };

    float acc[MF][NF][4] = {};

    load_tiles(0);
    store_tiles(0);
    __syncthreads();

    const int NT = K / BK;
    for (int kt = 0; kt < NT; kt++) {
        const int s = kt & 1;
        if (kt + 1 < NT) load_tiles((kt + 1) * BK);
        #pragma unroll
        for (int k8 = 0; k8 < BK / 8; k8++) {
            unsigned af[MF][4], bf[NF][2];
            #pragma unroll
            for (int i = 0; i < MF; i++) {
                int r = wm * (MF * 16) + i * 16 + g;
                const unsigned* p = &As[s * BM * LDA + r * LDA + k8 * 8];
                af[i][0] = p[tg];
                af[i][1] = p[8 * LDA + tg];
                af[i][2] = p[tg + 4];
                af[i][3] = p[8 * LDA + tg + 4];
            }
            #pragma unroll
            for (int j = 0; j < NF; j++) {
                int c = wn * (NF * 8) + j * 8 + g;
                const unsigned* p = &Bs[s * BN * LDA + c * LDA + k8 * 8];
                bf[j][0] = p[tg];
                bf[j][1] = p[tg + 4];
            }
            #pragma unroll
            for (int i = 0; i < MF; i++)
                #pragma unroll
                for (int j = 0; j < NF; j++) {
                    asm volatile(
                        "mma.sync.aligned.m16n8k8.row.col.f32.tf32.tf32.f32 "
                        "{%0,%1,%2,%3}, {%4,%5,%6,%7}, {%8,%9}, {%0,%1,%2,%3};\n"
                        : "+f"(acc[i][j][0]), "+f"(acc[i][j][1]),
                          "+f"(acc[i][j][2]), "+f"(acc[i][j][3])
                        : "r"(af[i][0]), "r"(af[i][1]), "r"(af[i][2]), "r"(af[i][3]),
                          "r"(bf[j][0]), "r"(bf[j][1]));
                }
        }
        if (kt + 1 < NT) {
            store_tiles((kt + 1) & 1);
            __syncthreads();
        }
    }

    // epilogue
    #pragma unroll
    for (int i = 0; i < MF; i++) {
        long mA = m0 + wm * (MF * 16) + i * 16 + g;
        long mB = mA + 8;
        #pragma unroll
        for (int j = 0; j < NF; j++) {
            int c = n0 + wn * (NF * 8) + j * 8 + tg * 2;
            float v0 = acc[i][j][0], v1 = acc[i][j][1];
            float v2 = acc[i][j][2], v3 = acc[i][j][3];
            if (EPI >= 1) {
                float b0 = bias[c], b1 = bias[c + 1];
                v0 += b0; v1 += b1; v2 += b0; v3 += b1;
            }
            if (EPI == 2) {
                v0 = fmaxf(v0, 0.f); v1 = fmaxf(v1, 0.f);
                v2 = fmaxf(v2, 0.f); v3 = fmaxf(v3, 0.f);
            }
            if (EPI == 3) {
                float2 rA = reinterpret_cast<const float2*>(res + mA * Nn + c)[0];
                float2 rB = reinterpret_cast<const float2*>(res + mB * Nn + c)[0];
                v0 += rA.x; v1 += rA.y; v2 += rB.x; v3 += rB.y;
            }
            reinterpret_cast<float2*>(C + mA * Nn + c)[0] = make_float2(v0, v1);
            reinterpret_cast<float2*>(C + mB * Nn + c)[0] = make_float2(v2, v3);
        }
    }
}

// ---- edge-side kernels ----------------------------------------------------
// deg + incoming edge_attr sums (warp per edge; lane == channel)
__global__ void k_degsum(const float* __restrict__ edge_attr,
                         const int* __restrict__ ei, int E) {
    int e = blockIdx.x * 8 + (threadIdx.x >> 5);
    if (e >= E) return;
    int l = threadIdx.x & 31;
    int dst = ei[E + e];
    atomicAdd(&g_easum[dst * 32 + l], edge_attr[e * 32 + l]);
    if (l == 0) atomicAdd(&g_deg[dst], 1.f);
}

// self-loop edge attrs = mean of incoming (0 for isolated)
__global__ void k_eamean(int N) {
    int i = blockIdx.x * blockDim.x + threadIdx.x;
    if (i >= N * 32) return;
    int nid = i >> 5;
    float d = fmaxf(g_deg[nid], 1.f);
    g_ea[i] = g_easum[i] / d;
}

// score[e,h] = sum_c att[h,c]*leaky(xl[src]+xr[dst]+ef[e]); + atomicMax per dst
__global__ void k_score(const int* __restrict__ ei, const float* __restrict__ att,
                        int E, int N) {
    int tot = E + N;
    int e = blockIdx.x * 8 + (threadIdx.x >> 5);
    if (e >= tot) return;
    int l = threadIdx.x & 31;
    int s = (e < E) ? ei[e]     : (e - E);
    int d = (e < E) ? ei[E + e] : (e - E);
    const float4* xl4 = reinterpret_cast<const float4*>(g_xl + (long)s * 512);
    const float4* xr4 = reinterpret_cast<const float4*>(g_xr + (long)d * 512);
    const float4* ef4 = reinterpret_cast<const float4*>(g_ef + (long)e * 512);
    const float4* at4 = reinterpret_cast<const float4*>(att);
    float sc[4];
    #pragma unroll
    for (int h = 0; h < 4; h++) {
        int idx = h * 32 + l;
        float4 a = xl4[idx], b = xr4[idx], c = ef4[idx], w = at4[idx];
        float zx = a.x + b.x + c.x; zx = zx > 0.f ? zx : 0.2f * zx;
        float zy = a.y + b.y + c.y; zy = zy > 0.f ? zy : 0.2f * zy;
        float zz = a.z + b.z + c.z; zz = zz > 0.f ? zz : 0.2f * zz;
        float zw = a.w + b.w + c.w; zw = zw > 0.f ? zw : 0.2f * zw;
        sc[h] = zx * w.x + zy * w.y + zz * w.z + zw * w.w;
    }
    #pragma unroll
    for (int h = 0; h < 4; h++)
        #pragma unroll
        for (int o = 16; o > 0; o >>= 1)
            sc[h] += __shfl_xor_sync(0xffffffffu, sc[h], o);
    if (l == 0) {
        #pragma unroll
        for (int h = 0; h < 4; h++) {
            g_score[(long)e * 4 + h] = sc[h];
            atomicMax(&g_smax[d * 4 + h], f_enc(sc[h]));
        }
    }
}

__global__ void k_exp(const int* __restrict__ ei, int E, int N) {
    int i = blockIdx.x * blockDim.x + threadIdx.x;
    int tot4 = (E + N) * 4;
    if (i >= tot4) return;
    int e = i >> 2, h = i & 3;
    int d = (e < E) ? ei[E + e] : (e - E);
    float m  = f_dec(g_smax[d * 4 + h]);
    float ex = expf(g_score[i] - m);
    g_score[i] = ex;
    atomicAdd(&g_ssum[d * 4 + h], ex);
}

__global__ void k_alpha(const int* __restrict__ ei, float* __restrict__ out_alpha,
                        int E, int N, int write_out) {
    int i = blockIdx.x * blockDim.x + threadIdx.x;
    int tot4 = (E + N) * 4;
    if (i >= tot4) return;
    int e = i >> 2, h = i & 3;
    int d = (e < E) ? ei[E + e] : (e - E);
    float a = g_score[i] / g_ssum[d * 4 + h];
    g_score[i] = a;
    if (write_out) out_alpha[i] = a;
}

// out[n,c] += (1/H) * sum_h alpha[e,h]*xl[src, h*128+c]   (warp per edge)
__global__ void k_agg(const int* __restrict__ ei, int E, int N) {
    int tot = E + N;
    int e = blockIdx.x * 8 + (threadIdx.x >> 5);
    if (e >= tot) return;
    int l = threadIdx.x & 31;
    int s = (e < E) ? ei[e]     : (e - E);
    int d = (e < E) ? ei[E + e] : (e - E);
    float a0 = g_score[(long)e * 4 + 0] * 0.25f;
    float a1 = g_score[(long)e * 4 + 1] * 0.25f;
    float a2 = g_score[(long)e * 4 + 2] * 0.25f;
    float a3 = g_score[(long)e * 4 + 3] * 0.25f;
    const float4* xl4 = reinterpret_cast<const float4*>(g_xl + (long)s * 512);
    float4 v0 = xl4[ 0 + l], v1 = xl4[32 + l], v2 = xl4[64 + l], v3 = xl4[96 + l];
    float rx = a0 * v0.x + a1 * v1.x + a2 * v2.x + a3 * v3.x;
    float ry = a0 * v0.y + a1 * v1.y + a2 * v2.y + a3 * v3.y;
    float rz = a0 * v0.z + a1 * v1.z + a2 * v2.z + a3 * v3.z;
    float rw = a0 * v0.w + a1 * v1.w + a2 * v2.w + a3 * v3.w;
    float* p = g_agg + d * 128 + 4 * l;
    atomicAdd(p + 0, rx); atomicAdd(p + 1, ry);
    atomicAdd(p + 2, rz); atomicAdd(p + 3, rw);
}

__global__ void k_res1(const float* __restrict__ gat_bias, int n) {
    int i = blockIdx.x * blockDim.x + threadIdx.x;
    if (i < n) g_r1[i] = g_h0[i] + g_agg[i] + gat_bias[i & 127];
}

// ---------------------------------------------------------------------------
static inline int G(int n) { return (n + 255) / 256; }

extern "C" void kernel_launch(void* const* d_in, const int* in_sizes, int n_in,
                              void* d_out, int out_size) {
    const float* x         = (const float*)d_in[0];
    const int*   ei        = (const int*)  d_in[1];
    const float* edge_attr = (const float*)d_in[2];
    const float* Wl  = (const float*)d_in[4];
    const float* bl  = (const float*)d_in[5];
    const float* Wr  = (const float*)d_in[6];
    const float* br  = (const float*)d_in[7];
    const float* We  = (const float*)d_in[8];
    const float* att = (const float*)d_in[9];
    const float* gbn = (const float*)d_in[10];
    const float* W1  = (const float*)d_in[11];
    const float* b1  = (const float*)d_in[12];
    const float* W2  = (const float*)d_in[13];
    const float* b2  = (const float*)d_in[14];
    const float* Wc  = (const float*)d_in[15];
    const float* bc  = (const float*)d_in[16];
    const float* nw0 = (const float*)d_in[17];
    const float* nb0 = (const float*)d_in[18];
    const float* nw1 = (const float*)d_in[19];
    const float* nb1 = (const float*)d_in[20];
    const float* nw2 = (const float*)d_in[21];
    const float* nb2 = (const float*)d_in[22];
    const float* nw3 = (const float*)d_in[23];
    const float* nb3 = (const float*)d_in[24];

    int N = in_sizes[0] / 128;
    int E = in_sizes[1] / 2;
    int TOT = E + N;
    float* out = (float*)d_out;
    int write_alpha = (out_size >= N * 64 + TOT * 4) ? 1 : 0;
    float* out_alpha = out + (size_t)N * 64;

    float *h0, *r1, *n1, *r2, *n2, *xl, *xr, *ea, *ef, *hid;
    float *easum, *deg, *score, *ssum, *agg, *cls, *stats;
    unsigned* smax;
    cudaGetSymbolAddress((void**)&h0,    g_h0);
    cudaGetSymbolAddress((void**)&r1,    g_r1);
    cudaGetSymbolAddress((void**)&n1,    g_n1);
    cudaGetSymbolAddress((void**)&r2,    g_r2);
    cudaGetSymbolAddress((void**)&n2,    g_n2);
    cudaGetSymbolAddress((void**)&xl,    g_xl);
    cudaGetSymbolAddress((void**)&xr,    g_xr);
    cudaGetSymbolAddress((void**)&ea,    g_ea);
    cudaGetSymbolAddress((void**)&ef,    g_ef);
    cudaGetSymbolAddress((void**)&hid,   g_hid);
    cudaGetSymbolAddress((void**)&easum, g_easum);
    cudaGetSymbolAddress((void**)&deg,   g_deg);
    cudaGetSymbolAddress((void**)&score, g_score);
    cudaGetSymbolAddress((void**)&smax,  g_smax);
    cudaGetSymbolAddress((void**)&ssum,  g_ssum);
    cudaGetSymbolAddress((void**)&agg,   g_agg);
    cudaGetSymbolAddress((void**)&cls,   g_cls);
    cudaGetSymbolAddress((void**)&stats, g_stats);

    // dynamic smem opt-in for the tensor GEMMs (host-side attr, capture-safe)
    const int SM128 = (2 * 128 * 36 + 2 * 128 * 36) * 4;  // 73728 B
    const int SM64  = (2 * 128 * 36 + 2 *  64 * 36) * 4;  // 55296 B
    cudaFuncSetAttribute(k_tgemm<128,2,4,0>, cudaFuncAttributeMaxDynamicSharedMemorySize, SM128);
    cudaFuncSetAttribute(k_tgemm<128,2,4,1>, cudaFuncAttributeMaxDynamicSharedMemorySize, SM128);
    cudaFuncSetAttribute(k_tgemm<128,2,4,2>, cudaFuncAttributeMaxDynamicSharedMemorySize, SM128);
    cudaFuncSetAttribute(k_tgemm<128,2,4,3>, cudaFuncAttributeMaxDynamicSharedMemorySize, SM128);
    cudaFuncSetAttribute(k_tgemm<64,4,2,1>,  cudaFuncAttributeMaxDynamicSharedMemorySize, SM64);

    // --- init atomics targets ---
    k_zero<<<1, 256>>>(stats, 8);
    k_zero<<<G(N), 256>>>(deg, N);
    k_zero<<<G(N * 32), 256>>>(easum, N * 32);
    k_zero<<<G(N * 4), 256>>>(ssum, N * 4);
    k_zero<<<G(N * 128), 256>>>(agg, N * 128);
    k_init_smax<<<G(N * 4), 256>>>(smax, N * 4);

    // --- graph_norm 0 ---
    k_reduce<<<1024, 256>>>(x, N * 128 / 4, stats + 0);
    k_norm<<<G(N * 128), 256>>>(x, h0, nw0, nb0, stats + 0, 127, N * 128,
                                1.f / (float)(N * 128));

    // --- GATv2 linear transforms (tensor cores) ---
    k_tgemm<128,2,4,1><<<dim3(512/128, N/128), 256, SM128>>>(h0, Wl, bl, nullptr, xl, N, 512, 128);
    k_tgemm<128,2,4,1><<<dim3(512/128, N/128), 256, SM128>>>(h0, Wr, br, nullptr, xr, N, 512, 128);

    // --- self-loop edge attrs ---
    k_degsum<<<(E + 7) / 8, 256>>>(edge_attr, ei, E);
    k_eamean<<<G(N * 32), 256>>>(N);

    // --- edge features: real edges then self loops (E % 128 == 0) ---
    k_tgemm<128,2,4,0><<<dim3(512/128, E/128), 256, SM128>>>(edge_attr, We, nullptr, nullptr, ef, E, 512, 32);
    k_tgemm<128,2,4,0><<<dim3(512/128, N/128), 256, SM128>>>(ea, We, nullptr, nullptr, ef + (size_t)E * 512, N, 512, 32);

    // --- attention scores + segment softmax ---
    k_score<<<(TOT + 7) / 8, 256>>>(ei, att, E, N);
    k_exp<<<G(TOT * 4), 256>>>(ei, E, N);
    k_alpha<<<G(TOT * 4), 256>>>(ei, out_alpha, E, N, write_alpha);

    // --- weighted aggregation (head mean folded) + residual ---
    k_agg<<<(TOT + 7) / 8, 256>>>(ei, E, N);
    k_res1<<<G(N * 128), 256>>>(gbn, N * 128);

    // --- graph_norm 1 ---
    k_reduce<<<1024, 256>>>(r1, N * 128 / 4, stats + 2);
    k_norm<<<G(N * 128), 256>>>(r1, n1, nw1, nb1, stats + 2, 127, N * 128,
                                1.f / (float)(N * 128));

    // --- MLP (tensor cores) ---
    k_tgemm<128,2,4,2><<<dim3(2048/128, N/128), 256, SM128>>>(n1, W1, b1, nullptr, hid, N, 2048, 128);
    k_tgemm<128,2,4,3><<<dim3(128/128, N/128), 256, SM128>>>(hid, W2, b2, n1, r2, N, 128, 2048);

    // --- graph_norm 2 ---
    k_reduce<<<1024, 256>>>(r2, N * 128 / 4, stats + 4);
    k_norm<<<G(N * 128), 256>>>(r2, n2, nw2, nb2, stats + 4, 127, N * 128,
                                1.f / (float)(N * 128));

    // --- classifier + graph_norm 3 (writes final output) ---
    k_tgemm<64,4,2,1><<<dim3(64/64, N/128), 256, SM64>>>(n2, Wc, bc, nullptr, cls, N, 64, 128);
    k_reduce<<<512, 256>>>(cls, N * 64 / 4, stats + 6);
    k_norm<<<G(N * 64), 256>>>(cls, out, nw3, nb3, stats + 6, 63, N * 64,
                               1.f / (float)(N * 64));
}

// round 5
// speedup vs baseline: 4.1022x; 1.2177x over previous
#include <cuda_runtime.h>
#include <math.h>
#include <float.h>

// ---------------------------------------------------------------------------
// SynGNNLayer. R5 = R4 with the k_gemm_score SMEM tile-load bug fixed
// (full 128-row tiles; R4 only filled 32 rows -> garbage scores).
// ---------------------------------------------------------------------------

#define NMAX 16384
#define EMAX 131072
#define TOTMAX (EMAX + NMAX)

static __device__ float g_h0 [NMAX * 128];
static __device__ float g_r1 [NMAX * 128];
static __device__ float g_n1 [NMAX * 128];
static __device__ float g_r2 [NMAX * 128];
static __device__ float g_n2 [NMAX * 128];
static __device__ float g_xl [NMAX * 512];
static __device__ float g_xr [NMAX * 512];
static __device__ float g_ea [NMAX * 32];           // self-loop edge attrs
static __device__ float g_hid[(size_t)NMAX * 2048];
static __device__ float g_easum[NMAX * 32];
static __device__ float g_deg [NMAX];
static __device__ float g_score[TOTMAX * 4];
static __device__ unsigned g_smax[NMAX * 4];
static __device__ float g_ssum[NMAX * 4];
static __device__ float g_agg [NMAX * 128];
static __device__ float g_cls [NMAX * 64];
static __device__ float g_stats[8];

// ---- monotone float <-> uint encoding for atomicMax on floats -------------
__device__ __forceinline__ unsigned f_enc(float f) {
    unsigned u = __float_as_uint(f);
    return (u & 0x80000000u) ? ~u : (u | 0x80000000u);
}
__device__ __forceinline__ float f_dec(unsigned k) {
    return (k & 0x80000000u) ? __uint_as_float(k ^ 0x80000000u)
                             : __uint_as_float(~k);
}
__device__ __forceinline__ unsigned tf32r(float f) {
    unsigned u; asm("cvt.rna.tf32.f32 %0, %1;" : "=r"(u) : "f"(f)); return u;
}

// ---------------------------------------------------------------------------
// one-shot init of every atomic target
__global__ void k_init(int N) {
    int i = blockIdx.x * blockDim.x + threadIdx.x;
    if (i < N * 128) g_agg[i] = 0.f;
    if (i < N * 32)  g_easum[i] = 0.f;
    if (i < N * 4)   { g_ssum[i] = 0.f; g_smax[i] = 0x00800000u; }
    if (i < N)       g_deg[i] = 0.f;
    if (i < 8)       g_stats[i] = 0.f;
}

// sum + sumsq reduction (n4 = n/4 float4 elements)
__global__ void k_reduce(const float* __restrict__ x, int n4, float* __restrict__ out) {
    float s = 0.f, ss = 0.f;
    for (int i = blockIdx.x * blockDim.x + threadIdx.x; i < n4; i += gridDim.x * blockDim.x) {
        float4 v = reinterpret_cast<const float4*>(x)[i];
        s  += v.x + v.y + v.z + v.w;
        ss += v.x * v.x + v.y * v.y + v.z * v.z + v.w * v.w;
    }
    #pragma unroll
    for (int o = 16; o > 0; o >>= 1) {
        s  += __shfl_xor_sync(0xffffffffu, s,  o);
        ss += __shfl_xor_sync(0xffffffffu, ss, o);
    }
    __shared__ float shs[8], shss[8];
    int w = threadIdx.x >> 5;
    if ((threadIdx.x & 31) == 0) { shs[w] = s; shss[w] = ss; }
    __syncthreads();
    if (threadIdx.x < 8) {
        s = shs[threadIdx.x]; ss = shss[threadIdx.x];
        #pragma unroll
        for (int o = 4; o > 0; o >>= 1) {
            s  += __shfl_xor_sync(0xffu, s,  o);
            ss += __shfl_xor_sync(0xffu, ss, o);
        }
        if (threadIdx.x == 0) { atomicAdd(out, s); atomicAdd(out + 1, ss); }
    }
}

// residual + reduction: r1 = h0 + agg + bias; accumulate sum/sumsq
__global__ void k_res_reduce(const float* __restrict__ gat_bias, int n4,
                             float* __restrict__ out) {
    float s = 0.f, ss = 0.f;
    const float4* b4 = reinterpret_cast<const float4*>(gat_bias);
    for (int i = blockIdx.x * blockDim.x + threadIdx.x; i < n4; i += gridDim.x * blockDim.x) {
        float4 a = reinterpret_cast<const float4*>(g_h0)[i];
        float4 g = reinterpret_cast<const float4*>(g_agg)[i];
        float4 b = b4[i & 31];
        float4 v = { a.x + g.x + b.x, a.y + g.y + b.y,
                     a.z + g.z + b.z, a.w + g.w + b.w };
        reinterpret_cast<float4*>(g_r1)[i] = v;
        s  += v.x + v.y + v.z + v.w;
        ss += v.x * v.x + v.y * v.y + v.z * v.z + v.w * v.w;
    }
    #pragma unroll
    for (int o = 16; o > 0; o >>= 1) {
        s  += __shfl_xor_sync(0xffffffffu, s,  o);
        ss += __shfl_xor_sync(0xffffffffu, ss, o);
    }
    __shared__ float shs[8], shss[8];
    int w = threadIdx.x >> 5;
    if ((threadIdx.x & 31) == 0) { shs[w] = s; shss[w] = ss; }
    __syncthreads();
    if (threadIdx.x < 8) {
        s = shs[threadIdx.x]; ss = shss[threadIdx.x];
        #pragma unroll
        for (int o = 4; o > 0; o >>= 1) {
            s  += __shfl_xor_sync(0xffu, s,  o);
            ss += __shfl_xor_sync(0xffu, ss, o);
        }
        if (threadIdx.x == 0) { atomicAdd(out, s); atomicAdd(out + 1, ss); }
    }
}

// graph_norm apply: y = (x - mu)/(std + 1e-5) * w[c] + b[c]
__global__ void k_norm(const float* __restrict__ x, float* __restrict__ y,
                       const float* __restrict__ w, const float* __restrict__ b,
                       const float* __restrict__ st, int Dmask, int n, float invn) {
    int i = blockIdx.x * blockDim.x + threadIdx.x;
    if (i >= n) return;
    float mu  = st[0] * invn;
    float var = st[1] * invn - mu * mu;
    float inv = 1.f / (sqrtf(fmaxf(var, 0.f)) + 1e-5f);
    int c = i & Dmask;
    y[i] = (x[i] - mu) * inv * w[c] + b[c];
}

// ---------------------------------------------------------------------------
// Tensor-core GEMM: C[M,Nn] = A[M,K] @ W[Nn,K]^T (+epilogue), tf32 mma.sync.
// EPI: 1 +bias, 2 +bias,relu, 3 +bias,+res
// ---------------------------------------------------------------------------
template<int BN, int WROWS, int WCOLS, int EPI>
__global__ void __launch_bounds__(256)
k_tgemm(const float* __restrict__ A, const float* __restrict__ W,
        const float* __restrict__ bias, const float* __restrict__ res,
        float* __restrict__ C, int M, int Nn, int K)
{
    constexpr int BM = 128, BK = 32, LDA = BK + 4;
    constexpr int MF = BM / (WROWS * 16);
    constexpr int NF = BN / (WCOLS * 8);
    constexpr int A_LD = (BM * BK / 4) / 256;
    constexpr int B_LD = (BN * BK / 4) / 256;

    extern __shared__ unsigned sh[];
    unsigned* As = sh;
    unsigned* Bs = sh + 2 * BM * LDA;

    const int tid = threadIdx.x;
    const int wid = tid >> 5, lane = tid & 31;
    const int wm = wid / WCOLS, wn = wid % WCOLS;
    const int g = lane >> 2, tg = lane & 3;
    const long m0 = (long)blockIdx.y * BM;
    const int  n0 = blockIdx.x * BN;

    float4 ar[A_LD], br[B_LD];

    auto load_tiles = [&](int kk) {
        #pragma unroll
        for (int i = 0; i < A_LD; i++) {
            int idx = tid + i * 256;
            int r = idx >> 3, c4 = idx & 7;
            ar[i] = reinterpret_cast<const float4*>(A + (m0 + r) * K + kk)[c4];
        }
        #pragma unroll
        for (int i = 0; i < B_LD; i++) {
            int idx = tid + i * 256;
            int r = idx >> 3, c4 = idx & 7;
            br[i] = reinterpret_cast<const float4*>(W + (long)(n0 + r) * K + kk)[c4];
        }
    };
    auto store_tiles = [&](int s) {
        #pragma unroll
        for (int i = 0; i < A_LD; i++) {
            int idx = tid + i * 256;
            int r = idx >> 3, c4 = idx & 7;
            uint4 u = { tf32r(ar[i].x), tf32r(ar[i].y), tf32r(ar[i].z), tf32r(ar[i].w) };
            reinterpret_cast<uint4*>(&As[s * BM * LDA + r * LDA + c4 * 4])[0] = u;
        }
        #pragma unroll
        for (int i = 0; i < B_LD; i++) {
            int idx = tid + i * 256;
            int r = idx >> 3, c4 = idx & 7;
            uint4 u = { tf32r(br[i].x), tf32r(br[i].y), tf32r(br[i].z), tf32r(br[i].w) };
            reinterpret_cast<uint4*>(&Bs[s * BN * LDA + r * LDA + c4 * 4])[0] = u;
        }
    };

    float acc[MF][NF][4] = {};
    load_tiles(0);
    store_tiles(0);
    __syncthreads();

    const int NT = K / BK;
    for (int kt = 0; kt < NT; kt++) {
        const int s = kt & 1;
        if (kt + 1 < NT) load_tiles((kt + 1) * BK);
        #pragma unroll
        for (int k8 = 0; k8 < BK / 8; k8++) {
            unsigned af[MF][4], bf[NF][2];
            #pragma unroll
            for (int i = 0; i < MF; i++) {
                int r = wm * (MF * 16) + i * 16 + g;
                const unsigned* p = &As[s * BM * LDA + r * LDA + k8 * 8];
                af[i][0] = p[tg];
                af[i][1] = p[8 * LDA + tg];
                af[i][2] = p[tg + 4];
                af[i][3] = p[8 * LDA + tg + 4];
            }
            #pragma unroll
            for (int j = 0; j < NF; j++) {
                int c = wn * (NF * 8) + j * 8 + g;
                const unsigned* p = &Bs[s * BN * LDA + c * LDA + k8 * 8];
                bf[j][0] = p[tg];
                bf[j][1] = p[tg + 4];
            }
            #pragma unroll
            for (int i = 0; i < MF; i++)
                #pragma unroll
                for (int j = 0; j < NF; j++) {
                    asm volatile(
                        "mma.sync.aligned.m16n8k8.row.col.f32.tf32.tf32.f32 "
                        "{%0,%1,%2,%3}, {%4,%5,%6,%7}, {%8,%9}, {%0,%1,%2,%3};\n"
                        : "+f"(acc[i][j][0]), "+f"(acc[i][j][1]),
                          "+f"(acc[i][j][2]), "+f"(acc[i][j][3])
                        : "r"(af[i][0]), "r"(af[i][1]), "r"(af[i][2]), "r"(af[i][3]),
                          "r"(bf[j][0]), "r"(bf[j][1]));
                }
        }
        if (kt + 1 < NT) {
            store_tiles((kt + 1) & 1);
            __syncthreads();
        }
    }

    #pragma unroll
    for (int i = 0; i < MF; i++) {
        long mA = m0 + wm * (MF * 16) + i * 16 + g;
        long mB = mA + 8;
        #pragma unroll
        for (int j = 0; j < NF; j++) {
            int c = n0 + wn * (NF * 8) + j * 8 + tg * 2;
            float v0 = acc[i][j][0], v1 = acc[i][j][1];
            float v2 = acc[i][j][2], v3 = acc[i][j][3];
            if (EPI >= 1) {
                float b0 = bias[c], b1 = bias[c + 1];
                v0 += b0; v1 += b1; v2 += b0; v3 += b1;
            }
            if (EPI == 2) {
                v0 = fmaxf(v0, 0.f); v1 = fmaxf(v1, 0.f);
                v2 = fmaxf(v2, 0.f); v3 = fmaxf(v3, 0.f);
            }
            if (EPI == 3) {
                float2 rA = reinterpret_cast<const float2*>(res + mA * Nn + c)[0];
                float2 rB = reinterpret_cast<const float2*>(res + mB * Nn + c)[0];
                v0 += rA.x; v1 += rA.y; v2 += rB.x; v3 += rB.y;
            }
            reinterpret_cast<float2*>(C + mA * Nn + c)[0] = make_float2(v0, v1);
            reinterpret_cast<float2*>(C + mB * Nn + c)[0] = make_float2(v2, v3);
        }
    }
}

// ---------------------------------------------------------------------------
// ef GEMM + fused attention score epilogue. BM=128, BN=128 (= one head), K=32.
// score[ge,h] = sum_c att[h,c]*leaky(ef + xl[src,h*128+c] + xr[dst,h*128+c]).
// ef is never written to memory.
// ---------------------------------------------------------------------------
__global__ void __launch_bounds__(256)
k_gemm_score(const float* __restrict__ A, const float* __restrict__ W,
             const float* __restrict__ att, const int* __restrict__ ei,
             int ebase, int E)
{
    constexpr int BM = 128, BN = 128, BK = 32, LDA = BK + 4;
    constexpr int MF = 4, NF = 4;   // WROWS=2, WCOLS=4

    extern __shared__ unsigned sh[];
    unsigned* As = sh;
    unsigned* Bs = sh + BM * LDA;
    float* srow = reinterpret_cast<float*>(sh);   // reused after mainloop

    const int tid = threadIdx.x;
    const int wid = tid >> 5, lane = tid & 31;
    const int wm = wid >> 2, wn = wid & 3;
    const int g = lane >> 2, tg = lane & 3;
    const long m0 = (long)blockIdx.y * BM;
    const int  n0 = blockIdx.x * BN;              // = h*128

    // load full 128x32 A and B tiles (4 float4 per thread each) -- R4 bugfix
    #pragma unroll
    for (int t = 0; t < 4; t++) {
        int idx = tid + t * 256;
        int r = idx >> 3, c4 = idx & 7;
        float4 a = reinterpret_cast<const float4*>(A + (m0 + r) * BK)[c4];
        uint4 ua = { tf32r(a.x), tf32r(a.y), tf32r(a.z), tf32r(a.w) };
        reinterpret_cast<uint4*>(&As[r * LDA + c4 * 4])[0] = ua;
        float4 b = reinterpret_cast<const float4*>(W + (long)(n0 + r) * BK)[c4];
        uint4 ub = { tf32r(b.x), tf32r(b.y), tf32r(b.z), tf32r(b.w) };
        reinterpret_cast<uint4*>(&Bs[r * LDA + c4 * 4])[0] = ub;
    }
    __syncthreads();

    float acc[MF][NF][4] = {};
    #pragma unroll
    for (int k8 = 0; k8 < 4; k8++) {
        unsigned af[MF][4], bf[NF][2];
        #pragma unroll
        for (int i = 0; i < MF; i++) {
            int r = wm * 64 + i * 16 + g;
            const unsigned* p = &As[r * LDA + k8 * 8];
            af[i][0] = p[tg];
            af[i][1] = p[8 * LDA + tg];
            af[i][2] = p[tg + 4];
            af[i][3] = p[8 * LDA + tg + 4];
        }
        #pragma unroll
        for (int j = 0; j < NF; j++) {
            int c = wn * 32 + j * 8 + g;
            const unsigned* p = &Bs[c * LDA + k8 * 8];
            bf[j][0] = p[tg];
            bf[j][1] = p[tg + 4];
        }
        #pragma unroll
        for (int i = 0; i < MF; i++)
            #pragma unroll
            for (int j = 0; j < NF; j++) {
                asm volatile(
                    "mma.sync.aligned.m16n8k8.row.col.f32.tf32.tf32.f32 "
                    "{%0,%1,%2,%3}, {%4,%5,%6,%7}, {%8,%9}, {%0,%1,%2,%3};\n"
                    : "+f"(acc[i][j][0]), "+f"(acc[i][j][1]),
                      "+f"(acc[i][j][2]), "+f"(acc[i][j][3])
                    : "r"(af[i][0]), "r"(af[i][1]), "r"(af[i][2]), "r"(af[i][3]),
                      "r"(bf[j][0]), "r"(bf[j][1]));
            }
    }

    // score epilogue: leaky(acc + xl[src] + xr[dst]) dot att, per row
    float part[MF][2] = {};
    #pragma unroll
    for (int i = 0; i < MF; i++) {
        int rA = wm * 64 + i * 16 + g;      // local rows
        int rB = rA + 8;
        int geA = ebase + (int)m0 + rA;
        int geB = ebase + (int)m0 + rB;
        int sA = (geA < E) ? ei[geA] : (geA - E);
        int dA = (geA < E) ? ei[E + geA] : (geA - E);
        int sB = (geB < E) ? ei[geB] : (geB - E);
        int dB = (geB < E) ? ei[E + geB] : (geB - E);
        const float* xlA = g_xl + (long)sA * 512 + n0;
        const float* xrA = g_xr + (long)dA * 512 + n0;
        const float* xlB = g_xl + (long)sB * 512 + n0;
        const float* xrB = g_xr + (long)dB * 512 + n0;
        #pragma unroll
        for (int j = 0; j < NF; j++) {
            int c = wn * 32 + j * 8 + tg * 2;
            float2 a0 = reinterpret_cast<const float2*>(att + n0 + c)[0];
            float2 lA = reinterpret_cast<const float2*>(xlA + c)[0];
            float2 rAv= reinterpret_cast<const float2*>(xrA + c)[0];
            float2 lB = reinterpret_cast<const float2*>(xlB + c)[0];
            float2 rBv= reinterpret_cast<const float2*>(xrB + c)[0];
            float z0 = acc[i][j][0] + lA.x + rAv.x; z0 = z0 > 0.f ? z0 : 0.2f * z0;
            float z1 = acc[i][j][1] + lA.y + rAv.y; z1 = z1 > 0.f ? z1 : 0.2f * z1;
            float z2 = acc[i][j][2] + lB.x + rBv.x; z2 = z2 > 0.f ? z2 : 0.2f * z2;
            float z3 = acc[i][j][3] + lB.y + rBv.y; z3 = z3 > 0.f ? z3 : 0.2f * z3;
            part[i][0] += z0 * a0.x + z1 * a0.y;
            part[i][1] += z2 * a0.x + z3 * a0.y;
        }
    }
    // reduce over tg (lane bits 0,1): lanes tg==0 hold warp-level row sums
    #pragma unroll
    for (int i = 0; i < MF; i++) {
        #pragma unroll
        for (int o = 1; o <= 2; o <<= 1) {
            part[i][0] += __shfl_xor_sync(0xffffffffu, part[i][0], o);
            part[i][1] += __shfl_xor_sync(0xffffffffu, part[i][1], o);
        }
    }
    __syncthreads();     // done with As/Bs; reuse as srow[4][128]
    if (tg == 0) {
        #pragma unroll
        for (int i = 0; i < MF; i++) {
            int rA = wm * 64 + i * 16 + g;
            srow[wn * 128 + rA]     = part[i][0];
            srow[wn * 128 + rA + 8] = part[i][1];
        }
    }
    __syncthreads();
    if (tid < 128) {
        float s = srow[tid] + srow[128 + tid] + srow[256 + tid] + srow[384 + tid];
        int ge = ebase + (int)m0 + tid;
        int d  = (ge < E) ? ei[E + ge] : (ge - E);
        int h  = blockIdx.x;
        g_score[(long)ge * 4 + h] = s;
        atomicMax(&g_smax[d * 4 + h], f_enc(s));
    }
}

// ---- edge-side kernels ----------------------------------------------------
// deg + incoming edge_attr sums; thread = (edge, 4-channel chunk)
__global__ void k_degsum(const float* __restrict__ edge_attr,
                         const int* __restrict__ ei, int E) {
    int i = blockIdx.x * blockDim.x + threadIdx.x;
    if (i >= E * 8) return;
    int e = i >> 3, c4 = i & 7;
    int dst = ei[E + e];
    float4 v = reinterpret_cast<const float4*>(edge_attr + (long)e * 32)[c4];
    atomicAdd(reinterpret_cast<float4*>(&g_easum[dst * 32 + c4 * 4]), v);
    if (c4 == 0) atomicAdd(&g_deg[dst], 1.f);
}

// self-loop edge attrs = mean of incoming (0 for isolated)
__global__ void k_eamean(int N) {
    int i = blockIdx.x * blockDim.x + threadIdx.x;
    if (i >= N * 32) return;
    int nid = i >> 5;
    float d = fmaxf(g_deg[nid], 1.f);
    g_ea[i] = g_easum[i] / d;
}

__global__ void k_exp(const int* __restrict__ ei, int E, int N) {
    int i = blockIdx.x * blockDim.x + threadIdx.x;
    int tot4 = (E + N) * 4;
    if (i >= tot4) return;
    int e = i >> 2, h = i & 3;
    int d = (e < E) ? ei[E + e] : (e - E);
    float m  = f_dec(g_smax[d * 4 + h]);
    float ex = expf(g_score[i] - m);
    g_score[i] = ex;
    atomicAdd(&g_ssum[d * 4 + h], ex);
}

// alpha = ex/ssum (write to out), then agg[d] += (1/H) sum_h alpha_h*xl[src]
__global__ void k_agg(const int* __restrict__ ei, float* __restrict__ out_alpha,
                      int E, int N, int write_out) {
    int tot = E + N;
    int e = blockIdx.x * 8 + (threadIdx.x >> 5);
    if (e >= tot) return;
    int l = threadIdx.x & 31;
    int s = (e < E) ? ei[e]     : (e - E);
    int d = (e < E) ? ei[E + e] : (e - E);
    float a0 = __fdividef(g_score[(long)e * 4 + 0], g_ssum[d * 4 + 0]);
    float a1 = __fdividef(g_score[(long)e * 4 + 1], g_ssum[d * 4 + 1]);
    float a2 = __fdividef(g_score[(long)e * 4 + 2], g_ssum[d * 4 + 2]);
    float a3 = __fdividef(g_score[(long)e * 4 + 3], g_ssum[d * 4 + 3]);
    if (write_out && l < 4) {
        float a = (l == 0) ? a0 : (l == 1) ? a1 : (l == 2) ? a2 : a3;
        out_alpha[(long)e * 4 + l] = a;
    }
    a0 *= 0.25f; a1 *= 0.25f; a2 *= 0.25f; a3 *= 0.25f;
    const float4* xl4 = reinterpret_cast<const float4*>(g_xl + (long)s * 512);
    float4 v0 = xl4[ 0 + l], v1 = xl4[32 + l], v2 = xl4[64 + l], v3 = xl4[96 + l];
    float4 r;
    r.x = a0 * v0.x + a1 * v1.x + a2 * v2.x + a3 * v3.x;
    r.y = a0 * v0.y + a1 * v1.y + a2 * v2.y + a3 * v3.y;
    r.z = a0 * v0.z + a1 * v1.z + a2 * v2.z + a3 * v3.z;
    r.w = a0 * v0.w + a1 * v1.w + a2 * v2.w + a3 * v3.w;
    atomicAdd(reinterpret_cast<float4*>(g_agg + d * 128 + 4 * l), r);
}

// ---------------------------------------------------------------------------
static inline int G(int n) { return (n + 255) / 256; }

extern "C" void kernel_launch(void* const* d_in, const int* in_sizes, int n_in,
                              void* d_out, int out_size) {
    const float* x         = (const float*)d_in[0];
    const int*   ei        = (const int*)  d_in[1];
    const float* edge_attr = (const float*)d_in[2];
    const float* Wl  = (const float*)d_in[4];
    const float* bl  = (const float*)d_in[5];
    const float* Wr  = (const float*)d_in[6];
    const float* br  = (const float*)d_in[7];
    const float* We  = (const float*)d_in[8];
    const float* att = (const float*)d_in[9];
    const float* gbn = (const float*)d_in[10];
    const float* W1  = (const float*)d_in[11];
    const float* b1  = (const float*)d_in[12];
    const float* W2  = (const float*)d_in[13];
    const float* b2  = (const float*)d_in[14];
    const float* Wc  = (const float*)d_in[15];
    const float* bc  = (const float*)d_in[16];
    const float* nw0 = (const float*)d_in[17];
    const float* nb0 = (const float*)d_in[18];
    const float* nw1 = (const float*)d_in[19];
    const float* nb1 = (const float*)d_in[20];
    const float* nw2 = (const float*)d_in[21];
    const float* nb2 = (const float*)d_in[22];
    const float* nw3 = (const float*)d_in[23];
    const float* nb3 = (const float*)d_in[24];

    int N = in_sizes[0] / 128;
    int E = in_sizes[1] / 2;
    int TOT = E + N;
    float* out = (float*)d_out;
    int write_alpha = (out_size >= N * 64 + TOT * 4) ? 1 : 0;
    float* out_alpha = out + (size_t)N * 64;

    float *h0, *r1, *n1, *r2, *n2, *ea, *hid, *cls, *stats;
    cudaGetSymbolAddress((void**)&h0,    g_h0);
    cudaGetSymbolAddress((void**)&r1,    g_r1);
    cudaGetSymbolAddress((void**)&n1,    g_n1);
    cudaGetSymbolAddress((void**)&r2,    g_r2);
    cudaGetSymbolAddress((void**)&n2,    g_n2);
    cudaGetSymbolAddress((void**)&ea,    g_ea);
    cudaGetSymbolAddress((void**)&hid,   g_hid);
    cudaGetSymbolAddress((void**)&cls,   g_cls);
    cudaGetSymbolAddress((void**)&stats, g_stats);
    float* xl; cudaGetSymbolAddress((void**)&xl, g_xl);
    float* xr; cudaGetSymbolAddress((void**)&xr, g_xr);

    const int SM128 = (2 * 128 * 36 + 2 * 128 * 36) * 4;  // 73728 B
    const int SM64  = (2 * 128 * 36 + 2 *  64 * 36) * 4;  // 55296 B
    const int SMSC  = (128 * 36 + 128 * 36) * 4;          // 36864 B
    cudaFuncSetAttribute(k_tgemm<128,2,4,1>, cudaFuncAttributeMaxDynamicSharedMemorySize, SM128);
    cudaFuncSetAttribute(k_tgemm<128,2,4,2>, cudaFuncAttributeMaxDynamicSharedMemorySize, SM128);
    cudaFuncSetAttribute(k_tgemm<128,2,4,3>, cudaFuncAttributeMaxDynamicSharedMemorySize, SM128);
    cudaFuncSetAttribute(k_tgemm<64,4,2,1>,  cudaFuncAttributeMaxDynamicSharedMemorySize, SM64);
    cudaFuncSetAttribute(k_gemm_score,       cudaFuncAttributeMaxDynamicSharedMemorySize, SMSC);

    // --- init all atomic targets (one kernel) ---
    k_init<<<G(N * 128), 256>>>(N);

    // --- graph_norm 0 ---
    k_reduce<<<1024, 256>>>(x, N * 128 / 4, stats + 0);
    k_norm<<<G(N * 128), 256>>>(x, h0, nw0, nb0, stats + 0, 127, N * 128,
                                1.f / (float)(N * 128));

    // --- GATv2 linear transforms ---
    k_tgemm<128,2,4,1><<<dim3(4, N/128), 256, SM128>>>(h0, Wl, bl, nullptr, xl, N, 512, 128);
    k_tgemm<128,2,4,1><<<dim3(4, N/128), 256, SM128>>>(h0, Wr, br, nullptr, xr, N, 512, 128);

    // --- self-loop edge attrs ---
    k_degsum<<<G(E * 8), 256>>>(edge_attr, ei, E);
    k_eamean<<<G(N * 32), 256>>>(N);

    // --- fused ef GEMM + attention scores (ef never materialized) ---
    k_gemm_score<<<dim3(4, E/128), 256, SMSC>>>(edge_attr, We, att, ei, 0, E);
    k_gemm_score<<<dim3(4, N/128), 256, SMSC>>>(ea, We, att, ei, E, E);

    // --- segment softmax + weighted aggregation ---
    k_exp<<<G(TOT * 4), 256>>>(ei, E, N);
    k_agg<<<(TOT + 7) / 8, 256>>>(ei, out_alpha, E, N, write_alpha);

    // --- residual + graph_norm 1 ---
    k_res_reduce<<<1024, 256>>>(gbn, N * 128 / 4, stats + 2);
    k_norm<<<G(N * 128), 256>>>(r1, n1, nw1, nb1, stats + 2, 127, N * 128,
                                1.f / (float)(N * 128));

    // --- MLP ---
    k_tgemm<128,2,4,2><<<dim3(16, N/128), 256, SM128>>>(n1, W1, b1, nullptr, hid, N, 2048, 128);
    k_tgemm<128,2,4,3><<<dim3(1, N/128), 256, SM128>>>(hid, W2, b2, n1, r2, N, 128, 2048);

    // --- graph_norm 2 ---
    k_reduce<<<1024, 256>>>(r2, N * 128 / 4, stats + 4);
    k_norm<<<G(N * 128), 256>>>(r2, n2, nw2, nb2, stats + 4, 127, N * 128,
                                1.f / (float)(N * 128));

    // --- classifier + graph_norm 3 ---
    k_tgemm<64,4,2,1><<<dim3(1, N/128), 256, SM64>>>(n2, Wc, bc, nullptr, cls, N, 64, 128);
    k_reduce<<<512, 256>>>(cls, N * 64 / 4, stats + 6);
    k_norm<<<G(N * 64), 256>>>(cls, out, nw3, nb3, stats + 6, 63, N * 64,
                               1.f / (float)(N * 64));
}

// round 6
// speedup vs baseline: 4.1976x; 1.0233x over previous
#include <cuda_runtime.h>
#include <math.h>
#include <float.h>

// ---------------------------------------------------------------------------
// SynGNNLayer. R6: 3-stage cp.async pipelined tf32 GEMMs; all GEMM operands
// pre-rounded to tf32 at their producers so the GEMM hot loop has zero cvt.
// ---------------------------------------------------------------------------

#define NMAX 16384
#define EMAX 131072
#define TOTMAX (EMAX + NMAX)

static __device__ float g_h0 [NMAX * 128];
static __device__ float g_r1 [NMAX * 128];
static __device__ float g_n1 [NMAX * 128];
static __device__ float g_r2 [NMAX * 128];
static __device__ float g_n2 [NMAX * 128];
static __device__ float g_xl [NMAX * 512];
static __device__ float g_xr [NMAX * 512];
static __device__ float g_ea [NMAX * 32];            // self-loop attrs (tf32)
static __device__ float g_eat[EMAX * 32];            // tf32 copy of edge_attr
static __device__ float g_hid[(size_t)NMAX * 2048];
static __device__ float g_easum[NMAX * 32];
static __device__ float g_deg [NMAX];
static __device__ float g_score[TOTMAX * 4];
static __device__ unsigned g_smax[NMAX * 4];
static __device__ float g_ssum[NMAX * 4];
static __device__ float g_agg [NMAX * 128];
static __device__ float g_cls [NMAX * 64];
static __device__ float g_stats[8];
// tf32-rounded weight copies
static __device__ float g_wl [512 * 128];
static __device__ float g_wr [512 * 128];
static __device__ float g_we [512 * 32];
static __device__ float g_w1 [2048 * 128];
static __device__ float g_w2 [128 * 2048];
static __device__ float g_wc [64 * 128];

// ---- helpers --------------------------------------------------------------
__device__ __forceinline__ unsigned f_enc(float f) {
    unsigned u = __float_as_uint(f);
    return (u & 0x80000000u) ? ~u : (u | 0x80000000u);
}
__device__ __forceinline__ float f_dec(unsigned k) {
    return (k & 0x80000000u) ? __uint_as_float(k ^ 0x80000000u)
                             : __uint_as_float(~k);
}
__device__ __forceinline__ unsigned tf32r(float f) {
    unsigned u; asm("cvt.rna.tf32.f32 %0, %1;" : "=r"(u) : "f"(f)); return u;
}
__device__ __forceinline__ float tf32f(float f) {
    return __uint_as_float(tf32r(f));
}
__device__ __forceinline__ void cp16(void* smem, const void* gmem) {
    unsigned s = (unsigned)__cvta_generic_to_shared(smem);
    asm volatile("cp.async.cg.shared.global [%0], [%1], 16;\n" :: "r"(s), "l"(gmem));
}
#define CP_COMMIT() asm volatile("cp.async.commit_group;\n" ::: "memory")
#define CP_WAIT1()  asm volatile("cp.async.wait_group 1;\n" ::: "memory")

// ---------------------------------------------------------------------------
__global__ void k_init(int N) {
    int i = blockIdx.x * blockDim.x + threadIdx.x;
    if (i < N * 128) g_agg[i] = 0.f;
    if (i < N * 32)  g_easum[i] = 0.f;
    if (i < N * 4)   { g_ssum[i] = 0.f; g_smax[i] = 0x00800000u; }
    if (i < N)       g_deg[i] = 0.f;
    if (i < 8)       g_stats[i] = 0.f;
}

// tf32-round copy
__global__ void k_round(const float* __restrict__ src, float* __restrict__ dst, int n4) {
    int i = blockIdx.x * blockDim.x + threadIdx.x;
    if (i >= n4) return;
    float4 v = reinterpret_cast<const float4*>(src)[i];
    v.x = tf32f(v.x); v.y = tf32f(v.y); v.z = tf32f(v.z); v.w = tf32f(v.w);
    reinterpret_cast<float4*>(dst)[i] = v;
}

// sum + sumsq reduction
__global__ void k_reduce(const float* __restrict__ x, int n4, float* __restrict__ out) {
    float s = 0.f, ss = 0.f;
    for (int i = blockIdx.x * blockDim.x + threadIdx.x; i < n4; i += gridDim.x * blockDim.x) {
        float4 v = reinterpret_cast<const float4*>(x)[i];
        s  += v.x + v.y + v.z + v.w;
        ss += v.x * v.x + v.y * v.y + v.z * v.z + v.w * v.w;
    }
    #pragma unroll
    for (int o = 16; o > 0; o >>= 1) {
        s  += __shfl_xor_sync(0xffffffffu, s,  o);
        ss += __shfl_xor_sync(0xffffffffu, ss, o);
    }
    __shared__ float shs[8], shss[8];
    int w = threadIdx.x >> 5;
    if ((threadIdx.x & 31) == 0) { shs[w] = s; shss[w] = ss; }
    __syncthreads();
    if (threadIdx.x < 8) {
        s = shs[threadIdx.x]; ss = shss[threadIdx.x];
        #pragma unroll
        for (int o = 4; o > 0; o >>= 1) {
            s  += __shfl_xor_sync(0xffu, s,  o);
            ss += __shfl_xor_sync(0xffu, ss, o);
        }
        if (threadIdx.x == 0) { atomicAdd(out, s); atomicAdd(out + 1, ss); }
    }
}

// residual + reduction: r1 = h0 + agg + bias
__global__ void k_res_reduce(const float* __restrict__ gat_bias, int n4,
                             float* __restrict__ out) {
    float s = 0.f, ss = 0.f;
    const float4* b4 = reinterpret_cast<const float4*>(gat_bias);
    for (int i = blockIdx.x * blockDim.x + threadIdx.x; i < n4; i += gridDim.x * blockDim.x) {
        float4 a = reinterpret_cast<const float4*>(g_h0)[i];
        float4 g = reinterpret_cast<const float4*>(g_agg)[i];
        float4 b = b4[i & 31];
        float4 v = { a.x + g.x + b.x, a.y + g.y + b.y,
                     a.z + g.z + b.z, a.w + g.w + b.w };
        reinterpret_cast<float4*>(g_r1)[i] = v;
        s  += v.x + v.y + v.z + v.w;
        ss += v.x * v.x + v.y * v.y + v.z * v.z + v.w * v.w;
    }
    #pragma unroll
    for (int o = 16; o > 0; o >>= 1) {
        s  += __shfl_xor_sync(0xffffffffu, s,  o);
        ss += __shfl_xor_sync(0xffffffffu, ss, o);
    }
    __shared__ float shs[8], shss[8];
    int w = threadIdx.x >> 5;
    if ((threadIdx.x & 31) == 0) { shs[w] = s; shss[w] = ss; }
    __syncthreads();
    if (threadIdx.x < 8) {
        s = shs[threadIdx.x]; ss = shss[threadIdx.x];
        #pragma unroll
        for (int o = 4; o > 0; o >>= 1) {
            s  += __shfl_xor_sync(0xffu, s,  o);
            ss += __shfl_xor_sync(0xffu, ss, o);
        }
        if (threadIdx.x == 0) { atomicAdd(out, s); atomicAdd(out + 1, ss); }
    }
}

// graph_norm apply; ROUND=1 -> tf32-round the result (feeds a GEMM)
template <int ROUND>
__global__ void k_norm(const float* __restrict__ x, float* __restrict__ y,
                       const float* __restrict__ w, const float* __restrict__ b,
                       const float* __restrict__ st, int Dmask, int n, float invn) {
    int i = blockIdx.x * blockDim.x + threadIdx.x;
    if (i >= n) return;
    float mu  = st[0] * invn;
    float var = st[1] * invn - mu * mu;
    float inv = 1.f / (sqrtf(fmaxf(var, 0.f)) + 1e-5f);
    int c = i & Dmask;
    float v = (x[i] - mu) * inv * w[c] + b[c];
    y[i] = ROUND ? tf32f(v) : v;
}

// ---------------------------------------------------------------------------
// Tensor-core GEMM, 3-stage cp.async pipeline, operands pre-rounded to tf32.
// C[M,Nn] = A[M,K] @ W[Nn,K]^T.  EPI: 1 +bias, 2 +bias,relu(+tf32 round),
// 3 +bias,+res
// ---------------------------------------------------------------------------
template<int BN, int WROWS, int WCOLS, int EPI>
__global__ void __launch_bounds__(256)
k_tgemm(const float* __restrict__ A, const float* __restrict__ W,
        const float* __restrict__ bias, const float* __restrict__ res,
        float* __restrict__ C, int M, int Nn, int K)
{
    constexpr int BM = 128, BK = 32, LDA = BK + 4, STAGES = 3;
    constexpr int MF = BM / (WROWS * 16);
    constexpr int NF = BN / (WCOLS * 8);
    constexpr int A_CP = (BM * BK / 4) / 256;
    constexpr int B_CP = (BN * BK / 4) / 256;

    extern __shared__ float sh[];
    float* As = sh;                          // [STAGES][BM][LDA]
    float* Bs = sh + STAGES * BM * LDA;      // [STAGES][BN][LDA]

    const int tid = threadIdx.x;
    const int wid = tid >> 5, lane = tid & 31;
    const int wm = wid / WCOLS, wn = wid % WCOLS;
    const int g = lane >> 2, tg = lane & 3;
    const long m0 = (long)blockIdx.y * BM;
    const int  n0 = blockIdx.x * BN;

    auto issue = [&](int stage, int kk) {
        #pragma unroll
        for (int i = 0; i < A_CP; i++) {
            int idx = tid + i * 256;
            int r = idx >> 3, c4 = idx & 7;
            cp16(&As[stage * BM * LDA + r * LDA + c4 * 4],
                 A + (m0 + r) * K + kk + c4 * 4);
        }
        #pragma unroll
        for (int i = 0; i < B_CP; i++) {
            int idx = tid + i * 256;
            int r = idx >> 3, c4 = idx & 7;
            cp16(&Bs[stage * BN * LDA + r * LDA + c4 * 4],
                 W + (long)(n0 + r) * K + kk + c4 * 4);
        }
        CP_COMMIT();
    };

    const int NT = K / BK;
    issue(0, 0);
    if (1 < NT) issue(1, BK); else CP_COMMIT();

    float acc[MF][NF][4] = {};
    for (int kt = 0; kt < NT; kt++) {
        CP_WAIT1();
        __syncthreads();
        if (kt + STAGES - 1 < NT)
            issue((kt + STAGES - 1) % STAGES, (kt + STAGES - 1) * BK);
        else
            CP_COMMIT();
        const unsigned* Asb = reinterpret_cast<const unsigned*>(As) + (kt % STAGES) * BM * LDA;
        const unsigned* Bsb = reinterpret_cast<const unsigned*>(Bs) + (kt % STAGES) * BN * LDA;
        #pragma unroll
        for (int k8 = 0; k8 < BK / 8; k8++) {
            unsigned af[MF][4], bf[NF][2];
            #pragma unroll
            for (int i = 0; i < MF; i++) {
                int r = wm * (MF * 16) + i * 16 + g;
                const unsigned* p = Asb + r * LDA + k8 * 8;
                af[i][0] = p[tg];
                af[i][1] = p[8 * LDA + tg];
                af[i][2] = p[tg + 4];
                af[i][3] = p[8 * LDA + tg + 4];
            }
            #pragma unroll
            for (int j = 0; j < NF; j++) {
                int c = wn * (NF * 8) + j * 8 + g;
                const unsigned* p = Bsb + c * LDA + k8 * 8;
                bf[j][0] = p[tg];
                bf[j][1] = p[tg + 4];
            }
            #pragma unroll
            for (int i = 0; i < MF; i++)
                #pragma unroll
                for (int j = 0; j < NF; j++) {
                    asm volatile(
                        "mma.sync.aligned.m16n8k8.row.col.f32.tf32.tf32.f32 "
                        "{%0,%1,%2,%3}, {%4,%5,%6,%7}, {%8,%9}, {%0,%1,%2,%3};\n"
                        : "+f"(acc[i][j][0]), "+f"(acc[i][j][1]),
                          "+f"(acc[i][j][2]), "+f"(acc[i][j][3])
                        : "r"(af[i][0]), "r"(af[i][1]), "r"(af[i][2]), "r"(af[i][3]),
                          "r"(bf[j][0]), "r"(bf[j][1]));
                }
        }
    }

    #pragma unroll
    for (int i = 0; i < MF; i++) {
        long mA = m0 + wm * (MF * 16) + i * 16 + g;
        long mB = mA + 8;
        #pragma unroll
        for (int j = 0; j < NF; j++) {
            int c = n0 + wn * (NF * 8) + j * 8 + tg * 2;
            float v0 = acc[i][j][0], v1 = acc[i][j][1];
            float v2 = acc[i][j][2], v3 = acc[i][j][3];
            if (EPI >= 1) {
                float b0 = bias[c], b1 = bias[c + 1];
                v0 += b0; v1 += b1; v2 += b0; v3 += b1;
            }
            if (EPI == 2) {      // relu + tf32 round (feeds MLP2 GEMM)
                v0 = tf32f(fmaxf(v0, 0.f)); v1 = tf32f(fmaxf(v1, 0.f));
                v2 = tf32f(fmaxf(v2, 0.f)); v3 = tf32f(fmaxf(v3, 0.f));
            }
            if (EPI == 3) {
                float2 rA = reinterpret_cast<const float2*>(res + mA * Nn + c)[0];
                float2 rB = reinterpret_cast<const float2*>(res + mB * Nn + c)[0];
                v0 += rA.x; v1 += rA.y; v2 += rB.x; v3 += rB.y;
            }
            reinterpret_cast<float2*>(C + mA * Nn + c)[0] = make_float2(v0, v1);
            reinterpret_cast<float2*>(C + mB * Nn + c)[0] = make_float2(v2, v3);
        }
    }
}

// ---------------------------------------------------------------------------
// ef GEMM + fused attention score epilogue (inputs pre-rounded; no cvt).
// ---------------------------------------------------------------------------
__global__ void __launch_bounds__(256)
k_gemm_score(const float* __restrict__ A, const float* __restrict__ W,
             const float* __restrict__ att, const int* __restrict__ ei,
             int ebase, int E)
{
    constexpr int BM = 128, BN = 128, BK = 32, LDA = BK + 4;
    constexpr int MF = 4, NF = 4;

    extern __shared__ float shf[];
    float* As = shf;
    float* Bs = shf + BM * LDA;
    float* srow = shf;

    const int tid = threadIdx.x;
    const int wid = tid >> 5, lane = tid & 31;
    const int wm = wid >> 2, wn = wid & 3;
    const int g = lane >> 2, tg = lane & 3;
    const long m0 = (long)blockIdx.y * BM;
    const int  n0 = blockIdx.x * BN;              // = h*128

    #pragma unroll
    for (int t = 0; t < 4; t++) {
        int idx = tid + t * 256;
        int r = idx >> 3, c4 = idx & 7;
        reinterpret_cast<float4*>(&As[r * LDA + c4 * 4])[0] =
            reinterpret_cast<const float4*>(A + (m0 + r) * BK)[c4];
        reinterpret_cast<float4*>(&Bs[r * LDA + c4 * 4])[0] =
            reinterpret_cast<const float4*>(W + (long)(n0 + r) * BK)[c4];
    }
    __syncthreads();

    float acc[MF][NF][4] = {};
    const unsigned* Asu = reinterpret_cast<const unsigned*>(As);
    const unsigned* Bsu = reinterpret_cast<const unsigned*>(Bs);
    #pragma unroll
    for (int k8 = 0; k8 < 4; k8++) {
        unsigned af[MF][4], bf[NF][2];
        #pragma unroll
        for (int i = 0; i < MF; i++) {
            int r = wm * 64 + i * 16 + g;
            const unsigned* p = Asu + r * LDA + k8 * 8;
            af[i][0] = p[tg];
            af[i][1] = p[8 * LDA + tg];
            af[i][2] = p[tg + 4];
            af[i][3] = p[8 * LDA + tg + 4];
        }
        #pragma unroll
        for (int j = 0; j < NF; j++) {
            int c = wn * 32 + j * 8 + g;
            const unsigned* p = Bsu + c * LDA + k8 * 8;
            bf[j][0] = p[tg];
            bf[j][1] = p[tg + 4];
        }
        #pragma unroll
        for (int i = 0; i < MF; i++)
            #pragma unroll
            for (int j = 0; j < NF; j++) {
                asm volatile(
                    "mma.sync.aligned.m16n8k8.row.col.f32.tf32.tf32.f32 "
                    "{%0,%1,%2,%3}, {%4,%5,%6,%7}, {%8,%9}, {%0,%1,%2,%3};\n"
                    : "+f"(acc[i][j][0]), "+f"(acc[i][j][1]),
                      "+f"(acc[i][j][2]), "+f"(acc[i][j][3])
                    : "r"(af[i][0]), "r"(af[i][1]), "r"(af[i][2]), "r"(af[i][3]),
                      "r"(bf[j][0]), "r"(bf[j][1]));
            }
    }

    // score epilogue: leaky(acc + xl[src] + xr[dst]) dot att
    float part[MF][2] = {};
    #pragma unroll
    for (int i = 0; i < MF; i++) {
        int rA = wm * 64 + i * 16 + g;
        int rB = rA + 8;
        int geA = ebase + (int)m0 + rA;
        int geB = ebase + (int)m0 + rB;
        int sA = (geA < E) ? ei[geA] : (geA - E);
        int dA = (geA < E) ? ei[E + geA] : (geA - E);
        int sB = (geB < E) ? ei[geB] : (geB - E);
        int dB = (geB < E) ? ei[E + geB] : (geB - E);
        const float* xlA = g_xl + (long)sA * 512 + n0;
        const float* xrA = g_xr + (long)dA * 512 + n0;
        const float* xlB = g_xl + (long)sB * 512 + n0;
        const float* xrB = g_xr + (long)dB * 512 + n0;
        #pragma unroll
        for (int j = 0; j < NF; j++) {
            int c = wn * 32 + j * 8 + tg * 2;
            float2 a0 = reinterpret_cast<const float2*>(att + n0 + c)[0];
            float2 lA = reinterpret_cast<const float2*>(xlA + c)[0];
            float2 rAv= reinterpret_cast<const float2*>(xrA + c)[0];
            float2 lB = reinterpret_cast<const float2*>(xlB + c)[0];
            float2 rBv= reinterpret_cast<const float2*>(xrB + c)[0];
            float z0 = acc[i][j][0] + lA.x + rAv.x; z0 = z0 > 0.f ? z0 : 0.2f * z0;
            float z1 = acc[i][j][1] + lA.y + rAv.y; z1 = z1 > 0.f ? z1 : 0.2f * z1;
            float z2 = acc[i][j][2] + lB.x + rBv.x; z2 = z2 > 0.f ? z2 : 0.2f * z2;
            float z3 = acc[i][j][3] + lB.y + rBv.y; z3 = z3 > 0.f ? z3 : 0.2f * z3;
            part[i][0] += z0 * a0.x + z1 * a0.y;
            part[i][1] += z2 * a0.x + z3 * a0.y;
        }
    }
    #pragma unroll
    for (int i = 0; i < MF; i++) {
        #pragma unroll
        for (int o = 1; o <= 2; o <<= 1) {
            part[i][0] += __shfl_xor_sync(0xffffffffu, part[i][0], o);
            part[i][1] += __shfl_xor_sync(0xffffffffu, part[i][1], o);
        }
    }
    __syncthreads();
    if (tg == 0) {
        #pragma unroll
        for (int i = 0; i < MF; i++) {
            int rA = wm * 64 + i * 16 + g;
            srow[wn * 128 + rA]     = part[i][0];
            srow[wn * 128 + rA + 8] = part[i][1];
        }
    }
    __syncthreads();
    if (tid < 128) {
        float s = srow[tid] + srow[128 + tid] + srow[256 + tid] + srow[384 + tid];
        int ge = ebase + (int)m0 + tid;
        int d  = (ge < E) ? ei[E + ge] : (ge - E);
        int h  = blockIdx.x;
        g_score[(long)ge * 4 + h] = s;
        atomicMax(&g_smax[d * 4 + h], f_enc(s));
    }
}

// ---- edge-side kernels ----------------------------------------------------
__global__ void k_degsum(const float* __restrict__ edge_attr,
                         const int* __restrict__ ei, int E) {
    int i = blockIdx.x * blockDim.x + threadIdx.x;
    if (i >= E * 8) return;
    int e = i >> 3, c4 = i & 7;
    int dst = ei[E + e];
    float4 v = reinterpret_cast<const float4*>(edge_attr + (long)e * 32)[c4];
    atomicAdd(reinterpret_cast<float4*>(&g_easum[dst * 32 + c4 * 4]), v);
    if (c4 == 0) atomicAdd(&g_deg[dst], 1.f);
}

// self-loop edge attrs = mean of incoming (tf32-rounded: feeds GEMM)
__global__ void k_eamean(int N) {
    int i = blockIdx.x * blockDim.x + threadIdx.x;
    if (i >= N * 32) return;
    int nid = i >> 5;
    float d = fmaxf(g_deg[nid], 1.f);
    g_ea[i] = tf32f(g_easum[i] / d);
}

__global__ void k_exp(const int* __restrict__ ei, int E, int N) {
    int i = blockIdx.x * blockDim.x + threadIdx.x;
    int tot4 = (E + N) * 4;
    if (i >= tot4) return;
    int e = i >> 2, h = i & 3;
    int d = (e < E) ? ei[E + e] : (e - E);
    float m  = f_dec(g_smax[d * 4 + h]);
    float ex = expf(g_score[i] - m);
    g_score[i] = ex;
    atomicAdd(&g_ssum[d * 4 + h], ex);
}

__global__ void k_agg(const int* __restrict__ ei, float* __restrict__ out_alpha,
                      int E, int N, int write_out) {
    int tot = E + N;
    int e = blockIdx.x * 8 + (threadIdx.x >> 5);
    if (e >= tot) return;
    int l = threadIdx.x & 31;
    int s = (e < E) ? ei[e]     : (e - E);
    int d = (e < E) ? ei[E + e] : (e - E);
    float a0 = __fdividef(g_score[(long)e * 4 + 0], g_ssum[d * 4 + 0]);
    float a1 = __fdividef(g_score[(long)e * 4 + 1], g_ssum[d * 4 + 1]);
    float a2 = __fdividef(g_score[(long)e * 4 + 2], g_ssum[d * 4 + 2]);
    float a3 = __fdividef(g_score[(long)e * 4 + 3], g_ssum[d * 4 + 3]);
    if (write_out && l < 4) {
        float a = (l == 0) ? a0 : (l == 1) ? a1 : (l == 2) ? a2 : a3;
        out_alpha[(long)e * 4 + l] = a;
    }
    a0 *= 0.25f; a1 *= 0.25f; a2 *= 0.25f; a3 *= 0.25f;
    const float4* xl4 = reinterpret_cast<const float4*>(g_xl + (long)s * 512);
    float4 v0 = xl4[ 0 + l], v1 = xl4[32 + l], v2 = xl4[64 + l], v3 = xl4[96 + l];
    float4 r;
    r.x = a0 * v0.x + a1 * v1.x + a2 * v2.x + a3 * v3.x;
    r.y = a0 * v0.y + a1 * v1.y + a2 * v2.y + a3 * v3.y;
    r.z = a0 * v0.z + a1 * v1.z + a2 * v2.z + a3 * v3.z;
    r.w = a0 * v0.w + a1 * v1.w + a2 * v2.w + a3 * v3.w;
    atomicAdd(reinterpret_cast<float4*>(g_agg + d * 128 + 4 * l), r);
}

// ---------------------------------------------------------------------------
static inline int G(int n) { return (n + 255) / 256; }

extern "C" void kernel_launch(void* const* d_in, const int* in_sizes, int n_in,
                              void* d_out, int out_size) {
    const float* x         = (const float*)d_in[0];
    const int*   ei        = (const int*)  d_in[1];
    const float* edge_attr = (const float*)d_in[2];
    const float* Wl  = (const float*)d_in[4];
    const float* bl  = (const float*)d_in[5];
    const float* Wr  = (const float*)d_in[6];
    const float* br  = (const float*)d_in[7];
    const float* We  = (const float*)d_in[8];
    const float* att = (const float*)d_in[9];
    const float* gbn = (const float*)d_in[10];
    const float* W1  = (const float*)d_in[11];
    const float* b1  = (const float*)d_in[12];
    const float* W2  = (const float*)d_in[13];
    const float* b2  = (const float*)d_in[14];
    const float* Wc  = (const float*)d_in[15];
    const float* bc  = (const float*)d_in[16];
    const float* nw0 = (const float*)d_in[17];
    const float* nb0 = (const float*)d_in[18];
    const float* nw1 = (const float*)d_in[19];
    const float* nb1 = (const float*)d_in[20];
    const float* nw2 = (const float*)d_in[21];
    const float* nb2 = (const float*)d_in[22];
    const float* nw3 = (const float*)d_in[23];
    const float* nb3 = (const float*)d_in[24];

    int N = in_sizes[0] / 128;
    int E = in_sizes[1] / 2;
    int TOT = E + N;
    float* out = (float*)d_out;
    int write_alpha = (out_size >= N * 64 + TOT * 4) ? 1 : 0;
    float* out_alpha = out + (size_t)N * 64;

    float *h0, *r1, *n1, *r2, *n2, *ea, *eat, *hid, *cls, *stats;
    float *wl, *wr, *we, *w1, *w2, *wc, *xl, *xr;
    cudaGetSymbolAddress((void**)&h0,    g_h0);
    cudaGetSymbolAddress((void**)&r1,    g_r1);
    cudaGetSymbolAddress((void**)&n1,    g_n1);
    cudaGetSymbolAddress((void**)&r2,    g_r2);
    cudaGetSymbolAddress((void**)&n2,    g_n2);
    cudaGetSymbolAddress((void**)&ea,    g_ea);
    cudaGetSymbolAddress((void**)&eat,   g_eat);
    cudaGetSymbolAddress((void**)&hid,   g_hid);
    cudaGetSymbolAddress((void**)&cls,   g_cls);
    cudaGetSymbolAddress((void**)&stats, g_stats);
    cudaGetSymbolAddress((void**)&wl,    g_wl);
    cudaGetSymbolAddress((void**)&wr,    g_wr);
    cudaGetSymbolAddress((void**)&we,    g_we);
    cudaGetSymbolAddress((void**)&w1,    g_w1);
    cudaGetSymbolAddress((void**)&w2,    g_w2);
    cudaGetSymbolAddress((void**)&wc,    g_wc);
    cudaGetSymbolAddress((void**)&xl,    g_xl);
    cudaGetSymbolAddress((void**)&xr,    g_xr);

    const int SM128 = 3 * (128 + 128) * 36 * 4;  // 110592 B
    const int SM64  = 3 * (128 +  64) * 36 * 4;  // 82944 B
    const int SMSC  = (128 * 36 + 128 * 36) * 4; // 36864 B
    cudaFuncSetAttribute(k_tgemm<128,2,4,1>, cudaFuncAttributeMaxDynamicSharedMemorySize, SM128);
    cudaFuncSetAttribute(k_tgemm<128,2,4,2>, cudaFuncAttributeMaxDynamicSharedMemorySize, SM128);
    cudaFuncSetAttribute(k_tgemm<128,2,4,3>, cudaFuncAttributeMaxDynamicSharedMemorySize, SM128);
    cudaFuncSetAttribute(k_tgemm<64,4,2,1>,  cudaFuncAttributeMaxDynamicSharedMemorySize, SM64);
    cudaFuncSetAttribute(k_gemm_score,       cudaFuncAttributeMaxDynamicSharedMemorySize, SMSC);

    // --- init + tf32 weight/attr copies ---
    k_init<<<G(N * 128), 256>>>(N);
    k_round<<<G(E * 8), 256>>>(edge_attr, eat, E * 8);
    k_round<<<G(512 * 32), 256>>>(Wl, wl, 512 * 32);
    k_round<<<G(512 * 32), 256>>>(Wr, wr, 512 * 32);
    k_round<<<G(512 * 8), 256>>>(We, we, 512 * 8);
    k_round<<<G(2048 * 32), 256>>>(W1, w1, 2048 * 32);
    k_round<<<G(128 * 512), 256>>>(W2, w2, 128 * 512);
    k_round<<<G(64 * 32), 256>>>(Wc, wc, 64 * 32);

    // --- graph_norm 0 (rounded: feeds xl/xr GEMMs) ---
    k_reduce<<<1024, 256>>>(x, N * 128 / 4, stats + 0);
    k_norm<1><<<G(N * 128), 256>>>(x, h0, nw0, nb0, stats + 0, 127, N * 128,
                                   1.f / (float)(N * 128));

    // --- GATv2 linear transforms ---
    k_tgemm<128,2,4,1><<<dim3(4, N/128), 256, SM128>>>(h0, wl, bl, nullptr, xl, N, 512, 128);
    k_tgemm<128,2,4,1><<<dim3(4, N/128), 256, SM128>>>(h0, wr, br, nullptr, xr, N, 512, 128);

    // --- self-loop edge attrs ---
    k_degsum<<<G(E * 8), 256>>>(edge_attr, ei, E);
    k_eamean<<<G(N * 32), 256>>>(N);

    // --- fused ef GEMM + attention scores ---
    k_gemm_score<<<dim3(4, E/128), 256, SMSC>>>(eat, we, att, ei, 0, E);
    k_gemm_score<<<dim3(4, N/128), 256, SMSC>>>(ea, we, att, ei, E, E);

    // --- segment softmax + weighted aggregation ---
    k_exp<<<G(TOT * 4), 256>>>(ei, E, N);
    k_agg<<<(TOT + 7) / 8, 256>>>(ei, out_alpha, E, N, write_alpha);

    // --- residual + graph_norm 1 (rounded: feeds MLP) ---
    k_res_reduce<<<1024, 256>>>(gbn, N * 128 / 4, stats + 2);
    k_norm<1><<<G(N * 128), 256>>>(r1, n1, nw1, nb1, stats + 2, 127, N * 128,
                                   1.f / (float)(N * 128));

    // --- MLP ---
    k_tgemm<128,2,4,2><<<dim3(16, N/128), 256, SM128>>>(n1, w1, b1, nullptr, hid, N, 2048, 128);
    k_tgemm<128,2,4,3><<<dim3(1, N/128), 256, SM128>>>(hid, w2, b2, n1, r2, N, 128, 2048);

    // --- graph_norm 2 (rounded: feeds classifier) ---
    k_reduce<<<1024, 256>>>(r2, N * 128 / 4, stats + 4);
    k_norm<1><<<G(N * 128), 256>>>(r2, n2, nw2, nb2, stats + 4, 127, N * 128,
                                   1.f / (float)(N * 128));

    // --- classifier + graph_norm 3 (final output: full fp32) ---
    k_tgemm<64,4,2,1><<<dim3(1, N/128), 256, SM64>>>(n2, wc, bc, nullptr, cls, N, 64, 128);
    k_reduce<<<512, 256>>>(cls, N * 64 / 4, stats + 6);
    k_norm<0><<<G(N * 64), 256>>>(cls, out, nw3, nb3, stats + 6, 63, N * 64,
                                  1.f / (float)(N * 64));
}

// round 7
// speedup vs baseline: 4.6925x; 1.1179x over previous
#include <cuda_runtime.h>
#include <math.h>
#include <float.h>

// ---------------------------------------------------------------------------
// SynGNNLayer. R7: __launch_bounds__(256,2) on tensor GEMMs (reg-cap 128 ->
// 2 CTAs/SM; R5/R6 ran at 1 CTA/SM, occ 12%). Single k_round_all launch so
// ncu's fixed launch index lands on a GEMM.
// ---------------------------------------------------------------------------

#define NMAX 16384
#define EMAX 131072
#define TOTMAX (EMAX + NMAX)

static __device__ float g_h0 [NMAX * 128];
static __device__ float g_r1 [NMAX * 128];
static __device__ float g_n1 [NMAX * 128];
static __device__ float g_r2 [NMAX * 128];
static __device__ float g_n2 [NMAX * 128];
static __device__ float g_xl [NMAX * 512];
static __device__ float g_xr [NMAX * 512];
static __device__ float g_ea [NMAX * 32];            // self-loop attrs (tf32)
static __device__ float g_eat[EMAX * 32];            // tf32 copy of edge_attr
static __device__ float g_hid[(size_t)NMAX * 2048];
static __device__ float g_easum[NMAX * 32];
static __device__ float g_deg [NMAX];
static __device__ float g_score[TOTMAX * 4];
static __device__ unsigned g_smax[NMAX * 4];
static __device__ float g_ssum[NMAX * 4];
static __device__ float g_agg [NMAX * 128];
static __device__ float g_cls [NMAX * 64];
static __device__ float g_stats[8];
// tf32-rounded weight copies
static __device__ float g_wl [512 * 128];
static __device__ float g_wr [512 * 128];
static __device__ float g_we [512 * 32];
static __device__ float g_w1 [2048 * 128];
static __device__ float g_w2 [128 * 2048];
static __device__ float g_wc [64 * 128];

// ---- helpers --------------------------------------------------------------
__device__ __forceinline__ unsigned f_enc(float f) {
    unsigned u = __float_as_uint(f);
    return (u & 0x80000000u) ? ~u : (u | 0x80000000u);
}
__device__ __forceinline__ float f_dec(unsigned k) {
    return (k & 0x80000000u) ? __uint_as_float(k ^ 0x80000000u)
                             : __uint_as_float(~k);
}
__device__ __forceinline__ unsigned tf32r(float f) {
    unsigned u; asm("cvt.rna.tf32.f32 %0, %1;" : "=r"(u) : "f"(f)); return u;
}
__device__ __forceinline__ float tf32f(float f) {
    return __uint_as_float(tf32r(f));
}
__device__ __forceinline__ void cp16(void* smem, const void* gmem) {
    unsigned s = (unsigned)__cvta_generic_to_shared(smem);
    asm volatile("cp.async.cg.shared.global [%0], [%1], 16;\n" :: "r"(s), "l"(gmem));
}
#define CP_COMMIT() asm volatile("cp.async.commit_group;\n" ::: "memory")
#define CP_WAIT1()  asm volatile("cp.async.wait_group 1;\n" ::: "memory")

// ---------------------------------------------------------------------------
__global__ void k_init(int N) {
    int i = blockIdx.x * blockDim.x + threadIdx.x;
    if (i < N * 128) g_agg[i] = 0.f;
    if (i < N * 32)  g_easum[i] = 0.f;
    if (i < N * 4)   { g_ssum[i] = 0.f; g_smax[i] = 0x00800000u; }
    if (i < N)       g_deg[i] = 0.f;
    if (i < 8)       g_stats[i] = 0.f;
}

// one launch: tf32-round edge_attr + all six weight matrices
__global__ void k_round_all(const float* __restrict__ ea,
                            const float* __restrict__ Wl, const float* __restrict__ Wr,
                            const float* __restrict__ We, const float* __restrict__ W1,
                            const float* __restrict__ W2, const float* __restrict__ Wc,
                            int E) {
    int i = blockIdx.x * blockDim.x + threadIdx.x;
    int nea = E * 8;
    const float* src; float* dst; int off;
    if      (i < nea)                    { src = ea; dst = g_eat; off = i; }
    else if ((i -= nea)     < 16384)     { src = Wl; dst = g_wl;  off = i; }
    else if ((i -= 16384)   < 16384)     { src = Wr; dst = g_wr;  off = i; }
    else if ((i -= 16384)   < 4096)      { src = We; dst = g_we;  off = i; }
    else if ((i -= 4096)    < 65536)     { src = W1; dst = g_w1;  off = i; }
    else if ((i -= 65536)   < 65536)     { src = W2; dst = g_w2;  off = i; }
    else if ((i -= 65536)   < 2048)      { src = Wc; dst = g_wc;  off = i; }
    else return;
    float4 v = reinterpret_cast<const float4*>(src)[off];
    v.x = tf32f(v.x); v.y = tf32f(v.y); v.z = tf32f(v.z); v.w = tf32f(v.w);
    reinterpret_cast<float4*>(dst)[off] = v;
}

// sum + sumsq reduction
__global__ void k_reduce(const float* __restrict__ x, int n4, float* __restrict__ out) {
    float s = 0.f, ss = 0.f;
    for (int i = blockIdx.x * blockDim.x + threadIdx.x; i < n4; i += gridDim.x * blockDim.x) {
        float4 v = reinterpret_cast<const float4*>(x)[i];
        s  += v.x + v.y + v.z + v.w;
        ss += v.x * v.x + v.y * v.y + v.z * v.z + v.w * v.w;
    }
    #pragma unroll
    for (int o = 16; o > 0; o >>= 1) {
        s  += __shfl_xor_sync(0xffffffffu, s,  o);
        ss += __shfl_xor_sync(0xffffffffu, ss, o);
    }
    __shared__ float shs[8], shss[8];
    int w = threadIdx.x >> 5;
    if ((threadIdx.x & 31) == 0) { shs[w] = s; shss[w] = ss; }
    __syncthreads();
    if (threadIdx.x < 8) {
        s = shs[threadIdx.x]; ss = shss[threadIdx.x];
        #pragma unroll
        for (int o = 4; o > 0; o >>= 1) {
            s  += __shfl_xor_sync(0xffu, s,  o);
            ss += __shfl_xor_sync(0xffu, ss, o);
        }
        if (threadIdx.x == 0) { atomicAdd(out, s); atomicAdd(out + 1, ss); }
    }
}

// residual + reduction: r1 = h0 + agg + bias
__global__ void k_res_reduce(const float* __restrict__ gat_bias, int n4,
                             float* __restrict__ out) {
    float s = 0.f, ss = 0.f;
    const float4* b4 = reinterpret_cast<const float4*>(gat_bias);
    for (int i = blockIdx.x * blockDim.x + threadIdx.x; i < n4; i += gridDim.x * blockDim.x) {
        float4 a = reinterpret_cast<const float4*>(g_h0)[i];
        float4 g = reinterpret_cast<const float4*>(g_agg)[i];
        float4 b = b4[i & 31];
        float4 v = { a.x + g.x + b.x, a.y + g.y + b.y,
                     a.z + g.z + b.z, a.w + g.w + b.w };
        reinterpret_cast<float4*>(g_r1)[i] = v;
        s  += v.x + v.y + v.z + v.w;
        ss += v.x * v.x + v.y * v.y + v.z * v.z + v.w * v.w;
    }
    #pragma unroll
    for (int o = 16; o > 0; o >>= 1) {
        s  += __shfl_xor_sync(0xffffffffu, s,  o);
        ss += __shfl_xor_sync(0xffffffffu, ss, o);
    }
    __shared__ float shs[8], shss[8];
    int w = threadIdx.x >> 5;
    if ((threadIdx.x & 31) == 0) { shs[w] = s; shss[w] = ss; }
    __syncthreads();
    if (threadIdx.x < 8) {
        s = shs[threadIdx.x]; ss = shss[threadIdx.x];
        #pragma unroll
        for (int o = 4; o > 0; o >>= 1) {
            s  += __shfl_xor_sync(0xffu, s,  o);
            ss += __shfl_xor_sync(0xffu, ss, o);
        }
        if (threadIdx.x == 0) { atomicAdd(out, s); atomicAdd(out + 1, ss); }
    }
}

// graph_norm apply; ROUND=1 -> tf32-round the result (feeds a GEMM)
template <int ROUND>
__global__ void k_norm(const float* __restrict__ x, float* __restrict__ y,
                       const float* __restrict__ w, const float* __restrict__ b,
                       const float* __restrict__ st, int Dmask, int n, float invn) {
    int i = blockIdx.x * blockDim.x + threadIdx.x;
    if (i >= n) return;
    float mu  = st[0] * invn;
    float var = st[1] * invn - mu * mu;
    float inv = 1.f / (sqrtf(fmaxf(var, 0.f)) + 1e-5f);
    int c = i & Dmask;
    float v = (x[i] - mu) * inv * w[c] + b[c];
    y[i] = ROUND ? tf32f(v) : v;
}

// ---------------------------------------------------------------------------
// Tensor-core GEMM, 3-stage cp.async pipeline, operands pre-rounded to tf32.
// __launch_bounds__(256,2): cap regs at 128 so 2 CTAs/SM are resident.
// EPI: 1 +bias, 2 +bias,relu(+tf32 round), 3 +bias,+res
// ---------------------------------------------------------------------------
template<int BN, int WROWS, int WCOLS, int EPI>
__global__ void __launch_bounds__(256, 2)
k_tgemm(const float* __restrict__ A, const float* __restrict__ W,
        const float* __restrict__ bias, const float* __restrict__ res,
        float* __restrict__ C, int M, int Nn, int K)
{
    constexpr int BM = 128, BK = 32, LDA = BK + 4, STAGES = 3;
    constexpr int MF = BM / (WROWS * 16);
    constexpr int NF = BN / (WCOLS * 8);
    constexpr int A_CP = (BM * BK / 4) / 256;
    constexpr int B_CP = (BN * BK / 4) / 256;

    extern __shared__ float sh[];
    float* As = sh;                          // [STAGES][BM][LDA]
    float* Bs = sh + STAGES * BM * LDA;      // [STAGES][BN][LDA]

    const int tid = threadIdx.x;
    const int wid = tid >> 5, lane = tid & 31;
    const int wm = wid / WCOLS, wn = wid % WCOLS;
    const int g = lane >> 2, tg = lane & 3;
    const long m0 = (long)blockIdx.y * BM;
    const int  n0 = blockIdx.x * BN;

    auto issue = [&](int stage, int kk) {
        #pragma unroll
        for (int i = 0; i < A_CP; i++) {
            int idx = tid + i * 256;
            int r = idx >> 3, c4 = idx & 7;
            cp16(&As[stage * BM * LDA + r * LDA + c4 * 4],
                 A + (m0 + r) * K + kk + c4 * 4);
        }
        #pragma unroll
        for (int i = 0; i < B_CP; i++) {
            int idx = tid + i * 256;
            int r = idx >> 3, c4 = idx & 7;
            cp16(&Bs[stage * BN * LDA + r * LDA + c4 * 4],
                 W + (long)(n0 + r) * K + kk + c4 * 4);
        }
        CP_COMMIT();
    };

    const int NT = K / BK;
    issue(0, 0);
    if (1 < NT) issue(1, BK); else CP_COMMIT();

    float acc[MF][NF][4] = {};
    for (int kt = 0; kt < NT; kt++) {
        CP_WAIT1();
        __syncthreads();
        if (kt + STAGES - 1 < NT)
            issue((kt + STAGES - 1) % STAGES, (kt + STAGES - 1) * BK);
        else
            CP_COMMIT();
        const unsigned* Asb = reinterpret_cast<const unsigned*>(As) + (kt % STAGES) * BM * LDA;
        const unsigned* Bsb = reinterpret_cast<const unsigned*>(Bs) + (kt % STAGES) * BN * LDA;
        #pragma unroll
        for (int k8 = 0; k8 < BK / 8; k8++) {
            unsigned af[MF][4], bf[NF][2];
            #pragma unroll
            for (int i = 0; i < MF; i++) {
                int r = wm * (MF * 16) + i * 16 + g;
                const unsigned* p = Asb + r * LDA + k8 * 8;
                af[i][0] = p[tg];
                af[i][1] = p[8 * LDA + tg];
                af[i][2] = p[tg + 4];
                af[i][3] = p[8 * LDA + tg + 4];
            }
            #pragma unroll
            for (int j = 0; j < NF; j++) {
                int c = wn * (NF * 8) + j * 8 + g;
                const unsigned* p = Bsb + c * LDA + k8 * 8;
                bf[j][0] = p[tg];
                bf[j][1] = p[tg + 4];
            }
            #pragma unroll
            for (int i = 0; i < MF; i++)
                #pragma unroll
                for (int j = 0; j < NF; j++) {
                    asm volatile(
                        "mma.sync.aligned.m16n8k8.row.col.f32.tf32.tf32.f32 "
                        "{%0,%1,%2,%3}, {%4,%5,%6,%7}, {%8,%9}, {%0,%1,%2,%3};\n"
                        : "+f"(acc[i][j][0]), "+f"(acc[i][j][1]),
                          "+f"(acc[i][j][2]), "+f"(acc[i][j][3])
                        : "r"(af[i][0]), "r"(af[i][1]), "r"(af[i][2]), "r"(af[i][3]),
                          "r"(bf[j][0]), "r"(bf[j][1]));
                }
        }
    }

    #pragma unroll
    for (int i = 0; i < MF; i++) {
        long mA = m0 + wm * (MF * 16) + i * 16 + g;
        long mB = mA + 8;
        #pragma unroll
        for (int j = 0; j < NF; j++) {
            int c = n0 + wn * (NF * 8) + j * 8 + tg * 2;
            float v0 = acc[i][j][0], v1 = acc[i][j][1];
            float v2 = acc[i][j][2], v3 = acc[i][j][3];
            if (EPI >= 1) {
                float b0 = bias[c], b1 = bias[c + 1];
                v0 += b0; v1 += b1; v2 += b0; v3 += b1;
            }
            if (EPI == 2) {      // relu + tf32 round (feeds MLP2 GEMM)
                v0 = tf32f(fmaxf(v0, 0.f)); v1 = tf32f(fmaxf(v1, 0.f));
                v2 = tf32f(fmaxf(v2, 0.f)); v3 = tf32f(fmaxf(v3, 0.f));
            }
            if (EPI == 3) {
                float2 rA = reinterpret_cast<const float2*>(res + mA * Nn + c)[0];
                float2 rB = reinterpret_cast<const float2*>(res + mB * Nn + c)[0];
                v0 += rA.x; v1 += rA.y; v2 += rB.x; v3 += rB.y;
            }
            reinterpret_cast<float2*>(C + mA * Nn + c)[0] = make_float2(v0, v1);
            reinterpret_cast<float2*>(C + mB * Nn + c)[0] = make_float2(v2, v3);
        }
    }
}

// ---------------------------------------------------------------------------
// ef GEMM + fused attention score epilogue (inputs pre-rounded; no cvt).
// ---------------------------------------------------------------------------
__global__ void __launch_bounds__(256, 2)
k_gemm_score(const float* __restrict__ A, const float* __restrict__ W,
             const float* __restrict__ att, const int* __restrict__ ei,
             int ebase, int E)
{
    constexpr int BM = 128, BN = 128, BK = 32, LDA = BK + 4;
    constexpr int MF = 4, NF = 4;

    extern __shared__ float shf[];
    float* As = shf;
    float* Bs = shf + BM * LDA;
    float* srow = shf;

    const int tid = threadIdx.x;
    const int wid = tid >> 5, lane = tid & 31;
    const int wm = wid >> 2, wn = wid & 3;
    const int g = lane >> 2, tg = lane & 3;
    const long m0 = (long)blockIdx.y * BM;
    const int  n0 = blockIdx.x * BN;              // = h*128

    #pragma unroll
    for (int t = 0; t < 4; t++) {
        int idx = tid + t * 256;
        int r = idx >> 3, c4 = idx & 7;
        reinterpret_cast<float4*>(&As[r * LDA + c4 * 4])[0] =
            reinterpret_cast<const float4*>(A + (m0 + r) * BK)[c4];
        reinterpret_cast<float4*>(&Bs[r * LDA + c4 * 4])[0] =
            reinterpret_cast<const float4*>(W + (long)(n0 + r) * BK)[c4];
    }
    __syncthreads();

    float acc[MF][NF][4] = {};
    const unsigned* Asu = reinterpret_cast<const unsigned*>(As);
    const unsigned* Bsu = reinterpret_cast<const unsigned*>(Bs);
    #pragma unroll
    for (int k8 = 0; k8 < 4; k8++) {
        unsigned af[MF][4], bf[NF][2];
        #pragma unroll
        for (int i = 0; i < MF; i++) {
            int r = wm * 64 + i * 16 + g;
            const unsigned* p = Asu + r * LDA + k8 * 8;
            af[i][0] = p[tg];
            af[i][1] = p[8 * LDA + tg];
            af[i][2] = p[tg + 4];
            af[i][3] = p[8 * LDA + tg + 4];
        }
        #pragma unroll
        for (int j = 0; j < NF; j++) {
            int c = wn * 32 + j * 8 + g;
            const unsigned* p = Bsu + c * LDA + k8 * 8;
            bf[j][0] = p[tg];
            bf[j][1] = p[tg + 4];
        }
        #pragma unroll
        for (int i = 0; i < MF; i++)
            #pragma unroll
            for (int j = 0; j < NF; j++) {
                asm volatile(
                    "mma.sync.aligned.m16n8k8.row.col.f32.tf32.tf32.f32 "
                    "{%0,%1,%2,%3}, {%4,%5,%6,%7}, {%8,%9}, {%0,%1,%2,%3};\n"
                    : "+f"(acc[i][j][0]), "+f"(acc[i][j][1]),
                      "+f"(acc[i][j][2]), "+f"(acc[i][j][3])
                    : "r"(af[i][0]), "r"(af[i][1]), "r"(af[i][2]), "r"(af[i][3]),
                      "r"(bf[j][0]), "r"(bf[j][1]));
            }
    }

    // score epilogue: leaky(acc + xl[src] + xr[dst]) dot att
    float part[MF][2] = {};
    #pragma unroll
    for (int i = 0; i < MF; i++) {
        int rA = wm * 64 + i * 16 + g;
        int rB = rA + 8;
        int geA = ebase + (int)m0 + rA;
        int geB = ebase + (int)m0 + rB;
        int sA = (geA < E) ? ei[geA] : (geA - E);
        int dA = (geA < E) ? ei[E + geA] : (geA - E);
        int sB = (geB < E) ? ei[geB] : (geB - E);
        int dB = (geB < E) ? ei[E + geB] : (geB - E);
        const float* xlA = g_xl + (long)sA * 512 + n0;
        const float* xrA = g_xr + (long)dA * 512 + n0;
        const float* xlB = g_xl + (long)sB * 512 + n0;
        const float* xrB = g_xr + (long)dB * 512 + n0;
        #pragma unroll
        for (int j = 0; j < NF; j++) {
            int c = wn * 32 + j * 8 + tg * 2;
            float2 a0 = reinterpret_cast<const float2*>(att + n0 + c)[0];
            float2 lA = reinterpret_cast<const float2*>(xlA + c)[0];
            float2 rAv= reinterpret_cast<const float2*>(xrA + c)[0];
            float2 lB = reinterpret_cast<const float2*>(xlB + c)[0];
            float2 rBv= reinterpret_cast<const float2*>(xrB + c)[0];
            float z0 = acc[i][j][0] + lA.x + rAv.x; z0 = z0 > 0.f ? z0 : 0.2f * z0;
            float z1 = acc[i][j][1] + lA.y + rAv.y; z1 = z1 > 0.f ? z1 : 0.2f * z1;
            float z2 = acc[i][j][2] + lB.x + rBv.x; z2 = z2 > 0.f ? z2 : 0.2f * z2;
            float z3 = acc[i][j][3] + lB.y + rBv.y; z3 = z3 > 0.f ? z3 : 0.2f * z3;
            part[i][0] += z0 * a0.x + z1 * a0.y;
            part[i][1] += z2 * a0.x + z3 * a0.y;
        }
    }
    #pragma unroll
    for (int i = 0; i < MF; i++) {
        #pragma unroll
        for (int o = 1; o <= 2; o <<= 1) {
            part[i][0] += __shfl_xor_sync(0xffffffffu, part[i][0], o);
            part[i][1] += __shfl_xor_sync(0xffffffffu, part[i][1], o);
        }
    }
    __syncthreads();
    if (tg == 0) {
        #pragma unroll
        for (int i = 0; i < MF; i++) {
            int rA = wm * 64 + i * 16 + g;
            srow[wn * 128 + rA]     = part[i][0];
            srow[wn * 128 + rA + 8] = part[i][1];
        }
    }
    __syncthreads();
    if (tid < 128) {
        float s = srow[tid] + srow[128 + tid] + srow[256 + tid] + srow[384 + tid];
        int ge = ebase + (int)m0 + tid;
        int d  = (ge < E) ? ei[E + ge] : (ge - E);
        int h  = blockIdx.x;
        g_score[(long)ge * 4 + h] = s;
        atomicMax(&g_smax[d * 4 + h], f_enc(s));
    }
}

// ---- edge-side kernels ----------------------------------------------------
__global__ void k_degsum(const float* __restrict__ edge_attr,
                         const int* __restrict__ ei, int E) {
    int i = blockIdx.x * blockDim.x + threadIdx.x;
    if (i >= E * 8) return;
    int e = i >> 3, c4 = i & 7;
    int dst = ei[E + e];
    float4 v = reinterpret_cast<const float4*>(edge_attr + (long)e * 32)[c4];
    atomicAdd(reinterpret_cast<float4*>(&g_easum[dst * 32 + c4 * 4]), v);
    if (c4 == 0) atomicAdd(&g_deg[dst], 1.f);
}

// self-loop edge attrs = mean of incoming (tf32-rounded: feeds GEMM)
__global__ void k_eamean(int N) {
    int i = blockIdx.x * blockDim.x + threadIdx.x;
    if (i >= N * 32) return;
    int nid = i >> 5;
    float d = fmaxf(g_deg[nid], 1.f);
    g_ea[i] = tf32f(g_easum[i] / d);
}

__global__ void k_exp(const int* __restrict__ ei, int E, int N) {
    int i = blockIdx.x * blockDim.x + threadIdx.x;
    int tot4 = (E + N) * 4;
    if (i >= tot4) return;
    int e = i >> 2, h = i & 3;
    int d = (e < E) ? ei[E + e] : (e - E);
    float m  = f_dec(g_smax[d * 4 + h]);
    float ex = expf(g_score[i] - m);
    g_score[i] = ex;
    atomicAdd(&g_ssum[d * 4 + h], ex);
}

__global__ void k_agg(const int* __restrict__ ei, float* __restrict__ out_alpha,
                      int E, int N, int write_out) {
    int tot = E + N;
    int e = blockIdx.x * 8 + (threadIdx.x >> 5);
    if (e >= tot) return;
    int l = threadIdx.x & 31;
    int s = (e < E) ? ei[e]     : (e - E);
    int d = (e < E) ? ei[E + e] : (e - E);
    float a0 = __fdividef(g_score[(long)e * 4 + 0], g_ssum[d * 4 + 0]);
    float a1 = __fdividef(g_score[(long)e * 4 + 1], g_ssum[d * 4 + 1]);
    float a2 = __fdividef(g_score[(long)e * 4 + 2], g_ssum[d * 4 + 2]);
    float a3 = __fdividef(g_score[(long)e * 4 + 3], g_ssum[d * 4 + 3]);
    if (write_out && l < 4) {
        float a = (l == 0) ? a0 : (l == 1) ? a1 : (l == 2) ? a2 : a3;
        out_alpha[(long)e * 4 + l] = a;
    }
    a0 *= 0.25f; a1 *= 0.25f; a2 *= 0.25f; a3 *= 0.25f;
    const float4* xl4 = reinterpret_cast<const float4*>(g_xl + (long)s * 512);
    float4 v0 = xl4[ 0 + l], v1 = xl4[32 + l], v2 = xl4[64 + l], v3 = xl4[96 + l];
    float4 r;
    r.x = a0 * v0.x + a1 * v1.x + a2 * v2.x + a3 * v3.x;
    r.y = a0 * v0.y + a1 * v1.y + a2 * v2.y + a3 * v3.y;
    r.z = a0 * v0.z + a1 * v1.z + a2 * v2.z + a3 * v3.z;
    r.w = a0 * v0.w + a1 * v1.w + a2 * v2.w + a3 * v3.w;
    atomicAdd(reinterpret_cast<float4*>(g_agg + d * 128 + 4 * l), r);
}

// ---------------------------------------------------------------------------
static inline int G(int n) { return (n + 255) / 256; }

extern "C" void kernel_launch(void* const* d_in, const int* in_sizes, int n_in,
                              void* d_out, int out_size) {
    const float* x         = (const float*)d_in[0];
    const int*   ei        = (const int*)  d_in[1];
    const float* edge_attr = (const float*)d_in[2];
    const float* Wl  = (const float*)d_in[4];
    const float* bl  = (const float*)d_in[5];
    const float* Wr  = (const float*)d_in[6];
    const float* br  = (const float*)d_in[7];
    const float* We  = (const float*)d_in[8];
    const float* att = (const float*)d_in[9];
    const float* gbn = (const float*)d_in[10];
    const float* W1  = (const float*)d_in[11];
    const float* b1  = (const float*)d_in[12];
    const float* W2  = (const float*)d_in[13];
    const float* b2  = (const float*)d_in[14];
    const float* Wc  = (const float*)d_in[15];
    const float* bc  = (const float*)d_in[16];
    const float* nw0 = (const float*)d_in[17];
    const float* nb0 = (const float*)d_in[18];
    const float* nw1 = (const float*)d_in[19];
    const float* nb1 = (const float*)d_in[20];
    const float* nw2 = (const float*)d_in[21];
    const float* nb2 = (const float*)d_in[22];
    const float* nw3 = (const float*)d_in[23];
    const float* nb3 = (const float*)d_in[24];

    int N = in_sizes[0] / 128;
    int E = in_sizes[1] / 2;
    int TOT = E + N;
    float* out = (float*)d_out;
    int write_alpha = (out_size >= N * 64 + TOT * 4) ? 1 : 0;
    float* out_alpha = out + (size_t)N * 64;

    float *h0, *r1, *n1, *r2, *n2, *ea, *eat, *hid, *cls, *stats;
    float *wl, *wr, *we, *w1, *w2, *wc, *xl, *xr;
    cudaGetSymbolAddress((void**)&h0,    g_h0);
    cudaGetSymbolAddress((void**)&r1,    g_r1);
    cudaGetSymbolAddress((void**)&n1,    g_n1);
    cudaGetSymbolAddress((void**)&r2,    g_r2);
    cudaGetSymbolAddress((void**)&n2,    g_n2);
    cudaGetSymbolAddress((void**)&ea,    g_ea);
    cudaGetSymbolAddress((void**)&eat,   g_eat);
    cudaGetSymbolAddress((void**)&hid,   g_hid);
    cudaGetSymbolAddress((void**)&cls,   g_cls);
    cudaGetSymbolAddress((void**)&stats, g_stats);
    cudaGetSymbolAddress((void**)&wl,    g_wl);
    cudaGetSymbolAddress((void**)&wr,    g_wr);
    cudaGetSymbolAddress((void**)&we,    g_we);
    cudaGetSymbolAddress((void**)&w1,    g_w1);
    cudaGetSymbolAddress((void**)&w2,    g_w2);
    cudaGetSymbolAddress((void**)&wc,    g_wc);
    cudaGetSymbolAddress((void**)&xl,    g_xl);
    cudaGetSymbolAddress((void**)&xr,    g_xr);

    const int SM128 = 3 * (128 + 128) * 36 * 4;  // 110592 B
    const int SM64  = 3 * (128 +  64) * 36 * 4;  // 82944 B
    const int SMSC  = (128 * 36 + 128 * 36) * 4; // 36864 B
    cudaFuncSetAttribute(k_tgemm<128,2,4,1>, cudaFuncAttributeMaxDynamicSharedMemorySize, SM128);
    cudaFuncSetAttribute(k_tgemm<128,2,4,2>, cudaFuncAttributeMaxDynamicSharedMemorySize, SM128);
    cudaFuncSetAttribute(k_tgemm<128,2,4,3>, cudaFuncAttributeMaxDynamicSharedMemorySize, SM128);
    cudaFuncSetAttribute(k_tgemm<64,4,2,1>,  cudaFuncAttributeMaxDynamicSharedMemorySize, SM64);
    cudaFuncSetAttribute(k_gemm_score,       cudaFuncAttributeMaxDynamicSharedMemorySize, SMSC);

    // launches 0-3: init, rounds, norm-0 stats+apply
    k_init<<<G(N * 128), 256>>>(N);
    int nround = E * 8 + 16384 + 16384 + 4096 + 65536 + 65536 + 2048;
    k_round_all<<<G(nround), 256>>>(edge_attr, Wl, Wr, We, W1, W2, Wc, E);
    k_reduce<<<1024, 256>>>(x, N * 128 / 4, stats + 0);
    k_norm<1><<<G(N * 128), 256>>>(x, h0, nw0, nb0, stats + 0, 127, N * 128,
                                   1.f / (float)(N * 128));

    // launches 4-5: GATv2 linear transforms (launch 5 = profiled kernel)
    k_tgemm<128,2,4,1><<<dim3(4, N/128), 256, SM128>>>(h0, wl, bl, nullptr, xl, N, 512, 128);
    k_tgemm<128,2,4,1><<<dim3(4, N/128), 256, SM128>>>(h0, wr, br, nullptr, xr, N, 512, 128);

    // --- self-loop edge attrs ---
    k_degsum<<<G(E * 8), 256>>>(edge_attr, ei, E);
    k_eamean<<<G(N * 32), 256>>>(N);

    // --- fused ef GEMM + attention scores ---
    k_gemm_score<<<dim3(4, E/128), 256, SMSC>>>(eat, we, att, ei, 0, E);
    k_gemm_score<<<dim3(4, N/128), 256, SMSC>>>(ea, we, att, ei, E, E);

    // --- segment softmax + weighted aggregation ---
    k_exp<<<G(TOT * 4), 256>>>(ei, E, N);
    k_agg<<<(TOT + 7) / 8, 256>>>(ei, out_alpha, E, N, write_alpha);

    // --- residual + graph_norm 1 (rounded: feeds MLP) ---
    k_res_reduce<<<1024, 256>>>(gbn, N * 128 / 4, stats + 2);
    k_norm<1><<<G(N * 128), 256>>>(r1, n1, nw1, nb1, stats + 2, 127, N * 128,
                                   1.f / (float)(N * 128));

    // --- MLP ---
    k_tgemm<128,2,4,2><<<dim3(16, N/128), 256, SM128>>>(n1, w1, b1, nullptr, hid, N, 2048, 128);
    k_tgemm<128,2,4,3><<<dim3(1, N/128), 256, SM128>>>(hid, w2, b2, n1, r2, N, 128, 2048);

    // --- graph_norm 2 (rounded: feeds classifier) ---
    k_reduce<<<1024, 256>>>(r2, N * 128 / 4, stats + 4);
    k_norm<1><<<G(N * 128), 256>>>(r2, n2, nw2, nb2, stats + 4, 127, N * 128,
                                   1.f / (float)(N * 128));

    // --- classifier + graph_norm 3 (final output: full fp32) ---
    k_tgemm<64,4,2,1><<<dim3(1, N/128), 256, SM64>>>(n2, wc, bc, nullptr, cls, N, 64, 128);
    k_reduce<<<512, 256>>>(cls, N * 64 / 4, stats + 6);
    k_norm<0><<<G(N * 64), 256>>>(cls, out, nw3, nb3, stats + 6, 63, N * 64,
                                  1.f / (float)(N * 64));
}

// round 8
// speedup vs baseline: 4.6977x; 1.0011x over previous
#include <cuda_runtime.h>
#include <math.h>
#include <float.h>

// ---------------------------------------------------------------------------
// SynGNNLayer. R7: __launch_bounds__(256,2) on tensor GEMMs (reg-cap 128 ->
// 2 CTAs/SM; R5/R6 ran at 1 CTA/SM, occ 12%). Single k_round_all launch so
// ncu's fixed launch index lands on a GEMM.
// ---------------------------------------------------------------------------

#define NMAX 16384
#define EMAX 131072
#define TOTMAX (EMAX + NMAX)

static __device__ float g_h0 [NMAX * 128];
static __device__ float g_r1 [NMAX * 128];
static __device__ float g_n1 [NMAX * 128];
static __device__ float g_r2 [NMAX * 128];
static __device__ float g_n2 [NMAX * 128];
static __device__ float g_xl [NMAX * 512];
static __device__ float g_xr [NMAX * 512];
static __device__ float g_ea [NMAX * 32];            // self-loop attrs (tf32)
static __device__ float g_eat[EMAX * 32];            // tf32 copy of edge_attr
static __device__ float g_hid[(size_t)NMAX * 2048];
static __device__ float g_easum[NMAX * 32];
static __device__ float g_deg [NMAX];
static __device__ float g_score[TOTMAX * 4];
static __device__ unsigned g_smax[NMAX * 4];
static __device__ float g_ssum[NMAX * 4];
static __device__ float g_agg [NMAX * 128];
static __device__ float g_cls [NMAX * 64];
static __device__ float g_stats[8];
// tf32-rounded weight copies
static __device__ float g_wl [512 * 128];
static __device__ float g_wr [512 * 128];
static __device__ float g_we [512 * 32];
static __device__ float g_w1 [2048 * 128];
static __device__ float g_w2 [128 * 2048];
static __device__ float g_wc [64 * 128];

// ---- helpers --------------------------------------------------------------
__device__ __forceinline__ unsigned f_enc(float f) {
    unsigned u = __float_as_uint(f);
    return (u & 0x80000000u) ? ~u : (u | 0x80000000u);
}
__device__ __forceinline__ float f_dec(unsigned k) {
    return (k & 0x80000000u) ? __uint_as_float(k ^ 0x80000000u)
                             : __uint_as_float(~k);
}
__device__ __forceinline__ unsigned tf32r(float f) {
    unsigned u; asm("cvt.rna.tf32.f32 %0, %1;" : "=r"(u) : "f"(f)); return u;
}
__device__ __forceinline__ float tf32f(float f) {
    return __uint_as_float(tf32r(f));
}
__device__ __forceinline__ void cp16(void* smem, const void* gmem) {
    unsigned s = (unsigned)__cvta_generic_to_shared(smem);
    asm volatile("cp.async.cg.shared.global [%0], [%1], 16;\n" :: "r"(s), "l"(gmem));
}
#define CP_COMMIT() asm volatile("cp.async.commit_group;\n" ::: "memory")
#define CP_WAIT1()  asm volatile("cp.async.wait_group 1;\n" ::: "memory")

// ---------------------------------------------------------------------------
__global__ void k_init(int N) {
    int i = blockIdx.x * blockDim.x + threadIdx.x;
    if (i < N * 128) g_agg[i] = 0.f;
    if (i < N * 32)  g_easum[i] = 0.f;
    if (i < N * 4)   { g_ssum[i] = 0.f; g_smax[i] = 0x00800000u; }
    if (i < N)       g_deg[i] = 0.f;
    if (i < 8)       g_stats[i] = 0.f;
}

// one launch: tf32-round edge_attr + all six weight matrices
__global__ void k_round_all(const float* __restrict__ ea,
                            const float* __restrict__ Wl, const float* __restrict__ Wr,
                            const float* __restrict__ We, const float* __restrict__ W1,
                            const float* __restrict__ W2, const float* __restrict__ Wc,
                            int E) {
    int i = blockIdx.x * blockDim.x + threadIdx.x;
    int nea = E * 8;
    const float* src; float* dst; int off;
    if      (i < nea)                    { src = ea; dst = g_eat; off = i; }
    else if ((i -= nea)     < 16384)     { src = Wl; dst = g_wl;  off = i; }
    else if ((i -= 16384)   < 16384)     { src = Wr; dst = g_wr;  off = i; }
    else if ((i -= 16384)   < 4096)      { src = We; dst = g_we;  off = i; }
    else if ((i -= 4096)    < 65536)     { src = W1; dst = g_w1;  off = i; }
    else if ((i -= 65536)   < 65536)     { src = W2; dst = g_w2;  off = i; }
    else if ((i -= 65536)   < 2048)      { src = Wc; dst = g_wc;  off = i; }
    else return;
    float4 v = reinterpret_cast<const float4*>(src)[off];
    v.x = tf32f(v.x); v.y = tf32f(v.y); v.z = tf32f(v.z); v.w = tf32f(v.w);
    reinterpret_cast<float4*>(dst)[off] = v;
}

// sum + sumsq reduction
__global__ void k_reduce(const float* __restrict__ x, int n4, float* __restrict__ out) {
    float s = 0.f, ss = 0.f;
    for (int i = blockIdx.x * blockDim.x + threadIdx.x; i < n4; i += gridDim.x * blockDim.x) {
        float4 v = reinterpret_cast<const float4*>(x)[i];
        s  += v.x + v.y + v.z + v.w;
        ss += v.x * v.x + v.y * v.y + v.z * v.z + v.w * v.w;
    }
    #pragma unroll
    for (int o = 16; o > 0; o >>= 1) {
        s  += __shfl_xor_sync(0xffffffffu, s,  o);
        ss += __shfl_xor_sync(0xffffffffu, ss, o);
    }
    __shared__ float shs[8], shss[8];
    int w = threadIdx.x >> 5;
    if ((threadIdx.x & 31) == 0) { shs[w] = s; shss[w] = ss; }
    __syncthreads();
    if (threadIdx.x < 8) {
        s = shs[threadIdx.x]; ss = shss[threadIdx.x];
        #pragma unroll
        for (int o = 4; o > 0; o >>= 1) {
            s  += __shfl_xor_sync(0xffu, s,  o);
            ss += __shfl_xor_sync(0xffu, ss, o);
        }
        if (threadIdx.x == 0) { atomicAdd(out, s); atomicAdd(out + 1, ss); }
    }
}

// residual + reduction: r1 = h0 + agg + bias
__global__ void k_res_reduce(const float* __restrict__ gat_bias, int n4,
                             float* __restrict__ out) {
    float s = 0.f, ss = 0.f;
    const float4* b4 = reinterpret_cast<const float4*>(gat_bias);
    for (int i = blockIdx.x * blockDim.x + threadIdx.x; i < n4; i += gridDim.x * blockDim.x) {
        float4 a = reinterpret_cast<const float4*>(g_h0)[i];
        float4 g = reinterpret_cast<const float4*>(g_agg)[i];
        float4 b = b4[i & 31];
        float4 v = { a.x + g.x + b.x, a.y + g.y + b.y,
                     a.z + g.z + b.z, a.w + g.w + b.w };
        reinterpret_cast<float4*>(g_r1)[i] = v;
        s  += v.x + v.y + v.z + v.w;
        ss += v.x * v.x + v.y * v.y + v.z * v.z + v.w * v.w;
    }
    #pragma unroll
    for (int o = 16; o > 0; o >>= 1) {
        s  += __shfl_xor_sync(0xffffffffu, s,  o);
        ss += __shfl_xor_sync(0xffffffffu, ss, o);
    }
    __shared__ float shs[8], shss[8];
    int w = threadIdx.x >> 5;
    if ((threadIdx.x & 31) == 0) { shs[w] = s; shss[w] = ss; }
    __syncthreads();
    if (threadIdx.x < 8) {
        s = shs[threadIdx.x]; ss = shss[threadIdx.x];
        #pragma unroll
        for (int o = 4; o > 0; o >>= 1) {
            s  += __shfl_xor_sync(0xffu, s,  o);
            ss += __shfl_xor_sync(0xffu, ss, o);
        }
        if (threadIdx.x == 0) { atomicAdd(out, s); atomicAdd(out + 1, ss); }
    }
}

// graph_norm apply; ROUND=1 -> tf32-round the result (feeds a GEMM)
template <int ROUND>
__global__ void k_norm(const float* __restrict__ x, float* __restrict__ y,
                       const float* __restrict__ w, const float* __restrict__ b,
                       const float* __restrict__ st, int Dmask, int n, float invn) {
    int i = blockIdx.x * blockDim.x + threadIdx.x;
    if (i >= n) return;
    float mu  = st[0] * invn;
    float var = st[1] * invn - mu * mu;
    float inv = 1.f / (sqrtf(fmaxf(var, 0.f)) + 1e-5f);
    int c = i & Dmask;
    float v = (x[i] - mu) * inv * w[c] + b[c];
    y[i] = ROUND ? tf32f(v) : v;
}

// ---------------------------------------------------------------------------
// Tensor-core GEMM, 3-stage cp.async pipeline, operands pre-rounded to tf32.
// __launch_bounds__(256,2): cap regs at 128 so 2 CTAs/SM are resident.
// EPI: 1 +bias, 2 +bias,relu(+tf32 round), 3 +bias,+res
// ---------------------------------------------------------------------------
template<int BN, int WROWS, int WCOLS, int EPI>
__global__ void __launch_bounds__(256, 2)
k_tgemm(const float* __restrict__ A, const float* __restrict__ W,
        const float* __restrict__ bias, const float* __restrict__ res,
        float* __restrict__ C, int M, int Nn, int K)
{
    constexpr int BM = 128, BK = 32, LDA = BK + 4, STAGES = 3;
    constexpr int MF = BM / (WROWS * 16);
    constexpr int NF = BN / (WCOLS * 8);
    constexpr int A_CP = (BM * BK / 4) / 256;
    constexpr int B_CP = (BN * BK / 4) / 256;

    extern __shared__ float sh[];
    float* As = sh;                          // [STAGES][BM][LDA]
    float* Bs = sh + STAGES * BM * LDA;      // [STAGES][BN][LDA]

    const int tid = threadIdx.x;
    const int wid = tid >> 5, lane = tid & 31;
    const int wm = wid / WCOLS, wn = wid % WCOLS;
    const int g = lane >> 2, tg = lane & 3;
    const long m0 = (long)blockIdx.y * BM;
    const int  n0 = blockIdx.x * BN;

    auto issue = [&](int stage, int kk) {
        #pragma unroll
        for (int i = 0; i < A_CP; i++) {
            int idx = tid + i * 256;
            int r = idx >> 3, c4 = idx & 7;
            cp16(&As[stage * BM * LDA + r * LDA + c4 * 4],
                 A + (m0 + r) * K + kk + c4 * 4);
        }
        #pragma unroll
        for (int i = 0; i < B_CP; i++) {
            int idx = tid + i * 256;
            int r = idx >> 3, c4 = idx & 7;
            cp16(&Bs[stage * BN * LDA + r * LDA + c4 * 4],
                 W + (long)(n0 + r) * K + kk + c4 * 4);
        }
        CP_COMMIT();
    };

    const int NT = K / BK;
    issue(0, 0);
    if (1 < NT) issue(1, BK); else CP_COMMIT();

    float acc[MF][NF][4] = {};
    for (int kt = 0; kt < NT; kt++) {
        CP_WAIT1();
        __syncthreads();
        if (kt + STAGES - 1 < NT)
            issue((kt + STAGES - 1) % STAGES, (kt + STAGES - 1) * BK);
        else
            CP_COMMIT();
        const unsigned* Asb = reinterpret_cast<const unsigned*>(As) + (kt % STAGES) * BM * LDA;
        const unsigned* Bsb = reinterpret_cast<const unsigned*>(Bs) + (kt % STAGES) * BN * LDA;
        #pragma unroll
        for (int k8 = 0; k8 < BK / 8; k8++) {
            unsigned af[MF][4], bf[NF][2];
            #pragma unroll
            for (int i = 0; i < MF; i++) {
                int r = wm * (MF * 16) + i * 16 + g;
                const unsigned* p = Asb + r * LDA + k8 * 8;
                af[i][0] = p[tg];
                af[i][1] = p[8 * LDA + tg];
                af[i][2] = p[tg + 4];
                af[i][3] = p[8 * LDA + tg + 4];
            }
            #pragma unroll
            for (int j = 0; j < NF; j++) {
                int c = wn * (NF * 8) + j * 8 + g;
                const unsigned* p = Bsb + c * LDA + k8 * 8;
                bf[j][0] = p[tg];
                bf[j][1] = p[tg + 4];
            }
            #pragma unroll
            for (int i = 0; i < MF; i++)
                #pragma unroll
                for (int j = 0; j < NF; j++) {
                    asm volatile(
                        "mma.sync.aligned.m16n8k8.row.col.f32.tf32.tf32.f32 "
                        "{%0,%1,%2,%3}, {%4,%5,%6,%7}, {%8,%9}, {%0,%1,%2,%3};\n"
                        : "+f"(acc[i][j][0]), "+f"(acc[i][j][1]),
                          "+f"(acc[i][j][2]), "+f"(acc[i][j][3])
                        : "r"(af[i][0]), "r"(af[i][1]), "r"(af[i][2]), "r"(af[i][3]),
                          "r"(bf[j][0]), "r"(bf[j][1]));
                }
        }
    }

    #pragma unroll
    for (int i = 0; i < MF; i++) {
        long mA = m0 + wm * (MF * 16) + i * 16 + g;
        long mB = mA + 8;
        #pragma unroll
        for (int j = 0; j < NF; j++) {
            int c = n0 + wn * (NF * 8) + j * 8 + tg * 2;
            float v0 = acc[i][j][0], v1 = acc[i][j][1];
            float v2 = acc[i][j][2], v3 = acc[i][j][3];
            if (EPI >= 1) {
                float b0 = bias[c], b1 = bias[c + 1];
                v0 += b0; v1 += b1; v2 += b0; v3 += b1;
            }
            if (EPI == 2) {      // relu + tf32 round (feeds MLP2 GEMM)
                v0 = tf32f(fmaxf(v0, 0.f)); v1 = tf32f(fmaxf(v1, 0.f));
                v2 = tf32f(fmaxf(v2, 0.f)); v3 = tf32f(fmaxf(v3, 0.f));
            }
            if (EPI == 3) {
                float2 rA = reinterpret_cast<const float2*>(res + mA * Nn + c)[0];
                float2 rB = reinterpret_cast<const float2*>(res + mB * Nn + c)[0];
                v0 += rA.x; v1 += rA.y; v2 += rB.x; v3 += rB.y;
            }
            reinterpret_cast<float2*>(C + mA * Nn + c)[0] = make_float2(v0, v1);
            reinterpret_cast<float2*>(C + mB * Nn + c)[0] = make_float2(v2, v3);
        }
    }
}

// ---------------------------------------------------------------------------
// ef GEMM + fused attention score epilogue (inputs pre-rounded; no cvt).
// ---------------------------------------------------------------------------
__global__ void __launch_bounds__(256, 2)
k_gemm_score(const float* __restrict__ A, const float* __restrict__ W,
             const float* __restrict__ att, const int* __restrict__ ei,
             int ebase, int E)
{
    constexpr int BM = 128, BN = 128, BK = 32, LDA = BK + 4;
    constexpr int MF = 4, NF = 4;

    extern __shared__ float shf[];
    float* As = shf;
    float* Bs = shf + BM * LDA;
    float* srow = shf;

    const int tid = threadIdx.x;
    const int wid = tid >> 5, lane = tid & 31;
    const int wm = wid >> 2, wn = wid & 3;
    const int g = lane >> 2, tg = lane & 3;
    const long m0 = (long)blockIdx.y * BM;
    const int  n0 = blockIdx.x * BN;              // = h*128

    #pragma unroll
    for (int t = 0; t < 4; t++) {
        int idx = tid + t * 256;
        int r = idx >> 3, c4 = idx & 7;
        reinterpret_cast<float4*>(&As[r * LDA + c4 * 4])[0] =
            reinterpret_cast<const float4*>(A + (m0 + r) * BK)[c4];
        reinterpret_cast<float4*>(&Bs[r * LDA + c4 * 4])[0] =
            reinterpret_cast<const float4*>(W + (long)(n0 + r) * BK)[c4];
    }
    __syncthreads();

    float acc[MF][NF][4] = {};
    const unsigned* Asu = reinterpret_cast<const unsigned*>(As);
    const unsigned* Bsu = reinterpret_cast<const unsigned*>(Bs);
    #pragma unroll
    for (int k8 = 0; k8 < 4; k8++) {
        unsigned af[MF][4], bf[NF][2];
        #pragma unroll
        for (int i = 0; i < MF; i++) {
            int r = wm * 64 + i * 16 + g;
            const unsigned* p = Asu + r * LDA + k8 * 8;
            af[i][0] = p[tg];
            af[i][1] = p[8 * LDA + tg];
            af[i][2] = p[tg + 4];
            af[i][3] = p[8 * LDA + tg + 4];
        }
        #pragma unroll
        for (int j = 0; j < NF; j++) {
            int c = wn * 32 + j * 8 + g;
            const unsigned* p = Bsu + c * LDA + k8 * 8;
            bf[j][0] = p[tg];
            bf[j][1] = p[tg + 4];
        }
        #pragma unroll
        for (int i = 0; i < MF; i++)
            #pragma unroll
            for (int j = 0; j < NF; j++) {
                asm volatile(
                    "mma.sync.aligned.m16n8k8.row.col.f32.tf32.tf32.f32 "
                    "{%0,%1,%2,%3}, {%4,%5,%6,%7}, {%8,%9}, {%0,%1,%2,%3};\n"
                    : "+f"(acc[i][j][0]), "+f"(acc[i][j][1]),
                      "+f"(acc[i][j][2]), "+f"(acc[i][j][3])
                    : "r"(af[i][0]), "r"(af[i][1]), "r"(af[i][2]), "r"(af[i][3]),
                      "r"(bf[j][0]), "r"(bf[j][1]));
            }
    }

    // score epilogue: leaky(acc + xl[src] + xr[dst]) dot att
    float part[MF][2] = {};
    #pragma unroll
    for (int i = 0; i < MF; i++) {
        int rA = wm * 64 + i * 16 + g;
        int rB = rA + 8;
        int geA = ebase + (int)m0 + rA;
        int geB = ebase + (int)m0 + rB;
        int sA = (geA < E) ? ei[geA] : (geA - E);
        int dA = (geA < E) ? ei[E + geA] : (geA - E);
        int sB = (geB < E) ? ei[geB] : (geB - E);
        int dB = (geB < E) ? ei[E + geB] : (geB - E);
        const float* xlA = g_xl + (long)sA * 512 + n0;
        const float* xrA = g_xr + (long)dA * 512 + n0;
        const float* xlB = g_xl + (long)sB * 512 + n0;
        const float* xrB = g_xr + (long)dB * 512 + n0;
        #pragma unroll
        for (int j = 0; j < NF; j++) {
            int c = wn * 32 + j * 8 + tg * 2;
            float2 a0 = reinterpret_cast<const float2*>(att + n0 + c)[0];
            float2 lA = reinterpret_cast<const float2*>(xlA + c)[0];
            float2 rAv= reinterpret_cast<const float2*>(xrA + c)[0];
            float2 lB = reinterpret_cast<const float2*>(xlB + c)[0];
            float2 rBv= reinterpret_cast<const float2*>(xrB + c)[0];
            float z0 = acc[i][j][0] + lA.x + rAv.x; z0 = z0 > 0.f ? z0 : 0.2f * z0;
            float z1 = acc[i][j][1] + lA.y + rAv.y; z1 = z1 > 0.f ? z1 : 0.2f * z1;
            float z2 = acc[i][j][2] + lB.x + rBv.x; z2 = z2 > 0.f ? z2 : 0.2f * z2;
            float z3 = acc[i][j][3] + lB.y + rBv.y; z3 = z3 > 0.f ? z3 : 0.2f * z3;
            part[i][0] += z0 * a0.x + z1 * a0.y;
            part[i][1] += z2 * a0.x + z3 * a0.y;
        }
    }
    #pragma unroll
    for (int i = 0; i < MF; i++) {
        #pragma unroll
        for (int o = 1; o <= 2; o <<= 1) {
            part[i][0] += __shfl_xor_sync(0xffffffffu, part[i][0], o);
            part[i][1] += __shfl_xor_sync(0xffffffffu, part[i][1], o);
        }
    }
    __syncthreads();
    if (tg == 0) {
        #pragma unroll
        for (int i = 0; i < MF; i++) {
            int rA = wm * 64 + i * 16 + g;
            srow[wn * 128 + rA]     = part[i][0];
            srow[wn * 128 + rA + 8] = part[i][1];
        }
    }
    __syncthreads();
    if (tid < 128) {
        float s = srow[tid] + srow[128 + tid] + srow[256 + tid] + srow[384 + tid];
        int ge = ebase + (int)m0 + tid;
        int d  = (ge < E) ? ei[E + ge] : (ge - E);
        int h  = blockIdx.x;
        g_score[(long)ge * 4 + h] = s;
        atomicMax(&g_smax[d * 4 + h], f_enc(s));
    }
}

// ---- edge-side kernels ----------------------------------------------------
__global__ void k_degsum(const float* __restrict__ edge_attr,
                         const int* __restrict__ ei, int E) {
    int i = blockIdx.x * blockDim.x + threadIdx.x;
    if (i >= E * 8) return;
    int e = i >> 3, c4 = i & 7;
    int dst = ei[E + e];
    float4 v = reinterpret_cast<const float4*>(edge_attr + (long)e * 32)[c4];
    atomicAdd(reinterpret_cast<float4*>(&g_easum[dst * 32 + c4 * 4]), v);
    if (c4 == 0) atomicAdd(&g_deg[dst], 1.f);
}

// self-loop edge attrs = mean of incoming (tf32-rounded: feeds GEMM)
__global__ void k_eamean(int N) {
    int i = blockIdx.x * blockDim.x + threadIdx.x;
    if (i >= N * 32) return;
    int nid = i >> 5;
    float d = fmaxf(g_deg[nid], 1.f);
    g_ea[i] = tf32f(g_easum[i] / d);
}

__global__ void k_exp(const int* __restrict__ ei, int E, int N) {
    int i = blockIdx.x * blockDim.x + threadIdx.x;
    int tot4 = (E + N) * 4;
    if (i >= tot4) return;
    int e = i >> 2, h = i & 3;
    int d = (e < E) ? ei[E + e] : (e - E);
    float m  = f_dec(g_smax[d * 4 + h]);
    float ex = expf(g_score[i] - m);
    g_score[i] = ex;
    atomicAdd(&g_ssum[d * 4 + h], ex);
}

__global__ void k_agg(const int* __restrict__ ei, float* __restrict__ out_alpha,
                      int E, int N, int write_out) {
    int tot = E + N;
    int e = blockIdx.x * 8 + (threadIdx.x >> 5);
    if (e >= tot) return;
    int l = threadIdx.x & 31;
    int s = (e < E) ? ei[e]     : (e - E);
    int d = (e < E) ? ei[E + e] : (e - E);
    float a0 = __fdividef(g_score[(long)e * 4 + 0], g_ssum[d * 4 + 0]);
    float a1 = __fdividef(g_score[(long)e * 4 + 1], g_ssum[d * 4 + 1]);
    float a2 = __fdividef(g_score[(long)e * 4 + 2], g_ssum[d * 4 + 2]);
    float a3 = __fdividef(g_score[(long)e * 4 + 3], g_ssum[d * 4 + 3]);
    if (write_out && l < 4) {
        float a = (l == 0) ? a0 : (l == 1) ? a1 : (l == 2) ? a2 : a3;
        out_alpha[(long)e * 4 + l] = a;
    }
    a0 *= 0.25f; a1 *= 0.25f; a2 *= 0.25f; a3 *= 0.25f;
    const float4* xl4 = reinterpret_cast<const float4*>(g_xl + (long)s * 512);
    float4 v0 = xl4[ 0 + l], v1 = xl4[32 + l], v2 = xl4[64 + l], v3 = xl4[96 + l];
    float4 r;
    r.x = a0 * v0.x + a1 * v1.x + a2 * v2.x + a3 * v3.x;
    r.y = a0 * v0.y + a1 * v1.y + a2 * v2.y + a3 * v3.y;
    r.z = a0 * v0.z + a1 * v1.z + a2 * v2.z + a3 * v3.z;
    r.w = a0 * v0.w + a1 * v1.w + a2 * v2.w + a3 * v3.w;
    atomicAdd(reinterpret_cast<float4*>(g_agg + d * 128 + 4 * l), r);
}

// ---------------------------------------------------------------------------
static inline int G(int n) { return (n + 255) / 256; }

extern "C" void kernel_launch(void* const* d_in, const int* in_sizes, int n_in,
                              void* d_out, int out_size) {
    const float* x         = (const float*)d_in[0];
    const int*   ei        = (const int*)  d_in[1];
    const float* edge_attr = (const float*)d_in[2];
    const float* Wl  = (const float*)d_in[4];
    const float* bl  = (const float*)d_in[5];
    const float* Wr  = (const float*)d_in[6];
    const float* br  = (const float*)d_in[7];
    const float* We  = (const float*)d_in[8];
    const float* att = (const float*)d_in[9];
    const float* gbn = (const float*)d_in[10];
    const float* W1  = (const float*)d_in[11];
    const float* b1  = (const float*)d_in[12];
    const float* W2  = (const float*)d_in[13];
    const float* b2  = (const float*)d_in[14];
    const float* Wc  = (const float*)d_in[15];
    const float* bc  = (const float*)d_in[16];
    const float* nw0 = (const float*)d_in[17];
    const float* nb0 = (const float*)d_in[18];
    const float* nw1 = (const float*)d_in[19];
    const float* nb1 = (const float*)d_in[20];
    const float* nw2 = (const float*)d_in[21];
    const float* nb2 = (const float*)d_in[22];
    const float* nw3 = (const float*)d_in[23];
    const float* nb3 = (const float*)d_in[24];

    int N = in_sizes[0] / 128;
    int E = in_sizes[1] / 2;
    int TOT = E + N;
    float* out = (float*)d_out;
    int write_alpha = (out_size >= N * 64 + TOT * 4) ? 1 : 0;
    float* out_alpha = out + (size_t)N * 64;

    float *h0, *r1, *n1, *r2, *n2, *ea, *eat, *hid, *cls, *stats;
    float *wl, *wr, *we, *w1, *w2, *wc, *xl, *xr;
    cudaGetSymbolAddress((void**)&h0,    g_h0);
    cudaGetSymbolAddress((void**)&r1,    g_r1);
    cudaGetSymbolAddress((void**)&n1,    g_n1);
    cudaGetSymbolAddress((void**)&r2,    g_r2);
    cudaGetSymbolAddress((void**)&n2,    g_n2);
    cudaGetSymbolAddress((void**)&ea,    g_ea);
    cudaGetSymbolAddress((void**)&eat,   g_eat);
    cudaGetSymbolAddress((void**)&hid,   g_hid);
    cudaGetSymbolAddress((void**)&cls,   g_cls);
    cudaGetSymbolAddress((void**)&stats, g_stats);
    cudaGetSymbolAddress((void**)&wl,    g_wl);
    cudaGetSymbolAddress((void**)&wr,    g_wr);
    cudaGetSymbolAddress((void**)&we,    g_we);
    cudaGetSymbolAddress((void**)&w1,    g_w1);
    cudaGetSymbolAddress((void**)&w2,    g_w2);
    cudaGetSymbolAddress((void**)&wc,    g_wc);
    cudaGetSymbolAddress((void**)&xl,    g_xl);
    cudaGetSymbolAddress((void**)&xr,    g_xr);

    const int SM128 = 3 * (128 + 128) * 36 * 4;  // 110592 B
    const int SM64  = 3 * (128 +  64) * 36 * 4;  // 82944 B
    const int SMSC  = (128 * 36 + 128 * 36) * 4; // 36864 B
    cudaFuncSetAttribute(k_tgemm<128,2,4,1>, cudaFuncAttributeMaxDynamicSharedMemorySize, SM128);
    cudaFuncSetAttribute(k_tgemm<128,2,4,2>, cudaFuncAttributeMaxDynamicSharedMemorySize, SM128);
    cudaFuncSetAttribute(k_tgemm<128,2,4,3>, cudaFuncAttributeMaxDynamicSharedMemorySize, SM128);
    cudaFuncSetAttribute(k_tgemm<64,4,2,1>,  cudaFuncAttributeMaxDynamicSharedMemorySize, SM64);
    cudaFuncSetAttribute(k_gemm_score,       cudaFuncAttributeMaxDynamicSharedMemorySize, SMSC);

    // launches 0-3: init, rounds, norm-0 stats+apply
    k_init<<<G(N * 128), 256>>>(N);
    int nround = E * 8 + 16384 + 16384 + 4096 + 65536 + 65536 + 2048;
    k_round_all<<<G(nround), 256>>>(edge_attr, Wl, Wr, We, W1, W2, Wc, E);
    k_reduce<<<1024, 256>>>(x, N * 128 / 4, stats + 0);
    k_norm<1><<<G(N * 128), 256>>>(x, h0, nw0, nb0, stats + 0, 127, N * 128,
                                   1.f / (float)(N * 128));

    // launches 4-5: GATv2 linear transforms (launch 5 = profiled kernel)
    k_tgemm<128,2,4,1><<<dim3(4, N/128), 256, SM128>>>(h0, wl, bl, nullptr, xl, N, 512, 128);
    k_tgemm<128,2,4,1><<<dim3(4, N/128), 256, SM128>>>(h0, wr, br, nullptr, xr, N, 512, 128);

    // --- self-loop edge attrs ---
    k_degsum<<<G(E * 8), 256>>>(edge_attr, ei, E);
    k_eamean<<<G(N * 32), 256>>>(N);

    // --- fused ef GEMM + attention scores ---
    k_gemm_score<<<dim3(4, E/128), 256, SMSC>>>(eat, we, att, ei, 0, E);
    k_gemm_score<<<dim3(4, N/128), 256, SMSC>>>(ea, we, att, ei, E, E);

    // --- segment softmax + weighted aggregation ---
    k_exp<<<G(TOT * 4), 256>>>(ei, E, N);
    k_agg<<<(TOT + 7) / 8, 256>>>(ei, out_alpha, E, N, write_alpha);

    // --- residual + graph_norm 1 (rounded: feeds MLP) ---
    k_res_reduce<<<1024, 256>>>(gbn, N * 128 / 4, stats + 2);
    k_norm<1><<<G(N * 128), 256>>>(r1, n1, nw1, nb1, stats + 2, 127, N * 128,
                                   1.f / (float)(N * 128));

    // --- MLP ---
    k_tgemm<128,2,4,2><<<dim3(16, N/128), 256, SM128>>>(n1, w1, b1, nullptr, hid, N, 2048, 128);
    k_tgemm<128,2,4,3><<<dim3(1, N/128), 256, SM128>>>(hid, w2, b2, n1, r2, N, 128, 2048);

    // --- graph_norm 2 (rounded: feeds classifier) ---
    k_reduce<<<1024, 256>>>(r2, N * 128 / 4, stats + 4);
    k_norm<1><<<G(N * 128), 256>>>(r2, n2, nw2, nb2, stats + 4, 127, N * 128,
                                   1.f / (float)(N * 128));

    // --- classifier + graph_norm 3 (final output: full fp32) ---
    k_tgemm<64,4,2,1><<<dim3(1, N/128), 256, SM64>>>(n2, wc, bc, nullptr, cls, N, 64, 128);
    k_reduce<<<512, 256>>>(cls, N * 64 / 4, stats + 6);
    k_norm<0><<<G(N * 64), 256>>>(cls, out, nw3, nb3, stats + 6, 63, N * 64,
                                  1.f / (float)(N * 64));
}

// round 9
// speedup vs baseline: 5.3053x; 1.1293x over previous
#include <cuda_runtime.h>
#include <cuda_fp16.h>
#include <math.h>
#include <float.h>

// ---------------------------------------------------------------------------
// SynGNNLayer. R8: MLP2 on fp16 mma (hid stored fp16, halves DRAM + 2x mma),
// stats fused into MLP2 epilogue, float4 k_norm, vectorized k_exp.
// ---------------------------------------------------------------------------

#define NMAX 16384
#define EMAX 131072
#define TOTMAX (EMAX + NMAX)

static __device__ float g_h0 [NMAX * 128];
static __device__ float g_r1 [NMAX * 128];
static __device__ float g_n1 [NMAX * 128];
static __device__ float g_r2 [NMAX * 128];
static __device__ float g_n2 [NMAX * 128];
static __device__ float g_xl [NMAX * 512];
static __device__ float g_xr [NMAX * 512];
static __device__ float g_ea [NMAX * 32];
static __device__ float g_eat[EMAX * 32];
static __device__ __half g_hid16[(size_t)NMAX * 2048];
static __device__ float g_easum[NMAX * 32];
static __device__ float g_deg [NMAX];
static __device__ float g_score[TOTMAX * 4];
static __device__ unsigned g_smax[NMAX * 4];
static __device__ float g_ssum[NMAX * 4];
static __device__ float g_agg [NMAX * 128];
static __device__ float g_cls [NMAX * 64];
static __device__ float g_stats[8];
static __device__ float g_wl [512 * 128];
static __device__ float g_wr [512 * 128];
static __device__ float g_we [512 * 32];
static __device__ float g_w1 [2048 * 128];
static __device__ __half g_w2h[128 * 2048];
static __device__ float g_wc [64 * 128];

// ---- helpers --------------------------------------------------------------
__device__ __forceinline__ unsigned f_enc(float f) {
    unsigned u = __float_as_uint(f);
    return (u & 0x80000000u) ? ~u : (u | 0x80000000u);
}
__device__ __forceinline__ float f_dec(unsigned k) {
    return (k & 0x80000000u) ? __uint_as_float(k ^ 0x80000000u)
                             : __uint_as_float(~k);
}
__device__ __forceinline__ unsigned tf32r(float f) {
    unsigned u; asm("cvt.rna.tf32.f32 %0, %1;" : "=r"(u) : "f"(f)); return u;
}
__device__ __forceinline__ float tf32f(float f) {
    return __uint_as_float(tf32r(f));
}
__device__ __forceinline__ void cp16(void* smem, const void* gmem) {
    unsigned s = (unsigned)__cvta_generic_to_shared(smem);
    asm volatile("cp.async.cg.shared.global [%0], [%1], 16;\n" :: "r"(s), "l"(gmem));
}
#define CP_COMMIT() asm volatile("cp.async.commit_group;\n" ::: "memory")
#define CP_WAIT1()  asm volatile("cp.async.wait_group 1;\n" ::: "memory")

// ---------------------------------------------------------------------------
__global__ void k_init(int N) {
    int i = blockIdx.x * blockDim.x + threadIdx.x;
    if (i < N * 128) g_agg[i] = 0.f;
    if (i < N * 32)  g_easum[i] = 0.f;
    if (i < N * 4)   { g_ssum[i] = 0.f; g_smax[i] = 0x00800000u; }
    if (i < N)       g_deg[i] = 0.f;
    if (i < 8)       g_stats[i] = 0.f;
}

// one launch: tf32-round edge_attr + weights; W2 -> fp16
__global__ void k_round_all(const float* __restrict__ ea,
                            const float* __restrict__ Wl, const float* __restrict__ Wr,
                            const float* __restrict__ We, const float* __restrict__ W1,
                            const float* __restrict__ W2, const float* __restrict__ Wc,
                            int E) {
    int i = blockIdx.x * blockDim.x + threadIdx.x;
    int nea = E * 8;
    const float* src; float* dst; int off;
    if      (i < nea)                { src = ea; dst = g_eat; off = i; }
    else if ((i -= nea)   < 16384)   { src = Wl; dst = g_wl;  off = i; }
    else if ((i -= 16384) < 16384)   { src = Wr; dst = g_wr;  off = i; }
    else if ((i -= 16384) < 4096)    { src = We; dst = g_we;  off = i; }
    else if ((i -= 4096)  < 65536)   { src = W1; dst = g_w1;  off = i; }
    else if ((i -= 65536) < 65536)   {           // W2 -> half
        float4 v = reinterpret_cast<const float4*>(W2)[i];
        __half2 h01 = __floats2half2_rn(v.x, v.y);
        __half2 h23 = __floats2half2_rn(v.z, v.w);
        uint2 u = { *(unsigned*)&h01, *(unsigned*)&h23 };
        reinterpret_cast<uint2*>(g_w2h)[i] = u;
        return;
    }
    else if ((i -= 65536) < 2048)    { src = Wc; dst = g_wc;  off = i; }
    else return;
    float4 v = reinterpret_cast<const float4*>(src)[off];
    v.x = tf32f(v.x); v.y = tf32f(v.y); v.z = tf32f(v.z); v.w = tf32f(v.w);
    reinterpret_cast<float4*>(dst)[off] = v;
}

// sum + sumsq reduction
__global__ void k_reduce(const float* __restrict__ x, int n4, float* __restrict__ out) {
    float s = 0.f, ss = 0.f;
    for (int i = blockIdx.x * blockDim.x + threadIdx.x; i < n4; i += gridDim.x * blockDim.x) {
        float4 v = reinterpret_cast<const float4*>(x)[i];
        s  += v.x + v.y + v.z + v.w;
        ss += v.x * v.x + v.y * v.y + v.z * v.z + v.w * v.w;
    }
    #pragma unroll
    for (int o = 16; o > 0; o >>= 1) {
        s  += __shfl_xor_sync(0xffffffffu, s,  o);
        ss += __shfl_xor_sync(0xffffffffu, ss, o);
    }
    __shared__ float shs[8], shss[8];
    int w = threadIdx.x >> 5;
    if ((threadIdx.x & 31) == 0) { shs[w] = s; shss[w] = ss; }
    __syncthreads();
    if (threadIdx.x < 8) {
        s = shs[threadIdx.x]; ss = shss[threadIdx.x];
        #pragma unroll
        for (int o = 4; o > 0; o >>= 1) {
            s  += __shfl_xor_sync(0xffu, s,  o);
            ss += __shfl_xor_sync(0xffu, ss, o);
        }
        if (threadIdx.x == 0) { atomicAdd(out, s); atomicAdd(out + 1, ss); }
    }
}

// residual + reduction: r1 = h0 + agg + bias
__global__ void k_res_reduce(const float* __restrict__ gat_bias, int n4,
                             float* __restrict__ out) {
    float s = 0.f, ss = 0.f;
    const float4* b4 = reinterpret_cast<const float4*>(gat_bias);
    for (int i = blockIdx.x * blockDim.x + threadIdx.x; i < n4; i += gridDim.x * blockDim.x) {
        float4 a = reinterpret_cast<const float4*>(g_h0)[i];
        float4 g = reinterpret_cast<const float4*>(g_agg)[i];
        float4 b = b4[i & 31];
        float4 v = { a.x + g.x + b.x, a.y + g.y + b.y,
                     a.z + g.z + b.z, a.w + g.w + b.w };
        reinterpret_cast<float4*>(g_r1)[i] = v;
        s  += v.x + v.y + v.z + v.w;
        ss += v.x * v.x + v.y * v.y + v.z * v.z + v.w * v.w;
    }
    #pragma unroll
    for (int o = 16; o > 0; o >>= 1) {
        s  += __shfl_xor_sync(0xffffffffu, s,  o);
        ss += __shfl_xor_sync(0xffffffffu, ss, o);
    }
    __shared__ float shs[8], shss[8];
    int w = threadIdx.x >> 5;
    if ((threadIdx.x & 31) == 0) { shs[w] = s; shss[w] = ss; }
    __syncthreads();
    if (threadIdx.x < 8) {
        s = shs[threadIdx.x]; ss = shss[threadIdx.x];
        #pragma unroll
        for (int o = 4; o > 0; o >>= 1) {
            s  += __shfl_xor_sync(0xffu, s,  o);
            ss += __shfl_xor_sync(0xffu, ss, o);
        }
        if (threadIdx.x == 0) { atomicAdd(out, s); atomicAdd(out + 1, ss); }
    }
}

// graph_norm apply, float4; DmaskV masks the float4 index to the channel group
template <int ROUND>
__global__ void k_norm(const float* __restrict__ x, float* __restrict__ y,
                       const float* __restrict__ w, const float* __restrict__ b,
                       const float* __restrict__ st, int DmaskV, int n4, float invn) {
    int i = blockIdx.x * blockDim.x + threadIdx.x;
    if (i >= n4) return;
    float mu  = st[0] * invn;
    float var = st[1] * invn - mu * mu;
    float inv = 1.f / (sqrtf(fmaxf(var, 0.f)) + 1e-5f);
    int c = i & DmaskV;
    float4 xv = reinterpret_cast<const float4*>(x)[i];
    float4 wv = reinterpret_cast<const float4*>(w)[c];
    float4 bv = reinterpret_cast<const float4*>(b)[c];
    float4 r;
    r.x = (xv.x - mu) * inv * wv.x + bv.x;
    r.y = (xv.y - mu) * inv * wv.y + bv.y;
    r.z = (xv.z - mu) * inv * wv.z + bv.z;
    r.w = (xv.w - mu) * inv * wv.w + bv.w;
    if (ROUND) { r.x = tf32f(r.x); r.y = tf32f(r.y); r.z = tf32f(r.z); r.w = tf32f(r.w); }
    reinterpret_cast<float4*>(y)[i] = r;
}

// ---------------------------------------------------------------------------
// tf32 tensor GEMM, 3-stage cp.async. EPI: 1 +bias, 2 +bias,relu -> HALF out
// (feeds fp16 MLP2), 3 +bias,+res
// ---------------------------------------------------------------------------
template<int BN, int WROWS, int WCOLS, int EPI>
__global__ void __launch_bounds__(256, 2)
k_tgemm(const float* __restrict__ A, const float* __restrict__ W,
        const float* __restrict__ bias, const float* __restrict__ res,
        float* __restrict__ C, int M, int Nn, int K)
{
    constexpr int BM = 128, BK = 32, LDA = BK + 4, STAGES = 3;
    constexpr int MF = BM / (WROWS * 16);
    constexpr int NF = BN / (WCOLS * 8);
    constexpr int A_CP = (BM * BK / 4) / 256;
    constexpr int B_CP = (BN * BK / 4) / 256;

    extern __shared__ float sh[];
    float* As = sh;
    float* Bs = sh + STAGES * BM * LDA;

    const int tid = threadIdx.x;
    const int wid = tid >> 5, lane = tid & 31;
    const int wm = wid / WCOLS, wn = wid % WCOLS;
    const int g = lane >> 2, tg = lane & 3;
    const long m0 = (long)blockIdx.y * BM;
    const int  n0 = blockIdx.x * BN;

    auto issue = [&](int stage, int kk) {
        #pragma unroll
        for (int i = 0; i < A_CP; i++) {
            int idx = tid + i * 256;
            int r = idx >> 3, c4 = idx & 7;
            cp16(&As[stage * BM * LDA + r * LDA + c4 * 4],
                 A + (m0 + r) * K + kk + c4 * 4);
        }
        #pragma unroll
        for (int i = 0; i < B_CP; i++) {
            int idx = tid + i * 256;
            int r = idx >> 3, c4 = idx & 7;
            cp16(&Bs[stage * BN * LDA + r * LDA + c4 * 4],
                 W + (long)(n0 + r) * K + kk + c4 * 4);
        }
        CP_COMMIT();
    };

    const int NT = K / BK;
    issue(0, 0);
    if (1 < NT) issue(1, BK); else CP_COMMIT();

    float acc[MF][NF][4] = {};
    for (int kt = 0; kt < NT; kt++) {
        CP_WAIT1();
        __syncthreads();
        if (kt + STAGES - 1 < NT)
            issue((kt + STAGES - 1) % STAGES, (kt + STAGES - 1) * BK);
        else
            CP_COMMIT();
        const unsigned* Asb = reinterpret_cast<const unsigned*>(As) + (kt % STAGES) * BM * LDA;
        const unsigned* Bsb = reinterpret_cast<const unsigned*>(Bs) + (kt % STAGES) * BN * LDA;
        #pragma unroll
        for (int k8 = 0; k8 < BK / 8; k8++) {
            unsigned af[MF][4], bf[NF][2];
            #pragma unroll
            for (int i = 0; i < MF; i++) {
                int r = wm * (MF * 16) + i * 16 + g;
                const unsigned* p = Asb + r * LDA + k8 * 8;
                af[i][0] = p[tg];
                af[i][1] = p[8 * LDA + tg];
                af[i][2] = p[tg + 4];
                af[i][3] = p[8 * LDA + tg + 4];
            }
            #pragma unroll
            for (int j = 0; j < NF; j++) {
                int c = wn * (NF * 8) + j * 8 + g;
                const unsigned* p = Bsb + c * LDA + k8 * 8;
                bf[j][0] = p[tg];
                bf[j][1] = p[tg + 4];
            }
            #pragma unroll
            for (int i = 0; i < MF; i++)
                #pragma unroll
                for (int j = 0; j < NF; j++) {
                    asm volatile(
                        "mma.sync.aligned.m16n8k8.row.col.f32.tf32.tf32.f32 "
                        "{%0,%1,%2,%3}, {%4,%5,%6,%7}, {%8,%9}, {%0,%1,%2,%3};\n"
                        : "+f"(acc[i][j][0]), "+f"(acc[i][j][1]),
                          "+f"(acc[i][j][2]), "+f"(acc[i][j][3])
                        : "r"(af[i][0]), "r"(af[i][1]), "r"(af[i][2]), "r"(af[i][3]),
                          "r"(bf[j][0]), "r"(bf[j][1]));
                }
        }
    }

    #pragma unroll
    for (int i = 0; i < MF; i++) {
        long mA = m0 + wm * (MF * 16) + i * 16 + g;
        long mB = mA + 8;
        #pragma unroll
        for (int j = 0; j < NF; j++) {
            int c = n0 + wn * (NF * 8) + j * 8 + tg * 2;
            float v0 = acc[i][j][0], v1 = acc[i][j][1];
            float v2 = acc[i][j][2], v3 = acc[i][j][3];
            if (EPI >= 1) {
                float b0 = bias[c], b1 = bias[c + 1];
                v0 += b0; v1 += b1; v2 += b0; v3 += b1;
            }
            if (EPI == 2) {      // relu -> fp16 output (hid)
                __half2 hA = __floats2half2_rn(fmaxf(v0, 0.f), fmaxf(v1, 0.f));
                __half2 hB = __floats2half2_rn(fmaxf(v2, 0.f), fmaxf(v3, 0.f));
                __half* Ch = reinterpret_cast<__half*>(C);
                *reinterpret_cast<__half2*>(Ch + mA * Nn + c) = hA;
                *reinterpret_cast<__half2*>(Ch + mB * Nn + c) = hB;
                continue;
            }
            if (EPI == 3) {
                float2 rA = reinterpret_cast<const float2*>(res + mA * Nn + c)[0];
                float2 rB = reinterpret_cast<const float2*>(res + mB * Nn + c)[0];
                v0 += rA.x; v1 += rA.y; v2 += rB.x; v3 += rB.y;
            }
            reinterpret_cast<float2*>(C + mA * Nn + c)[0] = make_float2(v0, v1);
            reinterpret_cast<float2*>(C + mB * Nn + c)[0] = make_float2(v2, v3);
        }
    }
}

// ---------------------------------------------------------------------------
// fp16 tensor GEMM (MLP2): r2 = hid16 @ W2h^T + b2 + n1, fused stats reduce.
// BM=BN=128, BKh=64 halfs; word-geometry identical to tf32 BK=32 (LDA=36 w).
// ---------------------------------------------------------------------------
__global__ void __launch_bounds__(256, 2)
k_hgemm(const __half* __restrict__ A, const __half* __restrict__ W,
        const float* __restrict__ bias, const float* __restrict__ res,
        float* __restrict__ C, float* __restrict__ stats_out, int M, int Nn, int K)
{
    constexpr int BM = 128, BN = 128, BKh = 64, LDW = 36, STAGES = 3;
    constexpr int MF = 4, NF = 4;   // warps 2x4

    extern __shared__ float sh[];
    unsigned* As = reinterpret_cast<unsigned*>(sh);           // [S][BM][36] words
    unsigned* Bs = As + STAGES * BM * LDW;

    const int tid = threadIdx.x;
    const int wid = tid >> 5, lane = tid & 31;
    const int wm = wid >> 2, wn = wid & 3;
    const int g = lane >> 2, tg = lane & 3;
    const long m0 = (long)blockIdx.y * BM;
    const int  n0 = blockIdx.x * BN;

    auto issue = [&](int stage, int kk) {
        #pragma unroll
        for (int i = 0; i < 4; i++) {        // BM*BKh/8 chunks /256
            int idx = tid + i * 256;
            int r = idx >> 3, c8 = idx & 7;
            cp16(&As[stage * BM * LDW + r * LDW + c8 * 4],
                 A + (m0 + r) * K + kk + c8 * 8);
        }
        #pragma unroll
        for (int i = 0; i < 4; i++) {
            int idx = tid + i * 256;
            int r = idx >> 3, c8 = idx & 7;
            cp16(&Bs[stage * BN * LDW + r * LDW + c8 * 4],
                 W + (long)(n0 + r) * K + kk + c8 * 8);
        }
        CP_COMMIT();
    };

    const int NT = K / BKh;
    issue(0, 0);
    issue(1, BKh);

    float acc[MF][NF][4] = {};
    for (int kt = 0; kt < NT; kt++) {
        CP_WAIT1();
        __syncthreads();
        if (kt + STAGES - 1 < NT)
            issue((kt + STAGES - 1) % STAGES, (kt + STAGES - 1) * BKh);
        else
            CP_COMMIT();
        const unsigned* Asb = As + (kt % STAGES) * BM * LDW;
        const unsigned* Bsb = Bs + (kt % STAGES) * BN * LDW;
        #pragma unroll
        for (int k16 = 0; k16 < 4; k16++) {   // 4 x k=16 steps
            unsigned af[MF][4], bf[NF][2];
            #pragma unroll
            for (int i = 0; i < MF; i++) {
                int r = wm * 64 + i * 16 + g;
                const unsigned* p = Asb + r * LDW + k16 * 8;
                af[i][0] = p[tg];
                af[i][1] = p[8 * LDW + tg];
                af[i][2] = p[tg + 4];
                af[i][3] = p[8 * LDW + tg + 4];
            }
            #pragma unroll
            for (int j = 0; j < NF; j++) {
                int c = wn * 32 + j * 8 + g;
                const unsigned* p = Bsb + c * LDW + k16 * 8;
                bf[j][0] = p[tg];
                bf[j][1] = p[tg + 4];
            }
            #pragma unroll
            for (int i = 0; i < MF; i++)
                #pragma unroll
                for (int j = 0; j < NF; j++) {
                    asm volatile(
                        "mma.sync.aligned.m16n8k16.row.col.f32.f16.f16.f32 "
                        "{%0,%1,%2,%3}, {%4,%5,%6,%7}, {%8,%9}, {%0,%1,%2,%3};\n"
                        : "+f"(acc[i][j][0]), "+f"(acc[i][j][1]),
                          "+f"(acc[i][j][2]), "+f"(acc[i][j][3])
                        : "r"(af[i][0]), "r"(af[i][1]), "r"(af[i][2]), "r"(af[i][3]),
                          "r"(bf[j][0]), "r"(bf[j][1]));
                }
        }
    }

    float s = 0.f, ss = 0.f;
    #pragma unroll
    for (int i = 0; i < MF; i++) {
        long mA = m0 + wm * 64 + i * 16 + g;
        long mB = mA + 8;
        #pragma unroll
        for (int j = 0; j < NF; j++) {
            int c = n0 + wn * 32 + j * 8 + tg * 2;
            float b0 = bias[c], b1 = bias[c + 1];
            float2 rA = reinterpret_cast<const float2*>(res + mA * Nn + c)[0];
            float2 rB = reinterpret_cast<const float2*>(res + mB * Nn + c)[0];
            float v0 = acc[i][j][0] + b0 + rA.x;
            float v1 = acc[i][j][1] + b1 + rA.y;
            float v2 = acc[i][j][2] + b0 + rB.x;
            float v3 = acc[i][j][3] + b1 + rB.y;
            reinterpret_cast<float2*>(C + mA * Nn + c)[0] = make_float2(v0, v1);
            reinterpret_cast<float2*>(C + mB * Nn + c)[0] = make_float2(v2, v3);
            s  += v0 + v1 + v2 + v3;
            ss += v0 * v0 + v1 * v1 + v2 * v2 + v3 * v3;
        }
    }
    // fused stats: block reduce then one atomic pair
    #pragma unroll
    for (int o = 16; o > 0; o >>= 1) {
        s  += __shfl_xor_sync(0xffffffffu, s,  o);
        ss += __shfl_xor_sync(0xffffffffu, ss, o);
    }
    __syncthreads();               // safe to reuse smem now
    float* red = sh;
    if (lane == 0) { red[wid] = s; red[8 + wid] = ss; }
    __syncthreads();
    if (tid == 0) {
        float ts = 0.f, tss = 0.f;
        #pragma unroll
        for (int w = 0; w < 8; w++) { ts += red[w]; tss += red[8 + w]; }
        atomicAdd(stats_out, ts);
        atomicAdd(stats_out + 1, tss);
    }
}

// ---------------------------------------------------------------------------
// ef GEMM + fused attention score epilogue.
// ---------------------------------------------------------------------------
__global__ void __launch_bounds__(256, 2)
k_gemm_score(const float* __restrict__ A, const float* __restrict__ W,
             const float* __restrict__ att, const int* __restrict__ ei,
             int ebase, int E)
{
    constexpr int BM = 128, BN = 128, BK = 32, LDA = BK + 4;
    constexpr int MF = 4, NF = 4;

    extern __shared__ float shf[];
    float* As = shf;
    float* Bs = shf + BM * LDA;
    float* srow = shf;

    const int tid = threadIdx.x;
    const int wid = tid >> 5, lane = tid & 31;
    const int wm = wid >> 2, wn = wid & 3;
    const int g = lane >> 2, tg = lane & 3;
    const long m0 = (long)blockIdx.y * BM;
    const int  n0 = blockIdx.x * BN;

    #pragma unroll
    for (int t = 0; t < 4; t++) {
        int idx = tid + t * 256;
        int r = idx >> 3, c4 = idx & 7;
        reinterpret_cast<float4*>(&As[r * LDA + c4 * 4])[0] =
            reinterpret_cast<const float4*>(A + (m0 + r) * BK)[c4];
        reinterpret_cast<float4*>(&Bs[r * LDA + c4 * 4])[0] =
            reinterpret_cast<const float4*>(W + (long)(n0 + r) * BK)[c4];
    }
    __syncthreads();

    float acc[MF][NF][4] = {};
    const unsigned* Asu = reinterpret_cast<const unsigned*>(As);
    const unsigned* Bsu = reinterpret_cast<const unsigned*>(Bs);
    #pragma unroll
    for (int k8 = 0; k8 < 4; k8++) {
        unsigned af[MF][4], bf[NF][2];
        #pragma unroll
        for (int i = 0; i < MF; i++) {
            int r = wm * 64 + i * 16 + g;
            const unsigned* p = Asu + r * LDA + k8 * 8;
            af[i][0] = p[tg];
            af[i][1] = p[8 * LDA + tg];
            af[i][2] = p[tg + 4];
            af[i][3] = p[8 * LDA + tg + 4];
        }
        #pragma unroll
        for (int j = 0; j < NF; j++) {
            int c = wn * 32 + j * 8 + g;
            const unsigned* p = Bsu + c * LDA + k8 * 8;
            bf[j][0] = p[tg];
            bf[j][1] = p[tg + 4];
        }
        #pragma unroll
        for (int i = 0; i < MF; i++)
            #pragma unroll
            for (int j = 0; j < NF; j++) {
                asm volatile(
                    "mma.sync.aligned.m16n8k8.row.col.f32.tf32.tf32.f32 "
                    "{%0,%1,%2,%3}, {%4,%5,%6,%7}, {%8,%9}, {%0,%1,%2,%3};\n"
                    : "+f"(acc[i][j][0]), "+f"(acc[i][j][1]),
                      "+f"(acc[i][j][2]), "+f"(acc[i][j][3])
                    : "r"(af[i][0]), "r"(af[i][1]), "r"(af[i][2]), "r"(af[i][3]),
                      "r"(bf[j][0]), "r"(bf[j][1]));
            }
    }

    float part[MF][2] = {};
    #pragma unroll
    for (int i = 0; i < MF; i++) {
        int rA = wm * 64 + i * 16 + g;
        int rB = rA + 8;
        int geA = ebase + (int)m0 + rA;
        int geB = ebase + (int)m0 + rB;
        int sA = (geA < E) ? ei[geA] : (geA - E);
        int dA = (geA < E) ? ei[E + geA] : (geA - E);
        int sB = (geB < E) ? ei[geB] : (geB - E);
        int dB = (geB < E) ? ei[E + geB] : (geB - E);
        const float* xlA = g_xl + (long)sA * 512 + n0;
        const float* xrA = g_xr + (long)dA * 512 + n0;
        const float* xlB = g_xl + (long)sB * 512 + n0;
        const float* xrB = g_xr + (long)dB * 512 + n0;
        #pragma unroll
        for (int j = 0; j < NF; j++) {
            int c = wn * 32 + j * 8 + tg * 2;
            float2 a0 = reinterpret_cast<const float2*>(att + n0 + c)[0];
            float2 lA = reinterpret_cast<const float2*>(xlA + c)[0];
            float2 rAv= reinterpret_cast<const float2*>(xrA + c)[0];
            float2 lB = reinterpret_cast<const float2*>(xlB + c)[0];
            float2 rBv= reinterpret_cast<const float2*>(xrB + c)[0];
            float z0 = acc[i][j][0] + lA.x + rAv.x; z0 = z0 > 0.f ? z0 : 0.2f * z0;
            float z1 = acc[i][j][1] + lA.y + rAv.y; z1 = z1 > 0.f ? z1 : 0.2f * z1;
            float z2 = acc[i][j][2] + lB.x + rBv.x; z2 = z2 > 0.f ? z2 : 0.2f * z2;
            float z3 = acc[i][j][3] + lB.y + rBv.y; z3 = z3 > 0.f ? z3 : 0.2f * z3;
            part[i][0] += z0 * a0.x + z1 * a0.y;
            part[i][1] += z2 * a0.x + z3 * a0.y;
        }
    }
    #pragma unroll
    for (int i = 0; i < MF; i++) {
        #pragma unroll
        for (int o = 1; o <= 2; o <<= 1) {
            part[i][0] += __shfl_xor_sync(0xffffffffu, part[i][0], o);
            part[i][1] += __shfl_xor_sync(0xffffffffu, part[i][1], o);
        }
    }
    __syncthreads();
    if (tg == 0) {
        #pragma unroll
        for (int i = 0; i < MF; i++) {
            int rA = wm * 64 + i * 16 + g;
            srow[wn * 128 + rA]     = part[i][0];
            srow[wn * 128 + rA + 8] = part[i][1];
        }
    }
    __syncthreads();
    if (tid < 128) {
        float s = srow[tid] + srow[128 + tid] + srow[256 + tid] + srow[384 + tid];
        int ge = ebase + (int)m0 + tid;
        int d  = (ge < E) ? ei[E + ge] : (ge - E);
        int h  = blockIdx.x;
        g_score[(long)ge * 4 + h] = s;
        atomicMax(&g_smax[d * 4 + h], f_enc(s));
    }
}

// ---- edge-side kernels ----------------------------------------------------
__global__ void k_degsum(const float* __restrict__ edge_attr,
                         const int* __restrict__ ei, int E) {
    int i = blockIdx.x * blockDim.x + threadIdx.x;
    if (i >= E * 8) return;
    int e = i >> 3, c4 = i & 7;
    int dst = ei[E + e];
    float4 v = reinterpret_cast<const float4*>(edge_attr + (long)e * 32)[c4];
    atomicAdd(reinterpret_cast<float4*>(&g_easum[dst * 32 + c4 * 4]), v);
    if (c4 == 0) atomicAdd(&g_deg[dst], 1.f);
}

__global__ void k_eamean(int N) {
    int i = blockIdx.x * blockDim.x + threadIdx.x;
    if (i >= N * 32) return;
    int nid = i >> 5;
    float d = fmaxf(g_deg[nid], 1.f);
    g_ea[i] = tf32f(g_easum[i] / d);
}

// vectorized: one thread per edge, all 4 heads; single float4 atomic on ssum
__global__ void k_exp(const int* __restrict__ ei, int E, int N) {
    int e = blockIdx.x * blockDim.x + threadIdx.x;
    if (e >= E + N) return;
    int d = (e < E) ? ei[E + e] : (e - E);
    uint4 mk = reinterpret_cast<const uint4*>(g_smax)[d];
    float4 sc = reinterpret_cast<const float4*>(g_score)[e];
    float4 ex;
    ex.x = expf(sc.x - f_dec(mk.x));
    ex.y = expf(sc.y - f_dec(mk.y));
    ex.z = expf(sc.z - f_dec(mk.z));
    ex.w = expf(sc.w - f_dec(mk.w));
    reinterpret_cast<float4*>(g_score)[e] = ex;
    atomicAdd(reinterpret_cast<float4*>(&g_ssum[d * 4]), ex);
}

__global__ void k_agg(const int* __restrict__ ei, float* __restrict__ out_alpha,
                      int E, int N, int write_out) {
    int tot = E + N;
    int e = blockIdx.x * 8 + (threadIdx.x >> 5);
    if (e >= tot) return;
    int l = threadIdx.x & 31;
    int s = (e < E) ? ei[e]     : (e - E);
    int d = (e < E) ? ei[E + e] : (e - E);
    float a0 = __fdividef(g_score[(long)e * 4 + 0], g_ssum[d * 4 + 0]);
    float a1 = __fdividef(g_score[(long)e * 4 + 1], g_ssum[d * 4 + 1]);
    float a2 = __fdividef(g_score[(long)e * 4 + 2], g_ssum[d * 4 + 2]);
    float a3 = __fdividef(g_score[(long)e * 4 + 3], g_ssum[d * 4 + 3]);
    if (write_out && l < 4) {
        float a = (l == 0) ? a0 : (l == 1) ? a1 : (l == 2) ? a2 : a3;
        out_alpha[(long)e * 4 + l] = a;
    }
    a0 *= 0.25f; a1 *= 0.25f; a2 *= 0.25f; a3 *= 0.25f;
    const float4* xl4 = reinterpret_cast<const float4*>(g_xl + (long)s * 512);
    float4 v0 = xl4[ 0 + l], v1 = xl4[32 + l], v2 = xl4[64 + l], v3 = xl4[96 + l];
    float4 r;
    r.x = a0 * v0.x + a1 * v1.x + a2 * v2.x + a3 * v3.x;
    r.y = a0 * v0.y + a1 * v1.y + a2 * v2.y + a3 * v3.y;
    r.z = a0 * v0.z + a1 * v1.z + a2 * v2.z + a3 * v3.z;
    r.w = a0 * v0.w + a1 * v1.w + a2 * v2.w + a3 * v3.w;
    atomicAdd(reinterpret_cast<float4*>(g_agg + d * 128 + 4 * l), r);
}

// ---------------------------------------------------------------------------
static inline int G(int n) { return (n + 255) / 256; }

extern "C" void kernel_launch(void* const* d_in, const int* in_sizes, int n_in,
                              void* d_out, int out_size) {
    const float* x         = (const float*)d_in[0];
    const int*   ei        = (const int*)  d_in[1];
    const float* edge_attr = (const float*)d_in[2];
    const float* Wl  = (const float*)d_in[4];
    const float* bl  = (const float*)d_in[5];
    const float* Wr  = (const float*)d_in[6];
    const float* br  = (const float*)d_in[7];
    const float* We  = (const float*)d_in[8];
    const float* att = (const float*)d_in[9];
    const float* gbn = (const float*)d_in[10];
    const float* W1  = (const float*)d_in[11];
    const float* b1  = (const float*)d_in[12];
    const float* W2  = (const float*)d_in[13];
    const float* b2  = (const float*)d_in[14];
    const float* Wc  = (const float*)d_in[15];
    const float* bc  = (const float*)d_in[16];
    const float* nw0 = (const float*)d_in[17];
    const float* nb0 = (const float*)d_in[18];
    const float* nw1 = (const float*)d_in[19];
    const float* nb1 = (const float*)d_in[20];
    const float* nw2 = (const float*)d_in[21];
    const float* nb2 = (const float*)d_in[22];
    const float* nw3 = (const float*)d_in[23];
    const float* nb3 = (const float*)d_in[24];

    int N = in_sizes[0] / 128;
    int E = in_sizes[1] / 2;
    int TOT = E + N;
    float* out = (float*)d_out;
    int write_alpha = (out_size >= N * 64 + TOT * 4) ? 1 : 0;
    float* out_alpha = out + (size_t)N * 64;

    float *h0, *r1, *n1, *r2, *n2, *ea, *eat, *cls, *stats;
    float *wl, *wr, *we, *w1, *wc, *xl, *xr;
    __half *hid16, *w2h;
    cudaGetSymbolAddress((void**)&h0,    g_h0);
    cudaGetSymbolAddress((void**)&r1,    g_r1);
    cudaGetSymbolAddress((void**)&n1,    g_n1);
    cudaGetSymbolAddress((void**)&r2,    g_r2);
    cudaGetSymbolAddress((void**)&n2,    g_n2);
    cudaGetSymbolAddress((void**)&ea,    g_ea);
    cudaGetSymbolAddress((void**)&eat,   g_eat);
    cudaGetSymbolAddress((void**)&hid16, g_hid16);
    cudaGetSymbolAddress((void**)&cls,   g_cls);
    cudaGetSymbolAddress((void**)&stats, g_stats);
    cudaGetSymbolAddress((void**)&wl,    g_wl);
    cudaGetSymbolAddress((void**)&wr,    g_wr);
    cudaGetSymbolAddress((void**)&we,    g_we);
    cudaGetSymbolAddress((void**)&w1,    g_w1);
    cudaGetSymbolAddress((void**)&w2h,   g_w2h);
    cudaGetSymbolAddress((void**)&wc,    g_wc);
    cudaGetSymbolAddress((void**)&xl,    g_xl);
    cudaGetSymbolAddress((void**)&xr,    g_xr);

    const int SM128 = 3 * (128 + 128) * 36 * 4;  // 110592 B (tf32 & fp16 same)
    const int SM64  = 3 * (128 +  64) * 36 * 4;
    const int SMSC  = (128 * 36 + 128 * 36) * 4;
    cudaFuncSetAttribute(k_tgemm<128,2,4,1>, cudaFuncAttributeMaxDynamicSharedMemorySize, SM128);
    cudaFuncSetAttribute(k_tgemm<128,2,4,2>, cudaFuncAttributeMaxDynamicSharedMemorySize, SM128);
    cudaFuncSetAttribute(k_tgemm<64,4,2,1>,  cudaFuncAttributeMaxDynamicSharedMemorySize, SM64);
    cudaFuncSetAttribute(k_hgemm,            cudaFuncAttributeMaxDynamicSharedMemorySize, SM128);
    cudaFuncSetAttribute(k_gemm_score,       cudaFuncAttributeMaxDynamicSharedMemorySize, SMSC);

    k_init<<<G(N * 128), 256>>>(N);
    int nround = E * 8 + 16384 + 16384 + 4096 + 65536 + 65536 + 2048;
    k_round_all<<<G(nround), 256>>>(edge_attr, Wl, Wr, We, W1, W2, Wc, E);
    k_reduce<<<1024, 256>>>(x, N * 128 / 4, stats + 0);
    k_norm<1><<<G(N * 32), 256>>>(x, h0, nw0, nb0, stats + 0, 31, N * 32,
                                  1.f / (float)(N * 128));

    // GATv2 linear transforms (launch 5 = profiled)
    k_tgemm<128,2,4,1><<<dim3(4, N/128), 256, SM128>>>(h0, wl, bl, nullptr, xl, N, 512, 128);
    k_tgemm<128,2,4,1><<<dim3(4, N/128), 256, SM128>>>(h0, wr, br, nullptr, xr, N, 512, 128);

    k_degsum<<<G(E * 8), 256>>>(edge_attr, ei, E);
    k_eamean<<<G(N * 32), 256>>>(N);

    k_gemm_score<<<dim3(4, E/128), 256, SMSC>>>(eat, we, att, ei, 0, E);
    k_gemm_score<<<dim3(4, N/128), 256, SMSC>>>(ea, we, att, ei, E, E);

    k_exp<<<G(TOT), 256>>>(ei, E, N);
    k_agg<<<(TOT + 7) / 8, 256>>>(ei, out_alpha, E, N, write_alpha);

    k_res_reduce<<<1024, 256>>>(gbn, N * 128 / 4, stats + 2);
    k_norm<1><<<G(N * 32), 256>>>(r1, n1, nw1, nb1, stats + 2, 31, N * 32,
                                  1.f / (float)(N * 128));

    // MLP: tf32 -> fp16 hid -> fp16 GEMM with fused stats4
    k_tgemm<128,2,4,2><<<dim3(16, N/128), 256, SM128>>>(n1, w1, b1, nullptr,
                                                        (float*)hid16, N, 2048, 128);
    k_hgemm<<<dim3(1, N/128), 256, SM128>>>(hid16, w2h, b2, n1, r2, stats + 4,
                                            N, 128, 2048);

    k_norm<1><<<G(N * 32), 256>>>(r2, n2, nw2, nb2, stats + 4, 31, N * 32,
                                  1.f / (float)(N * 128));

    // classifier + graph_norm 3
    k_tgemm<64,4,2,1><<<dim3(1, N/128), 256, SM64>>>(n2, wc, bc, nullptr, cls, N, 64, 128);
    k_reduce<<<512, 256>>>(cls, N * 64 / 4, stats + 6);
    k_norm<0><<<G(N * 16), 256>>>(cls, out, nw3, nb3, stats + 6, 15, N * 16,
                                  1.f / (float)(N * 64));
}

// round 10
// speedup vs baseline: 6.0554x; 1.1414x over previous
#include <cuda_runtime.h>
#include <cuda_fp16.h>
#include <math.h>
#include <float.h>

// ---------------------------------------------------------------------------
// SynGNNLayer. R10: ALL dense GEMMs on fp16 mma (layout validated in R8);
// activations h0/n1/n2 stored fp16; classifier stats fused into epilogue.
// Score GEMM stays tf32 (epilogue-gather bound).
// ---------------------------------------------------------------------------

#define NMAX 16384
#define EMAX 131072
#define TOTMAX (EMAX + NMAX)

static __device__ __half g_h0h[NMAX * 128];
static __device__ float  g_r1 [NMAX * 128];
static __device__ __half g_n1h[NMAX * 128];
static __device__ float  g_r2 [NMAX * 128];
static __device__ __half g_n2h[NMAX * 128];
static __device__ float  g_xl [NMAX * 512];
static __device__ float  g_xr [NMAX * 512];
static __device__ float  g_ea [NMAX * 32];
static __device__ float  g_eat[EMAX * 32];
static __device__ __half g_hid16[(size_t)NMAX * 2048];
static __device__ float  g_easum[NMAX * 32];
static __device__ float  g_deg [NMAX];
static __device__ float  g_score[TOTMAX * 4];
static __device__ unsigned g_smax[NMAX * 4];
static __device__ float  g_ssum[NMAX * 4];
static __device__ float  g_agg [NMAX * 128];
static __device__ float  g_cls [NMAX * 64];
static __device__ float  g_stats[8];
static __device__ __half g_wlh[512 * 128];
static __device__ __half g_wrh[512 * 128];
static __device__ float  g_we [512 * 32];
static __device__ __half g_w1h[2048 * 128];
static __device__ __half g_w2h[128 * 2048];
static __device__ __half g_wch[64 * 128];

// ---- helpers --------------------------------------------------------------
__device__ __forceinline__ unsigned f_enc(float f) {
    unsigned u = __float_as_uint(f);
    return (u & 0x80000000u) ? ~u : (u | 0x80000000u);
}
__device__ __forceinline__ float f_dec(unsigned k) {
    return (k & 0x80000000u) ? __uint_as_float(k ^ 0x80000000u)
                             : __uint_as_float(~k);
}
__device__ __forceinline__ unsigned tf32r(float f) {
    unsigned u; asm("cvt.rna.tf32.f32 %0, %1;" : "=r"(u) : "f"(f)); return u;
}
__device__ __forceinline__ float tf32f(float f) {
    return __uint_as_float(tf32r(f));
}
__device__ __forceinline__ uint2 pack4h(float4 v) {
    __half2 h01 = __floats2half2_rn(v.x, v.y);
    __half2 h23 = __floats2half2_rn(v.z, v.w);
    uint2 u;
    u.x = *reinterpret_cast<unsigned*>(&h01);
    u.y = *reinterpret_cast<unsigned*>(&h23);
    return u;
}
__device__ __forceinline__ void cp16(void* smem, const void* gmem) {
    unsigned s = (unsigned)__cvta_generic_to_shared(smem);
    asm volatile("cp.async.cg.shared.global [%0], [%1], 16;\n" :: "r"(s), "l"(gmem));
}
#define CP_COMMIT() asm volatile("cp.async.commit_group;\n" ::: "memory")
#define CP_WAIT1()  asm volatile("cp.async.wait_group 1;\n" ::: "memory")

// ---------------------------------------------------------------------------
__global__ void k_init(int N) {
    int i = blockIdx.x * blockDim.x + threadIdx.x;
    if (i < N * 128) g_agg[i] = 0.f;
    if (i < N * 32)  g_easum[i] = 0.f;
    if (i < N * 4)   { g_ssum[i] = 0.f; g_smax[i] = 0x00800000u; }
    if (i < N)       g_deg[i] = 0.f;
    if (i < 8)       g_stats[i] = 0.f;
}

// one launch: edge_attr->tf32, We->tf32, other weights -> fp16
__global__ void k_round_all(const float* __restrict__ ea,
                            const float* __restrict__ Wl, const float* __restrict__ Wr,
                            const float* __restrict__ We, const float* __restrict__ W1,
                            const float* __restrict__ W2, const float* __restrict__ Wc,
                            int E) {
    int i = blockIdx.x * blockDim.x + threadIdx.x;
    int nea = E * 8;
    if (i < nea) {
        float4 v = reinterpret_cast<const float4*>(ea)[i];
        v.x = tf32f(v.x); v.y = tf32f(v.y); v.z = tf32f(v.z); v.w = tf32f(v.w);
        reinterpret_cast<float4*>(g_eat)[i] = v;
        return;
    }
    i -= nea;
    if (i < 16384) {
        reinterpret_cast<uint2*>(g_wlh)[i] = pack4h(reinterpret_cast<const float4*>(Wl)[i]);
        return;
    }
    i -= 16384;
    if (i < 16384) {
        reinterpret_cast<uint2*>(g_wrh)[i] = pack4h(reinterpret_cast<const float4*>(Wr)[i]);
        return;
    }
    i -= 16384;
    if (i < 4096) {
        float4 v = reinterpret_cast<const float4*>(We)[i];
        v.x = tf32f(v.x); v.y = tf32f(v.y); v.z = tf32f(v.z); v.w = tf32f(v.w);
        reinterpret_cast<float4*>(g_we)[i] = v;
        return;
    }
    i -= 4096;
    if (i < 65536) {
        reinterpret_cast<uint2*>(g_w1h)[i] = pack4h(reinterpret_cast<const float4*>(W1)[i]);
        return;
    }
    i -= 65536;
    if (i < 65536) {
        reinterpret_cast<uint2*>(g_w2h)[i] = pack4h(reinterpret_cast<const float4*>(W2)[i]);
        return;
    }
    i -= 65536;
    if (i < 2048)
        reinterpret_cast<uint2*>(g_wch)[i] = pack4h(reinterpret_cast<const float4*>(Wc)[i]);
}

// sum + sumsq reduction
__global__ void k_reduce(const float* __restrict__ x, int n4, float* __restrict__ out) {
    float s = 0.f, ss = 0.f;
    for (int i = blockIdx.x * blockDim.x + threadIdx.x; i < n4; i += gridDim.x * blockDim.x) {
        float4 v = reinterpret_cast<const float4*>(x)[i];
        s  += v.x + v.y + v.z + v.w;
        ss += v.x * v.x + v.y * v.y + v.z * v.z + v.w * v.w;
    }
    #pragma unroll
    for (int o = 16; o > 0; o >>= 1) {
        s  += __shfl_xor_sync(0xffffffffu, s,  o);
        ss += __shfl_xor_sync(0xffffffffu, ss, o);
    }
    __shared__ float shs[8], shss[8];
    int w = threadIdx.x >> 5;
    if ((threadIdx.x & 31) == 0) { shs[w] = s; shss[w] = ss; }
    __syncthreads();
    if (threadIdx.x < 8) {
        s = shs[threadIdx.x]; ss = shss[threadIdx.x];
        #pragma unroll
        for (int o = 4; o > 0; o >>= 1) {
            s  += __shfl_xor_sync(0xffu, s,  o);
            ss += __shfl_xor_sync(0xffu, ss, o);
        }
        if (threadIdx.x == 0) { atomicAdd(out, s); atomicAdd(out + 1, ss); }
    }
}

// residual + reduction: r1 = h0(half) + agg + bias
__global__ void k_res_reduce(const float* __restrict__ gat_bias, int n4,
                             float* __restrict__ out) {
    float s = 0.f, ss = 0.f;
    const float4* b4 = reinterpret_cast<const float4*>(gat_bias);
    for (int i = blockIdx.x * blockDim.x + threadIdx.x; i < n4; i += gridDim.x * blockDim.x) {
        uint2 hu = reinterpret_cast<const uint2*>(g_h0h)[i];
        float2 a01 = __half22float2(*reinterpret_cast<__half2*>(&hu.x));
        float2 a23 = __half22float2(*reinterpret_cast<__half2*>(&hu.y));
        float4 g = reinterpret_cast<const float4*>(g_agg)[i];
        float4 b = b4[i & 31];
        float4 v = { a01.x + g.x + b.x, a01.y + g.y + b.y,
                     a23.x + g.z + b.z, a23.y + g.w + b.w };
        reinterpret_cast<float4*>(g_r1)[i] = v;
        s  += v.x + v.y + v.z + v.w;
        ss += v.x * v.x + v.y * v.y + v.z * v.z + v.w * v.w;
    }
    #pragma unroll
    for (int o = 16; o > 0; o >>= 1) {
        s  += __shfl_xor_sync(0xffffffffu, s,  o);
        ss += __shfl_xor_sync(0xffffffffu, ss, o);
    }
    __shared__ float shs[8], shss[8];
    int w = threadIdx.x >> 5;
    if ((threadIdx.x & 31) == 0) { shs[w] = s; shss[w] = ss; }
    __syncthreads();
    if (threadIdx.x < 8) {
        s = shs[threadIdx.x]; ss = shss[threadIdx.x];
        #pragma unroll
        for (int o = 4; o > 0; o >>= 1) {
            s  += __shfl_xor_sync(0xffu, s,  o);
            ss += __shfl_xor_sync(0xffu, ss, o);
        }
        if (threadIdx.x == 0) { atomicAdd(out, s); atomicAdd(out + 1, ss); }
    }
}

// graph_norm apply, float4 in. MODE 0: fp32 out; MODE 1: fp16 out.
template <int MODE>
__global__ void k_norm(const float* __restrict__ x, void* __restrict__ y,
                       const float* __restrict__ w, const float* __restrict__ b,
                       const float* __restrict__ st, int DmaskV, int n4, float invn) {
    int i = blockIdx.x * blockDim.x + threadIdx.x;
    if (i >= n4) return;
    float mu  = st[0] * invn;
    float var = st[1] * invn - mu * mu;
    float inv = 1.f / (sqrtf(fmaxf(var, 0.f)) + 1e-5f);
    int c = i & DmaskV;
    float4 xv = reinterpret_cast<const float4*>(x)[i];
    float4 wv = reinterpret_cast<const float4*>(w)[c];
    float4 bv = reinterpret_cast<const float4*>(b)[c];
    float4 r;
    r.x = (xv.x - mu) * inv * wv.x + bv.x;
    r.y = (xv.y - mu) * inv * wv.y + bv.y;
    r.z = (xv.z - mu) * inv * wv.z + bv.z;
    r.w = (xv.w - mu) * inv * wv.w + bv.w;
    if (MODE == 0) reinterpret_cast<float4*>(y)[i] = r;
    else           reinterpret_cast<uint2*>(y)[i] = pack4h(r);
}

// ---------------------------------------------------------------------------
// Unified fp16 tensor GEMM: C[M,Nn] = A[M,K] @ W[Nn,K]^T (+epilogue).
// BM=128, BKh=64 halfs, LDW=36 words (layout validated R8), 3-stage cp.async.
// EPI: 1 +bias fp32 out (+opt fused stats), 2 +bias,relu half out,
//      3 +bias,+res(half) fp32 out + fused stats.
// ---------------------------------------------------------------------------
template<int BN, int WROWS, int WCOLS, int EPI>
__global__ void __launch_bounds__(256, 2)
k_hgemm(const __half* __restrict__ A, const __half* __restrict__ W,
        const float* __restrict__ bias, const __half* __restrict__ res,
        float* __restrict__ C, float* __restrict__ stats_out, int M, int Nn, int K)
{
    constexpr int BM = 128, BKh = 64, LDW = 36, STAGES = 3;
    constexpr int MF = BM / (WROWS * 16);
    constexpr int NF = BN / (WCOLS * 8);
    constexpr int A_CP = (BM * BKh / 8) / 256;
    constexpr int B_CP = (BN * BKh / 8) / 256;

    extern __shared__ float sh[];
    unsigned* As = reinterpret_cast<unsigned*>(sh);
    unsigned* Bs = As + STAGES * BM * LDW;

    const int tid = threadIdx.x;
    const int wid = tid >> 5, lane = tid & 31;
    const int wm = wid / WCOLS, wn = wid % WCOLS;
    const int g = lane >> 2, tg = lane & 3;
    const long m0 = (long)blockIdx.y * BM;
    const int  n0 = blockIdx.x * BN;

    auto issue = [&](int stage, int kk) {
        #pragma unroll
        for (int i = 0; i < A_CP; i++) {
            int idx = tid + i * 256;
            int r = idx >> 3, c8 = idx & 7;
            cp16(&As[stage * BM * LDW + r * LDW + c8 * 4],
                 A + (m0 + r) * K + kk + c8 * 8);
        }
        #pragma unroll
        for (int i = 0; i < B_CP; i++) {
            int idx = tid + i * 256;
            int r = idx >> 3, c8 = idx & 7;
            cp16(&Bs[stage * BN * LDW + r * LDW + c8 * 4],
                 W + (long)(n0 + r) * K + kk + c8 * 8);
        }
        CP_COMMIT();
    };

    const int NT = K / BKh;
    issue(0, 0);
    if (1 < NT) issue(1, BKh); else CP_COMMIT();

    float acc[MF][NF][4] = {};
    for (int kt = 0; kt < NT; kt++) {
        CP_WAIT1();
        __syncthreads();
        if (kt + STAGES - 1 < NT)
            issue((kt + STAGES - 1) % STAGES, (kt + STAGES - 1) * BKh);
        else
            CP_COMMIT();
        const unsigned* Asb = As + (kt % STAGES) * BM * LDW;
        const unsigned* Bsb = Bs + (kt % STAGES) * BN * LDW;
        #pragma unroll
        for (int k16 = 0; k16 < 4; k16++) {
            unsigned af[MF][4], bf[NF][2];
            #pragma unroll
            for (int i = 0; i < MF; i++) {
                int r = wm * (MF * 16) + i * 16 + g;
                const unsigned* p = Asb + r * LDW + k16 * 8;
                af[i][0] = p[tg];
                af[i][1] = p[8 * LDW + tg];
                af[i][2] = p[tg + 4];
                af[i][3] = p[8 * LDW + tg + 4];
            }
            #pragma unroll
            for (int j = 0; j < NF; j++) {
                int c = wn * (NF * 8) + j * 8 + g;
                const unsigned* p = Bsb + c * LDW + k16 * 8;
                bf[j][0] = p[tg];
                bf[j][1] = p[tg + 4];
            }
            #pragma unroll
            for (int i = 0; i < MF; i++)
                #pragma unroll
                for (int j = 0; j < NF; j++) {
                    asm volatile(
                        "mma.sync.aligned.m16n8k16.row.col.f32.f16.f16.f32 "
                        "{%0,%1,%2,%3}, {%4,%5,%6,%7}, {%8,%9}, {%0,%1,%2,%3};\n"
                        : "+f"(acc[i][j][0]), "+f"(acc[i][j][1]),
                          "+f"(acc[i][j][2]), "+f"(acc[i][j][3])
                        : "r"(af[i][0]), "r"(af[i][1]), "r"(af[i][2]), "r"(af[i][3]),
                          "r"(bf[j][0]), "r"(bf[j][1]));
                }
        }
    }

    float s = 0.f, ss = 0.f;
    #pragma unroll
    for (int i = 0; i < MF; i++) {
        long mA = m0 + wm * (MF * 16) + i * 16 + g;
        long mB = mA + 8;
        #pragma unroll
        for (int j = 0; j < NF; j++) {
            int c = n0 + wn * (NF * 8) + j * 8 + tg * 2;
            float b0 = bias[c], b1 = bias[c + 1];
            float v0 = acc[i][j][0] + b0, v1 = acc[i][j][1] + b1;
            float v2 = acc[i][j][2] + b0, v3 = acc[i][j][3] + b1;
            if (EPI == 2) {      // relu -> fp16 out (hid)
                __half2 hA = __floats2half2_rn(fmaxf(v0, 0.f), fmaxf(v1, 0.f));
                __half2 hB = __floats2half2_rn(fmaxf(v2, 0.f), fmaxf(v3, 0.f));
                __half* Ch = reinterpret_cast<__half*>(C);
                *reinterpret_cast<__half2*>(Ch + mA * Nn + c) = hA;
                *reinterpret_cast<__half2*>(Ch + mB * Nn + c) = hB;
                continue;
            }
            if (EPI == 3) {
                float2 rA = __half22float2(*reinterpret_cast<const __half2*>(res + mA * Nn + c));
                float2 rB = __half22float2(*reinterpret_cast<const __half2*>(res + mB * Nn + c));
                v0 += rA.x; v1 += rA.y; v2 += rB.x; v3 += rB.y;
            }
            reinterpret_cast<float2*>(C + mA * Nn + c)[0] = make_float2(v0, v1);
            reinterpret_cast<float2*>(C + mB * Nn + c)[0] = make_float2(v2, v3);
            s  += v0 + v1 + v2 + v3;
            ss += v0 * v0 + v1 * v1 + v2 * v2 + v3 * v3;
        }
    }
    if (EPI != 2 && stats_out != nullptr) {
        #pragma unroll
        for (int o = 16; o > 0; o >>= 1) {
            s  += __shfl_xor_sync(0xffffffffu, s,  o);
            ss += __shfl_xor_sync(0xffffffffu, ss, o);
        }
        __syncthreads();
        float* red = sh;
        if (lane == 0) { red[wid] = s; red[8 + wid] = ss; }
        __syncthreads();
        if (tid == 0) {
            float ts = 0.f, tss = 0.f;
            #pragma unroll
            for (int w = 0; w < 8; w++) { ts += red[w]; tss += red[8 + w]; }
            atomicAdd(stats_out, ts);
            atomicAdd(stats_out + 1, tss);
        }
    }
}

// ---------------------------------------------------------------------------
// ef GEMM (tf32) + fused attention score epilogue.
// ---------------------------------------------------------------------------
__global__ void __launch_bounds__(256, 2)
k_gemm_score(const float* __restrict__ A, const float* __restrict__ W,
             const float* __restrict__ att, const int* __restrict__ ei,
             int ebase, int E)
{
    constexpr int BM = 128, BN = 128, BK = 32, LDA = BK + 4;
    constexpr int MF = 4, NF = 4;

    extern __shared__ float shf[];
    float* As = shf;
    float* Bs = shf + BM * LDA;
    float* srow = shf;

    const int tid = threadIdx.x;
    const int wid = tid >> 5, lane = tid & 31;
    const int wm = wid >> 2, wn = wid & 3;
    const int g = lane >> 2, tg = lane & 3;
    const long m0 = (long)blockIdx.y * BM;
    const int  n0 = blockIdx.x * BN;

    #pragma unroll
    for (int t = 0; t < 4; t++) {
        int idx = tid + t * 256;
        int r = idx >> 3, c4 = idx & 7;
        reinterpret_cast<float4*>(&As[r * LDA + c4 * 4])[0] =
            reinterpret_cast<const float4*>(A + (m0 + r) * BK)[c4];
        reinterpret_cast<float4*>(&Bs[r * LDA + c4 * 4])[0] =
            reinterpret_cast<const float4*>(W + (long)(n0 + r) * BK)[c4];
    }
    __syncthreads();

    float acc[MF][NF][4] = {};
    const unsigned* Asu = reinterpret_cast<const unsigned*>(As);
    const unsigned* Bsu = reinterpret_cast<const unsigned*>(Bs);
    #pragma unroll
    for (int k8 = 0; k8 < 4; k8++) {
        unsigned af[MF][4], bf[NF][2];
        #pragma unroll
        for (int i = 0; i < MF; i++) {
            int r = wm * 64 + i * 16 + g;
            const unsigned* p = Asu + r * LDA + k8 * 8;
            af[i][0] = p[tg];
            af[i][1] = p[8 * LDA + tg];
            af[i][2] = p[tg + 4];
            af[i][3] = p[8 * LDA + tg + 4];
        }
        #pragma unroll
        for (int j = 0; j < NF; j++) {
            int c = wn * 32 + j * 8 + g;
            const unsigned* p = Bsu + c * LDA + k8 * 8;
            bf[j][0] = p[tg];
            bf[j][1] = p[tg + 4];
        }
        #pragma unroll
        for (int i = 0; i < MF; i++)
            #pragma unroll
            for (int j = 0; j < NF; j++) {
                asm volatile(
                    "mma.sync.aligned.m16n8k8.row.col.f32.tf32.tf32.f32 "
                    "{%0,%1,%2,%3}, {%4,%5,%6,%7}, {%8,%9}, {%0,%1,%2,%3};\n"
                    : "+f"(acc[i][j][0]), "+f"(acc[i][j][1]),
                      "+f"(acc[i][j][2]), "+f"(acc[i][j][3])
                    : "r"(af[i][0]), "r"(af[i][1]), "r"(af[i][2]), "r"(af[i][3]),
                      "r"(bf[j][0]), "r"(bf[j][1]));
            }
    }

    float part[MF][2] = {};
    #pragma unroll
    for (int i = 0; i < MF; i++) {
        int rA = wm * 64 + i * 16 + g;
        int rB = rA + 8;
        int geA = ebase + (int)m0 + rA;
        int geB = ebase + (int)m0 + rB;
        int sA = (geA < E) ? ei[geA] : (geA - E);
        int dA = (geA < E) ? ei[E + geA] : (geA - E);
        int sB = (geB < E) ? ei[geB] : (geB - E);
        int dB = (geB < E) ? ei[E + geB] : (geB - E);
        const float* xlA = g_xl + (long)sA * 512 + n0;
        const float* xrA = g_xr + (long)dA * 512 + n0;
        const float* xlB = g_xl + (long)sB * 512 + n0;
        const float* xrB = g_xr + (long)dB * 512 + n0;
        #pragma unroll
        for (int j = 0; j < NF; j++) {
            int c = wn * 32 + j * 8 + tg * 2;
            float2 a0 = reinterpret_cast<const float2*>(att + n0 + c)[0];
            float2 lA = reinterpret_cast<const float2*>(xlA + c)[0];
            float2 rAv= reinterpret_cast<const float2*>(xrA + c)[0];
            float2 lB = reinterpret_cast<const float2*>(xlB + c)[0];
            float2 rBv= reinterpret_cast<const float2*>(xrB + c)[0];
            float z0 = acc[i][j][0] + lA.x + rAv.x; z0 = z0 > 0.f ? z0 : 0.2f * z0;
            float z1 = acc[i][j][1] + lA.y + rAv.y; z1 = z1 > 0.f ? z1 : 0.2f * z1;
            float z2 = acc[i][j][2] + lB.x + rBv.x; z2 = z2 > 0.f ? z2 : 0.2f * z2;
            float z3 = acc[i][j][3] + lB.y + rBv.y; z3 = z3 > 0.f ? z3 : 0.2f * z3;
            part[i][0] += z0 * a0.x + z1 * a0.y;
            part[i][1] += z2 * a0.x + z3 * a0.y;
        }
    }
    #pragma unroll
    for (int i = 0; i < MF; i++) {
        #pragma unroll
        for (int o = 1; o <= 2; o <<= 1) {
            part[i][0] += __shfl_xor_sync(0xffffffffu, part[i][0], o);
            part[i][1] += __shfl_xor_sync(0xffffffffu, part[i][1], o);
        }
    }
    __syncthreads();
    if (tg == 0) {
        #pragma unroll
        for (int i = 0; i < MF; i++) {
            int rA = wm * 64 + i * 16 + g;
            srow[wn * 128 + rA]     = part[i][0];
            srow[wn * 128 + rA + 8] = part[i][1];
        }
    }
    __syncthreads();
    if (tid < 128) {
        float s = srow[tid] + srow[128 + tid] + srow[256 + tid] + srow[384 + tid];
        int ge = ebase + (int)m0 + tid;
        int d  = (ge < E) ? ei[E + ge] : (ge - E);
        int h  = blockIdx.x;
        g_score[(long)ge * 4 + h] = s;
        atomicMax(&g_smax[d * 4 + h], f_enc(s));
    }
}

// ---- edge-side kernels ----------------------------------------------------
__global__ void k_degsum(const float* __restrict__ edge_attr,
                         const int* __restrict__ ei, int E) {
    int i = blockIdx.x * blockDim.x + threadIdx.x;
    if (i >= E * 8) return;
    int e = i >> 3, c4 = i & 7;
    int dst = ei[E + e];
    float4 v = reinterpret_cast<const float4*>(edge_attr + (long)e * 32)[c4];
    atomicAdd(reinterpret_cast<float4*>(&g_easum[dst * 32 + c4 * 4]), v);
    if (c4 == 0) atomicAdd(&g_deg[dst], 1.f);
}

__global__ void k_eamean(int N) {
    int i = blockIdx.x * blockDim.x + threadIdx.x;
    if (i >= N * 32) return;
    int nid = i >> 5;
    float d = fmaxf(g_deg[nid], 1.f);
    g_ea[i] = tf32f(g_easum[i] / d);
}

__global__ void k_exp(const int* __restrict__ ei, int E, int N) {
    int e = blockIdx.x * blockDim.x + threadIdx.x;
    if (e >= E + N) return;
    int d = (e < E) ? ei[E + e] : (e - E);
    uint4 mk = reinterpret_cast<const uint4*>(g_smax)[d];
    float4 sc = reinterpret_cast<const float4*>(g_score)[e];
    float4 ex;
    ex.x = expf(sc.x - f_dec(mk.x));
    ex.y = expf(sc.y - f_dec(mk.y));
    ex.z = expf(sc.z - f_dec(mk.z));
    ex.w = expf(sc.w - f_dec(mk.w));
    reinterpret_cast<float4*>(g_score)[e] = ex;
    atomicAdd(reinterpret_cast<float4*>(&g_ssum[d * 4]), ex);
}

__global__ void k_agg(const int* __restrict__ ei, float* __restrict__ out_alpha,
                      int E, int N, int write_out) {
    int tot = E + N;
    int e = blockIdx.x * 8 + (threadIdx.x >> 5);
    if (e >= tot) return;
    int l = threadIdx.x & 31;
    int s = (e < E) ? ei[e]     : (e - E);
    int d = (e < E) ? ei[E + e] : (e - E);
    float a0 = __fdividef(g_score[(long)e * 4 + 0], g_ssum[d * 4 + 0]);
    float a1 = __fdividef(g_score[(long)e * 4 + 1], g_ssum[d * 4 + 1]);
    float a2 = __fdividef(g_score[(long)e * 4 + 2], g_ssum[d * 4 + 2]);
    float a3 = __fdividef(g_score[(long)e * 4 + 3], g_ssum[d * 4 + 3]);
    if (write_out && l < 4) {
        float a = (l == 0) ? a0 : (l == 1) ? a1 : (l == 2) ? a2 : a3;
        out_alpha[(long)e * 4 + l] = a;
    }
    a0 *= 0.25f; a1 *= 0.25f; a2 *= 0.25f; a3 *= 0.25f;
    const float4* xl4 = reinterpret_cast<const float4*>(g_xl + (long)s * 512);
    float4 v0 = xl4[ 0 + l], v1 = xl4[32 + l], v2 = xl4[64 + l], v3 = xl4[96 + l];
    float4 r;
    r.x = a0 * v0.x + a1 * v1.x + a2 * v2.x + a3 * v3.x;
    r.y = a0 * v0.y + a1 * v1.y + a2 * v2.y + a3 * v3.y;
    r.z = a0 * v0.z + a1 * v1.z + a2 * v2.z + a3 * v3.z;
    r.w = a0 * v0.w + a1 * v1.w + a2 * v2.w + a3 * v3.w;
    atomicAdd(reinterpret_cast<float4*>(g_agg + d * 128 + 4 * l), r);
}

// ---------------------------------------------------------------------------
static inline int G(int n) { return (n + 255) / 256; }

extern "C" void kernel_launch(void* const* d_in, const int* in_sizes, int n_in,
                              void* d_out, int out_size) {
    const float* x         = (const float*)d_in[0];
    const int*   ei        = (const int*)  d_in[1];
    const float* edge_attr = (const float*)d_in[2];
    const float* Wl  = (const float*)d_in[4];
    const float* bl  = (const float*)d_in[5];
    const float* Wr  = (const float*)d_in[6];
    const float* br  = (const float*)d_in[7];
    const float* We  = (const float*)d_in[8];
    const float* att = (const float*)d_in[9];
    const float* gbn = (const float*)d_in[10];
    const float* W1  = (const float*)d_in[11];
    const float* b1  = (const float*)d_in[12];
    const float* W2  = (const float*)d_in[13];
    const float* b2  = (const float*)d_in[14];
    const float* Wc  = (const float*)d_in[15];
    const float* bc  = (const float*)d_in[16];
    const float* nw0 = (const float*)d_in[17];
    const float* nb0 = (const float*)d_in[18];
    const float* nw1 = (const float*)d_in[19];
    const float* nb1 = (const float*)d_in[20];
    const float* nw2 = (const float*)d_in[21];
    const float* nb2 = (const float*)d_in[22];
    const float* nw3 = (const float*)d_in[23];
    const float* nb3 = (const float*)d_in[24];

    int N = in_sizes[0] / 128;
    int E = in_sizes[1] / 2;
    int TOT = E + N;
    float* out = (float*)d_out;
    int write_alpha = (out_size >= N * 64 + TOT * 4) ? 1 : 0;
    float* out_alpha = out + (size_t)N * 64;

    float *r1, *r2, *ea, *eat, *cls, *stats, *we, *xl, *xr;
    __half *h0h, *n1h, *n2h, *hid16, *wlh, *wrh, *w1h, *w2h, *wch;
    cudaGetSymbolAddress((void**)&h0h,   g_h0h);
    cudaGetSymbolAddress((void**)&r1,    g_r1);
    cudaGetSymbolAddress((void**)&n1h,   g_n1h);
    cudaGetSymbolAddress((void**)&r2,    g_r2);
    cudaGetSymbolAddress((void**)&n2h,   g_n2h);
    cudaGetSymbolAddress((void**)&ea,    g_ea);
    cudaGetSymbolAddress((void**)&eat,   g_eat);
    cudaGetSymbolAddress((void**)&hid16, g_hid16);
    cudaGetSymbolAddress((void**)&cls,   g_cls);
    cudaGetSymbolAddress((void**)&stats, g_stats);
    cudaGetSymbolAddress((void**)&wlh,   g_wlh);
    cudaGetSymbolAddress((void**)&wrh,   g_wrh);
    cudaGetSymbolAddress((void**)&we,    g_we);
    cudaGetSymbolAddress((void**)&w1h,   g_w1h);
    cudaGetSymbolAddress((void**)&w2h,   g_w2h);
    cudaGetSymbolAddress((void**)&wch,   g_wch);
    cudaGetSymbolAddress((void**)&xl,    g_xl);
    cudaGetSymbolAddress((void**)&xr,    g_xr);

    const int SMH128 = 3 * (128 + 128) * 36 * 4;  // 110592 B
    const int SMH64  = 3 * (128 +  64) * 36 * 4;  // 82944 B
    const int SMSC   = (128 * 36 + 128 * 36) * 4;
    cudaFuncSetAttribute(k_hgemm<128,2,4,1>, cudaFuncAttributeMaxDynamicSharedMemorySize, SMH128);
    cudaFuncSetAttribute(k_hgemm<128,2,4,2>, cudaFuncAttributeMaxDynamicSharedMemorySize, SMH128);
    cudaFuncSetAttribute(k_hgemm<128,2,4,3>, cudaFuncAttributeMaxDynamicSharedMemorySize, SMH128);
    cudaFuncSetAttribute(k_hgemm<64,4,2,1>,  cudaFuncAttributeMaxDynamicSharedMemorySize, SMH64);
    cudaFuncSetAttribute(k_gemm_score,       cudaFuncAttributeMaxDynamicSharedMemorySize, SMSC);

    k_init<<<G(N * 128), 256>>>(N);
    int nround = E * 8 + 16384 + 16384 + 4096 + 65536 + 65536 + 2048;
    k_round_all<<<G(nround), 256>>>(edge_attr, Wl, Wr, We, W1, W2, Wc, E);
    k_reduce<<<1024, 256>>>(x, N * 128 / 4, stats + 0);
    k_norm<1><<<G(N * 32), 256>>>(x, h0h, nw0, nb0, stats + 0, 31, N * 32,
                                  1.f / (float)(N * 128));

    // GATv2 linear transforms (fp16; launch 5 = profiled)
    k_hgemm<128,2,4,1><<<dim3(4, N/128), 256, SMH128>>>(h0h, wlh, bl, nullptr, xl, nullptr, N, 512, 128);
    k_hgemm<128,2,4,1><<<dim3(4, N/128), 256, SMH128>>>(h0h, wrh, br, nullptr, xr, nullptr, N, 512, 128);

    k_degsum<<<G(E * 8), 256>>>(edge_attr, ei, E);
    k_eamean<<<G(N * 32), 256>>>(N);

    k_gemm_score<<<dim3(4, E/128), 256, SMSC>>>(eat, we, att, ei, 0, E);
    k_gemm_score<<<dim3(4, N/128), 256, SMSC>>>(ea, we, att, ei, E, E);

    k_exp<<<G(TOT), 256>>>(ei, E, N);
    k_agg<<<(TOT + 7) / 8, 256>>>(ei, out_alpha, E, N, write_alpha);

    k_res_reduce<<<1024, 256>>>(gbn, N * 128 / 4, stats + 2);
    k_norm<1><<<G(N * 32), 256>>>(r1, n1h, nw1, nb1, stats + 2, 31, N * 32,
                                  1.f / (float)(N * 128));

    // MLP (all fp16): n1 @ W1 -> hid16; hid16 @ W2 + n1 -> r2 (+fused stats)
    k_hgemm<128,2,4,2><<<dim3(16, N/128), 256, SMH128>>>(n1h, w1h, b1, nullptr,
                                                         (float*)hid16, nullptr, N, 2048, 128);
    k_hgemm<128,2,4,3><<<dim3(1, N/128), 256, SMH128>>>(hid16, w2h, b2, n1h, r2,
                                                        stats + 4, N, 128, 2048);

    k_norm<1><<<G(N * 32), 256>>>(r2, n2h, nw2, nb2, stats + 4, 31, N * 32,
                                  1.f / (float)(N * 128));

    // classifier (fp16, fused stats) + graph_norm 3
    k_hgemm<64,4,2,1><<<dim3(1, N/128), 256, SMH64>>>(n2h, wch, bc, nullptr, cls,
                                                      stats + 6, N, 64, 128);
    k_norm<0><<<G(N * 16), 256>>>(cls, out, nw3, nb3, stats + 6, 15, N * 16,
                                  1.f / (float)(N * 64));
}

// round 11
// speedup vs baseline: 6.2874x; 1.0383x over previous
#include <cuda_runtime.h>
#include <cuda_fp16.h>
#include <math.h>
#include <float.h>

// ---------------------------------------------------------------------------
// SynGNNLayer. R11: xl/xr stored fp16 (halves edge-phase L2 traffic; arrays
// now L2-resident), MLP2 split to BN=64 grid(2,128) for full SM fill.
// ---------------------------------------------------------------------------

#define NMAX 16384
#define EMAX 131072
#define TOTMAX (EMAX + NMAX)

static __device__ __half g_h0h[NMAX * 128];
static __device__ float  g_r1 [NMAX * 128];
static __device__ __half g_n1h[NMAX * 128];
static __device__ float  g_r2 [NMAX * 128];
static __device__ __half g_n2h[NMAX * 128];
static __device__ __half g_xlh[NMAX * 512];
static __device__ __half g_xrh[NMAX * 512];
static __device__ float  g_ea [NMAX * 32];
static __device__ float  g_eat[EMAX * 32];
static __device__ __half g_hid16[(size_t)NMAX * 2048];
static __device__ float  g_easum[NMAX * 32];
static __device__ float  g_deg [NMAX];
static __device__ float  g_score[TOTMAX * 4];
static __device__ unsigned g_smax[NMAX * 4];
static __device__ float  g_ssum[NMAX * 4];
static __device__ float  g_agg [NMAX * 128];
static __device__ float  g_cls [NMAX * 64];
static __device__ float  g_stats[8];
static __device__ __half g_wlh[512 * 128];
static __device__ __half g_wrh[512 * 128];
static __device__ float  g_we [512 * 32];
static __device__ __half g_w1h[2048 * 128];
static __device__ __half g_w2h[128 * 2048];
static __device__ __half g_wch[64 * 128];

// ---- helpers --------------------------------------------------------------
__device__ __forceinline__ unsigned f_enc(float f) {
    unsigned u = __float_as_uint(f);
    return (u & 0x80000000u) ? ~u : (u | 0x80000000u);
}
__device__ __forceinline__ float f_dec(unsigned k) {
    return (k & 0x80000000u) ? __uint_as_float(k ^ 0x80000000u)
                             : __uint_as_float(~k);
}
__device__ __forceinline__ unsigned tf32r(float f) {
    unsigned u; asm("cvt.rna.tf32.f32 %0, %1;" : "=r"(u) : "f"(f)); return u;
}
__device__ __forceinline__ float tf32f(float f) {
    return __uint_as_float(tf32r(f));
}
__device__ __forceinline__ uint2 pack4h(float4 v) {
    __half2 h01 = __floats2half2_rn(v.x, v.y);
    __half2 h23 = __floats2half2_rn(v.z, v.w);
    uint2 u;
    u.x = *reinterpret_cast<unsigned*>(&h01);
    u.y = *reinterpret_cast<unsigned*>(&h23);
    return u;
}
__device__ __forceinline__ void cp16(void* smem, const void* gmem) {
    unsigned s = (unsigned)__cvta_generic_to_shared(smem);
    asm volatile("cp.async.cg.shared.global [%0], [%1], 16;\n" :: "r"(s), "l"(gmem));
}
#define CP_COMMIT() asm volatile("cp.async.commit_group;\n" ::: "memory")
#define CP_WAIT1()  asm volatile("cp.async.wait_group 1;\n" ::: "memory")

// ---------------------------------------------------------------------------
__global__ void k_init(int N) {
    int i = blockIdx.x * blockDim.x + threadIdx.x;
    if (i < N * 128) g_agg[i] = 0.f;
    if (i < N * 32)  g_easum[i] = 0.f;
    if (i < N * 4)   { g_ssum[i] = 0.f; g_smax[i] = 0x00800000u; }
    if (i < N)       g_deg[i] = 0.f;
    if (i < 8)       g_stats[i] = 0.f;
}

// one launch: edge_attr->tf32, We->tf32, other weights -> fp16
__global__ void k_round_all(const float* __restrict__ ea,
                            const float* __restrict__ Wl, const float* __restrict__ Wr,
                            const float* __restrict__ We, const float* __restrict__ W1,
                            const float* __restrict__ W2, const float* __restrict__ Wc,
                            int E) {
    int i = blockIdx.x * blockDim.x + threadIdx.x;
    int nea = E * 8;
    if (i < nea) {
        float4 v = reinterpret_cast<const float4*>(ea)[i];
        v.x = tf32f(v.x); v.y = tf32f(v.y); v.z = tf32f(v.z); v.w = tf32f(v.w);
        reinterpret_cast<float4*>(g_eat)[i] = v;
        return;
    }
    i -= nea;
    if (i < 16384) {
        reinterpret_cast<uint2*>(g_wlh)[i] = pack4h(reinterpret_cast<const float4*>(Wl)[i]);
        return;
    }
    i -= 16384;
    if (i < 16384) {
        reinterpret_cast<uint2*>(g_wrh)[i] = pack4h(reinterpret_cast<const float4*>(Wr)[i]);
        return;
    }
    i -= 16384;
    if (i < 4096) {
        float4 v = reinterpret_cast<const float4*>(We)[i];
        v.x = tf32f(v.x); v.y = tf32f(v.y); v.z = tf32f(v.z); v.w = tf32f(v.w);
        reinterpret_cast<float4*>(g_we)[i] = v;
        return;
    }
    i -= 4096;
    if (i < 65536) {
        reinterpret_cast<uint2*>(g_w1h)[i] = pack4h(reinterpret_cast<const float4*>(W1)[i]);
        return;
    }
    i -= 65536;
    if (i < 65536) {
        reinterpret_cast<uint2*>(g_w2h)[i] = pack4h(reinterpret_cast<const float4*>(W2)[i]);
        return;
    }
    i -= 65536;
    if (i < 2048)
        reinterpret_cast<uint2*>(g_wch)[i] = pack4h(reinterpret_cast<const float4*>(Wc)[i]);
}

// sum + sumsq reduction
__global__ void k_reduce(const float* __restrict__ x, int n4, float* __restrict__ out) {
    float s = 0.f, ss = 0.f;
    for (int i = blockIdx.x * blockDim.x + threadIdx.x; i < n4; i += gridDim.x * blockDim.x) {
        float4 v = reinterpret_cast<const float4*>(x)[i];
        s  += v.x + v.y + v.z + v.w;
        ss += v.x * v.x + v.y * v.y + v.z * v.z + v.w * v.w;
    }
    #pragma unroll
    for (int o = 16; o > 0; o >>= 1) {
        s  += __shfl_xor_sync(0xffffffffu, s,  o);
        ss += __shfl_xor_sync(0xffffffffu, ss, o);
    }
    __shared__ float shs[8], shss[8];
    int w = threadIdx.x >> 5;
    if ((threadIdx.x & 31) == 0) { shs[w] = s; shss[w] = ss; }
    __syncthreads();
    if (threadIdx.x < 8) {
        s = shs[threadIdx.x]; ss = shss[threadIdx.x];
        #pragma unroll
        for (int o = 4; o > 0; o >>= 1) {
            s  += __shfl_xor_sync(0xffu, s,  o);
            ss += __shfl_xor_sync(0xffu, ss, o);
        }
        if (threadIdx.x == 0) { atomicAdd(out, s); atomicAdd(out + 1, ss); }
    }
}

// residual + reduction: r1 = h0(half) + agg + bias
__global__ void k_res_reduce(const float* __restrict__ gat_bias, int n4,
                             float* __restrict__ out) {
    float s = 0.f, ss = 0.f;
    const float4* b4 = reinterpret_cast<const float4*>(gat_bias);
    for (int i = blockIdx.x * blockDim.x + threadIdx.x; i < n4; i += gridDim.x * blockDim.x) {
        uint2 hu = reinterpret_cast<const uint2*>(g_h0h)[i];
        float2 a01 = __half22float2(*reinterpret_cast<__half2*>(&hu.x));
        float2 a23 = __half22float2(*reinterpret_cast<__half2*>(&hu.y));
        float4 g = reinterpret_cast<const float4*>(g_agg)[i];
        float4 b = b4[i & 31];
        float4 v = { a01.x + g.x + b.x, a01.y + g.y + b.y,
                     a23.x + g.z + b.z, a23.y + g.w + b.w };
        reinterpret_cast<float4*>(g_r1)[i] = v;
        s  += v.x + v.y + v.z + v.w;
        ss += v.x * v.x + v.y * v.y + v.z * v.z + v.w * v.w;
    }
    #pragma unroll
    for (int o = 16; o > 0; o >>= 1) {
        s  += __shfl_xor_sync(0xffffffffu, s,  o);
        ss += __shfl_xor_sync(0xffffffffu, ss, o);
    }
    __shared__ float shs[8], shss[8];
    int w = threadIdx.x >> 5;
    if ((threadIdx.x & 31) == 0) { shs[w] = s; shss[w] = ss; }
    __syncthreads();
    if (threadIdx.x < 8) {
        s = shs[threadIdx.x]; ss = shss[threadIdx.x];
        #pragma unroll
        for (int o = 4; o > 0; o >>= 1) {
            s  += __shfl_xor_sync(0xffu, s,  o);
            ss += __shfl_xor_sync(0xffu, ss, o);
        }
        if (threadIdx.x == 0) { atomicAdd(out, s); atomicAdd(out + 1, ss); }
    }
}

// graph_norm apply, float4 in. MODE 0: fp32 out; MODE 1: fp16 out.
template <int MODE>
__global__ void k_norm(const float* __restrict__ x, void* __restrict__ y,
                       const float* __restrict__ w, const float* __restrict__ b,
                       const float* __restrict__ st, int DmaskV, int n4, float invn) {
    int i = blockIdx.x * blockDim.x + threadIdx.x;
    if (i >= n4) return;
    float mu  = st[0] * invn;
    float var = st[1] * invn - mu * mu;
    float inv = 1.f / (sqrtf(fmaxf(var, 0.f)) + 1e-5f);
    int c = i & DmaskV;
    float4 xv = reinterpret_cast<const float4*>(x)[i];
    float4 wv = reinterpret_cast<const float4*>(w)[c];
    float4 bv = reinterpret_cast<const float4*>(b)[c];
    float4 r;
    r.x = (xv.x - mu) * inv * wv.x + bv.x;
    r.y = (xv.y - mu) * inv * wv.y + bv.y;
    r.z = (xv.z - mu) * inv * wv.z + bv.z;
    r.w = (xv.w - mu) * inv * wv.w + bv.w;
    if (MODE == 0) reinterpret_cast<float4*>(y)[i] = r;
    else           reinterpret_cast<uint2*>(y)[i] = pack4h(r);
}

// ---------------------------------------------------------------------------
// Unified fp16 tensor GEMM: C[M,Nn] = A[M,K] @ W[Nn,K]^T (+epilogue).
// EPI: 1 +bias fp32 out (+opt fused stats), 2 +bias,relu half out,
//      3 +bias,+res(half) fp32 out + fused stats, 4 +bias half out.
// ---------------------------------------------------------------------------
template<int BN, int WROWS, int WCOLS, int EPI>
__global__ void __launch_bounds__(256, 2)
k_hgemm(const __half* __restrict__ A, const __half* __restrict__ W,
        const float* __restrict__ bias, const __half* __restrict__ res,
        float* __restrict__ C, float* __restrict__ stats_out, int M, int Nn, int K)
{
    constexpr int BM = 128, BKh = 64, LDW = 36, STAGES = 3;
    constexpr int MF = BM / (WROWS * 16);
    constexpr int NF = BN / (WCOLS * 8);
    constexpr int A_CP = (BM * BKh / 8) / 256;
    constexpr int B_CP = (BN * BKh / 8) / 256;

    extern __shared__ float sh[];
    unsigned* As = reinterpret_cast<unsigned*>(sh);
    unsigned* Bs = As + STAGES * BM * LDW;

    const int tid = threadIdx.x;
    const int wid = tid >> 5, lane = tid & 31;
    const int wm = wid / WCOLS, wn = wid % WCOLS;
    const int g = lane >> 2, tg = lane & 3;
    const long m0 = (long)blockIdx.y * BM;
    const int  n0 = blockIdx.x * BN;

    auto issue = [&](int stage, int kk) {
        #pragma unroll
        for (int i = 0; i < A_CP; i++) {
            int idx = tid + i * 256;
            int r = idx >> 3, c8 = idx & 7;
            cp16(&As[stage * BM * LDW + r * LDW + c8 * 4],
                 A + (m0 + r) * K + kk + c8 * 8);
        }
        #pragma unroll
        for (int i = 0; i < B_CP; i++) {
            int idx = tid + i * 256;
            int r = idx >> 3, c8 = idx & 7;
            cp16(&Bs[stage * BN * LDW + r * LDW + c8 * 4],
                 W + (long)(n0 + r) * K + kk + c8 * 8);
        }
        CP_COMMIT();
    };

    const int NT = K / BKh;
    issue(0, 0);
    if (1 < NT) issue(1, BKh); else CP_COMMIT();

    float acc[MF][NF][4] = {};
    for (int kt = 0; kt < NT; kt++) {
        CP_WAIT1();
        __syncthreads();
        if (kt + STAGES - 1 < NT)
            issue((kt + STAGES - 1) % STAGES, (kt + STAGES - 1) * BKh);
        else
            CP_COMMIT();
        const unsigned* Asb = As + (kt % STAGES) * BM * LDW;
        const unsigned* Bsb = Bs + (kt % STAGES) * BN * LDW;
        #pragma unroll
        for (int k16 = 0; k16 < 4; k16++) {
            unsigned af[MF][4], bf[NF][2];
            #pragma unroll
            for (int i = 0; i < MF; i++) {
                int r = wm * (MF * 16) + i * 16 + g;
                const unsigned* p = Asb + r * LDW + k16 * 8;
                af[i][0] = p[tg];
                af[i][1] = p[8 * LDW + tg];
                af[i][2] = p[tg + 4];
                af[i][3] = p[8 * LDW + tg + 4];
            }
            #pragma unroll
            for (int j = 0; j < NF; j++) {
                int c = wn * (NF * 8) + j * 8 + g;
                const unsigned* p = Bsb + c * LDW + k16 * 8;
                bf[j][0] = p[tg];
                bf[j][1] = p[tg + 4];
            }
            #pragma unroll
            for (int i = 0; i < MF; i++)
                #pragma unroll
                for (int j = 0; j < NF; j++) {
                    asm volatile(
                        "mma.sync.aligned.m16n8k16.row.col.f32.f16.f16.f32 "
                        "{%0,%1,%2,%3}, {%4,%5,%6,%7}, {%8,%9}, {%0,%1,%2,%3};\n"
                        : "+f"(acc[i][j][0]), "+f"(acc[i][j][1]),
                          "+f"(acc[i][j][2]), "+f"(acc[i][j][3])
                        : "r"(af[i][0]), "r"(af[i][1]), "r"(af[i][2]), "r"(af[i][3]),
                          "r"(bf[j][0]), "r"(bf[j][1]));
                }
        }
    }

    float s = 0.f, ss = 0.f;
    #pragma unroll
    for (int i = 0; i < MF; i++) {
        long mA = m0 + wm * (MF * 16) + i * 16 + g;
        long mB = mA + 8;
        #pragma unroll
        for (int j = 0; j < NF; j++) {
            int c = n0 + wn * (NF * 8) + j * 8 + tg * 2;
            float b0 = bias[c], b1 = bias[c + 1];
            float v0 = acc[i][j][0] + b0, v1 = acc[i][j][1] + b1;
            float v2 = acc[i][j][2] + b0, v3 = acc[i][j][3] + b1;
            if (EPI == 2 || EPI == 4) {     // half out (hid: relu; xl/xr: plain)
                if (EPI == 2) {
                    v0 = fmaxf(v0, 0.f); v1 = fmaxf(v1, 0.f);
                    v2 = fmaxf(v2, 0.f); v3 = fmaxf(v3, 0.f);
                }
                __half2 hA = __floats2half2_rn(v0, v1);
                __half2 hB = __floats2half2_rn(v2, v3);
                __half* Ch = reinterpret_cast<__half*>(C);
                *reinterpret_cast<__half2*>(Ch + mA * Nn + c) = hA;
                *reinterpret_cast<__half2*>(Ch + mB * Nn + c) = hB;
                continue;
            }
            if (EPI == 3) {
                float2 rA = __half22float2(*reinterpret_cast<const __half2*>(res + mA * Nn + c));
                float2 rB = __half22float2(*reinterpret_cast<const __half2*>(res + mB * Nn + c));
                v0 += rA.x; v1 += rA.y; v2 += rB.x; v3 += rB.y;
            }
            reinterpret_cast<float2*>(C + mA * Nn + c)[0] = make_float2(v0, v1);
            reinterpret_cast<float2*>(C + mB * Nn + c)[0] = make_float2(v2, v3);
            s  += v0 + v1 + v2 + v3;
            ss += v0 * v0 + v1 * v1 + v2 * v2 + v3 * v3;
        }
    }
    if (EPI != 2 && EPI != 4 && stats_out != nullptr) {
        #pragma unroll
        for (int o = 16; o > 0; o >>= 1) {
            s  += __shfl_xor_sync(0xffffffffu, s,  o);
            ss += __shfl_xor_sync(0xffffffffu, ss, o);
        }
        __syncthreads();
        float* red = sh;
        if (lane == 0) { red[wid] = s; red[8 + wid] = ss; }
        __syncthreads();
        if (tid == 0) {
            float ts = 0.f, tss = 0.f;
            #pragma unroll
            for (int w = 0; w < 8; w++) { ts += red[w]; tss += red[8 + w]; }
            atomicAdd(stats_out, ts);
            atomicAdd(stats_out + 1, tss);
        }
    }
}

// ---------------------------------------------------------------------------
// ef GEMM (tf32) + fused attention score epilogue (xl/xr now fp16).
// ---------------------------------------------------------------------------
__global__ void __launch_bounds__(256, 2)
k_gemm_score(const float* __restrict__ A, const float* __restrict__ W,
             const float* __restrict__ att, const int* __restrict__ ei,
             int ebase, int E)
{
    constexpr int BM = 128, BN = 128, BK = 32, LDA = BK + 4;
    constexpr int MF = 4, NF = 4;

    extern __shared__ float shf[];
    float* As = shf;
    float* Bs = shf + BM * LDA;
    float* srow = shf;

    const int tid = threadIdx.x;
    const int wid = tid >> 5, lane = tid & 31;
    const int wm = wid >> 2, wn = wid & 3;
    const int g = lane >> 2, tg = lane & 3;
    const long m0 = (long)blockIdx.y * BM;
    const int  n0 = blockIdx.x * BN;

    #pragma unroll
    for (int t = 0; t < 4; t++) {
        int idx = tid + t * 256;
        int r = idx >> 3, c4 = idx & 7;
        reinterpret_cast<float4*>(&As[r * LDA + c4 * 4])[0] =
            reinterpret_cast<const float4*>(A + (m0 + r) * BK)[c4];
        reinterpret_cast<float4*>(&Bs[r * LDA + c4 * 4])[0] =
            reinterpret_cast<const float4*>(W + (long)(n0 + r) * BK)[c4];
    }
    __syncthreads();

    float acc[MF][NF][4] = {};
    const unsigned* Asu = reinterpret_cast<const unsigned*>(As);
    const unsigned* Bsu = reinterpret_cast<const unsigned*>(Bs);
    #pragma unroll
    for (int k8 = 0; k8 < 4; k8++) {
        unsigned af[MF][4], bf[NF][2];
        #pragma unroll
        for (int i = 0; i < MF; i++) {
            int r = wm * 64 + i * 16 + g;
            const unsigned* p = Asu + r * LDA + k8 * 8;
            af[i][0] = p[tg];
            af[i][1] = p[8 * LDA + tg];
            af[i][2] = p[tg + 4];
            af[i][3] = p[8 * LDA + tg + 4];
        }
        #pragma unroll
        for (int j = 0; j < NF; j++) {
            int c = wn * 32 + j * 8 + g;
            const unsigned* p = Bsu + c * LDA + k8 * 8;
            bf[j][0] = p[tg];
            bf[j][1] = p[tg + 4];
        }
        #pragma unroll
        for (int i = 0; i < MF; i++)
            #pragma unroll
            for (int j = 0; j < NF; j++) {
                asm volatile(
                    "mma.sync.aligned.m16n8k8.row.col.f32.tf32.tf32.f32 "
                    "{%0,%1,%2,%3}, {%4,%5,%6,%7}, {%8,%9}, {%0,%1,%2,%3};\n"
                    : "+f"(acc[i][j][0]), "+f"(acc[i][j][1]),
                      "+f"(acc[i][j][2]), "+f"(acc[i][j][3])
                    : "r"(af[i][0]), "r"(af[i][1]), "r"(af[i][2]), "r"(af[i][3]),
                      "r"(bf[j][0]), "r"(bf[j][1]));
            }
    }

    float part[MF][2] = {};
    #pragma unroll
    for (int i = 0; i < MF; i++) {
        int rA = wm * 64 + i * 16 + g;
        int rB = rA + 8;
        int geA = ebase + (int)m0 + rA;
        int geB = ebase + (int)m0 + rB;
        int sA = (geA < E) ? ei[geA] : (geA - E);
        int dA = (geA < E) ? ei[E + geA] : (geA - E);
        int sB = (geB < E) ? ei[geB] : (geB - E);
        int dB = (geB < E) ? ei[E + geB] : (geB - E);
        const __half* xlA = g_xlh + (long)sA * 512 + n0;
        const __half* xrA = g_xrh + (long)dA * 512 + n0;
        const __half* xlB = g_xlh + (long)sB * 512 + n0;
        const __half* xrB = g_xrh + (long)dB * 512 + n0;
        #pragma unroll
        for (int j = 0; j < NF; j++) {
            int c = wn * 32 + j * 8 + tg * 2;
            float2 a0 = reinterpret_cast<const float2*>(att + n0 + c)[0];
            float2 lA = __half22float2(*reinterpret_cast<const __half2*>(xlA + c));
            float2 rAv= __half22float2(*reinterpret_cast<const __half2*>(xrA + c));
            float2 lB = __half22float2(*reinterpret_cast<const __half2*>(xlB + c));
            float2 rBv= __half22float2(*reinterpret_cast<const __half2*>(xrB + c));
            float z0 = acc[i][j][0] + lA.x + rAv.x; z0 = z0 > 0.f ? z0 : 0.2f * z0;
            float z1 = acc[i][j][1] + lA.y + rAv.y; z1 = z1 > 0.f ? z1 : 0.2f * z1;
            float z2 = acc[i][j][2] + lB.x + rBv.x; z2 = z2 > 0.f ? z2 : 0.2f * z2;
            float z3 = acc[i][j][3] + lB.y + rBv.y; z3 = z3 > 0.f ? z3 : 0.2f * z3;
            part[i][0] += z0 * a0.x + z1 * a0.y;
            part[i][1] += z2 * a0.x + z3 * a0.y;
        }
    }
    #pragma unroll
    for (int i = 0; i < MF; i++) {
        #pragma unroll
        for (int o = 1; o <= 2; o <<= 1) {
            part[i][0] += __shfl_xor_sync(0xffffffffu, part[i][0], o);
            part[i][1] += __shfl_xor_sync(0xffffffffu, part[i][1], o);
        }
    }
    __syncthreads();
    if (tg == 0) {
        #pragma unroll
        for (int i = 0; i < MF; i++) {
            int rA = wm * 64 + i * 16 + g;
            srow[wn * 128 + rA]     = part[i][0];
            srow[wn * 128 + rA + 8] = part[i][1];
        }
    }
    __syncthreads();
    if (tid < 128) {
        float s = srow[tid] + srow[128 + tid] + srow[256 + tid] + srow[384 + tid];
        int ge = ebase + (int)m0 + tid;
        int d  = (ge < E) ? ei[E + ge] : (ge - E);
        int h  = blockIdx.x;
        g_score[(long)ge * 4 + h] = s;
        atomicMax(&g_smax[d * 4 + h], f_enc(s));
    }
}

// ---- edge-side kernels ----------------------------------------------------
__global__ void k_degsum(const float* __restrict__ edge_attr,
                         const int* __restrict__ ei, int E) {
    int i = blockIdx.x * blockDim.x + threadIdx.x;
    if (i >= E * 8) return;
    int e = i >> 3, c4 = i & 7;
    int dst = ei[E + e];
    float4 v = reinterpret_cast<const float4*>(edge_attr + (long)e * 32)[c4];
    atomicAdd(reinterpret_cast<float4*>(&g_easum[dst * 32 + c4 * 4]), v);
    if (c4 == 0) atomicAdd(&g_deg[dst], 1.f);
}

__global__ void k_eamean(int N) {
    int i = blockIdx.x * blockDim.x + threadIdx.x;
    if (i >= N * 32) return;
    int nid = i >> 5;
    float d = fmaxf(g_deg[nid], 1.f);
    g_ea[i] = tf32f(g_easum[i] / d);
}

__global__ void k_exp(const int* __restrict__ ei, int E, int N) {
    int e = blockIdx.x * blockDim.x + threadIdx.x;
    if (e >= E + N) return;
    int d = (e < E) ? ei[E + e] : (e - E);
    uint4 mk = reinterpret_cast<const uint4*>(g_smax)[d];
    float4 sc = reinterpret_cast<const float4*>(g_score)[e];
    float4 ex;
    ex.x = expf(sc.x - f_dec(mk.x));
    ex.y = expf(sc.y - f_dec(mk.y));
    ex.z = expf(sc.z - f_dec(mk.z));
    ex.w = expf(sc.w - f_dec(mk.w));
    reinterpret_cast<float4*>(g_score)[e] = ex;
    atomicAdd(reinterpret_cast<float4*>(&g_ssum[d * 4]), ex);
}

__global__ void k_agg(const int* __restrict__ ei, float* __restrict__ out_alpha,
                      int E, int N, int write_out) {
    int tot = E + N;
    int e = blockIdx.x * 8 + (threadIdx.x >> 5);
    if (e >= tot) return;
    int l = threadIdx.x & 31;
    int s = (e < E) ? ei[e]     : (e - E);
    int d = (e < E) ? ei[E + e] : (e - E);
    float a0 = __fdividef(g_score[(long)e * 4 + 0], g_ssum[d * 4 + 0]);
    float a1 = __fdividef(g_score[(long)e * 4 + 1], g_ssum[d * 4 + 1]);
    float a2 = __fdividef(g_score[(long)e * 4 + 2], g_ssum[d * 4 + 2]);
    float a3 = __fdividef(g_score[(long)e * 4 + 3], g_ssum[d * 4 + 3]);
    if (write_out && l < 4) {
        float a = (l == 0) ? a0 : (l == 1) ? a1 : (l == 2) ? a2 : a3;
        out_alpha[(long)e * 4 + l] = a;
    }
    a0 *= 0.25f; a1 *= 0.25f; a2 *= 0.25f; a3 *= 0.25f;
    // fp16 xl: lane l covers channels 4l..4l+3 of each head block
    const uint2* xl2 = reinterpret_cast<const uint2*>(g_xlh + (long)s * 512);
    float4 r = {0.f, 0.f, 0.f, 0.f};
    float av[4] = {a0, a1, a2, a3};
    #pragma unroll
    for (int h = 0; h < 4; h++) {
        uint2 hu = xl2[h * 32 + l];
        float2 v01 = __half22float2(*reinterpret_cast<__half2*>(&hu.x));
        float2 v23 = __half22float2(*reinterpret_cast<__half2*>(&hu.y));
        r.x += av[h] * v01.x;
        r.y += av[h] * v01.y;
        r.z += av[h] * v23.x;
        r.w += av[h] * v23.y;
    }
    atomicAdd(reinterpret_cast<float4*>(g_agg + d * 128 + 4 * l), r);
}

// ---------------------------------------------------------------------------
static inline int G(int n) { return (n + 255) / 256; }

extern "C" void kernel_launch(void* const* d_in, const int* in_sizes, int n_in,
                              void* d_out, int out_size) {
    const float* x         = (const float*)d_in[0];
    const int*   ei        = (const int*)  d_in[1];
    const float* edge_attr = (const float*)d_in[2];
    const float* Wl  = (const float*)d_in[4];
    const float* bl  = (const float*)d_in[5];
    const float* Wr  = (const float*)d_in[6];
    const float* br  = (const float*)d_in[7];
    const float* We  = (const float*)d_in[8];
    const float* att = (const float*)d_in[9];
    const float* gbn = (const float*)d_in[10];
    const float* W1  = (const float*)d_in[11];
    const float* b1  = (const float*)d_in[12];
    const float* W2  = (const float*)d_in[13];
    const float* b2  = (const float*)d_in[14];
    const float* Wc  = (const float*)d_in[15];
    const float* bc  = (const float*)d_in[16];
    const float* nw0 = (const float*)d_in[17];
    const float* nb0 = (const float*)d_in[18];
    const float* nw1 = (const float*)d_in[19];
    const float* nb1 = (const float*)d_in[20];
    const float* nw2 = (const float*)d_in[21];
    const float* nb2 = (const float*)d_in[22];
    const float* nw3 = (const float*)d_in[23];
    const float* nb3 = (const float*)d_in[24];

    int N = in_sizes[0] / 128;
    int E = in_sizes[1] / 2;
    int TOT = E + N;
    float* out = (float*)d_out;
    int write_alpha = (out_size >= N * 64 + TOT * 4) ? 1 : 0;
    float* out_alpha = out + (size_t)N * 64;

    float *r1, *r2, *ea, *eat, *cls, *stats, *we;
    __half *h0h, *n1h, *n2h, *hid16, *wlh, *wrh, *w1h, *w2h, *wch, *xlh, *xrh;
    cudaGetSymbolAddress((void**)&h0h,   g_h0h);
    cudaGetSymbolAddress((void**)&r1,    g_r1);
    cudaGetSymbolAddress((void**)&n1h,   g_n1h);
    cudaGetSymbolAddress((void**)&r2,    g_r2);
    cudaGetSymbolAddress((void**)&n2h,   g_n2h);
    cudaGetSymbolAddress((void**)&ea,    g_ea);
    cudaGetSymbolAddress((void**)&eat,   g_eat);
    cudaGetSymbolAddress((void**)&hid16, g_hid16);
    cudaGetSymbolAddress((void**)&cls,   g_cls);
    cudaGetSymbolAddress((void**)&stats, g_stats);
    cudaGetSymbolAddress((void**)&wlh,   g_wlh);
    cudaGetSymbolAddress((void**)&wrh,   g_wrh);
    cudaGetSymbolAddress((void**)&we,    g_we);
    cudaGetSymbolAddress((void**)&w1h,   g_w1h);
    cudaGetSymbolAddress((void**)&w2h,   g_w2h);
    cudaGetSymbolAddress((void**)&wch,   g_wch);
    cudaGetSymbolAddress((void**)&xlh,   g_xlh);
    cudaGetSymbolAddress((void**)&xrh,   g_xrh);

    const int SMH128 = 3 * (128 + 128) * 36 * 4;  // 110592 B
    const int SMH64  = 3 * (128 +  64) * 36 * 4;  // 82944 B
    const int SMSC   = (128 * 36 + 128 * 36) * 4;
    cudaFuncSetAttribute(k_hgemm<128,2,4,4>, cudaFuncAttributeMaxDynamicSharedMemorySize, SMH128);
    cudaFuncSetAttribute(k_hgemm<128,2,4,2>, cudaFuncAttributeMaxDynamicSharedMemorySize, SMH128);
    cudaFuncSetAttribute(k_hgemm<64,4,2,3>,  cudaFuncAttributeMaxDynamicSharedMemorySize, SMH64);
    cudaFuncSetAttribute(k_hgemm<64,4,2,1>,  cudaFuncAttributeMaxDynamicSharedMemorySize, SMH64);
    cudaFuncSetAttribute(k_gemm_score,       cudaFuncAttributeMaxDynamicSharedMemorySize, SMSC);

    k_init<<<G(N * 128), 256>>>(N);
    int nround = E * 8 + 16384 + 16384 + 4096 + 65536 + 65536 + 2048;
    k_round_all<<<G(nround), 256>>>(edge_attr, Wl, Wr, We, W1, W2, Wc, E);
    k_reduce<<<1024, 256>>>(x, N * 128 / 4, stats + 0);
    k_norm<1><<<G(N * 32), 256>>>(x, h0h, nw0, nb0, stats + 0, 31, N * 32,
                                  1.f / (float)(N * 128));

    // GATv2 linear transforms (fp16 in AND out; launch 5 = profiled)
    k_hgemm<128,2,4,4><<<dim3(4, N/128), 256, SMH128>>>(h0h, wlh, bl, nullptr, (float*)xlh, nullptr, N, 512, 128);
    k_hgemm<128,2,4,4><<<dim3(4, N/128), 256, SMH128>>>(h0h, wrh, br, nullptr, (float*)xrh, nullptr, N, 512, 128);

    k_degsum<<<G(E * 8), 256>>>(edge_attr, ei, E);
    k_eamean<<<G(N * 32), 256>>>(N);

    k_gemm_score<<<dim3(4, E/128), 256, SMSC>>>(eat, we, att, ei, 0, E);
    k_gemm_score<<<dim3(4, N/128), 256, SMSC>>>(ea, we, att, ei, E, E);

    k_exp<<<G(TOT), 256>>>(ei, E, N);
    k_agg<<<(TOT + 7) / 8, 256>>>(ei, out_alpha, E, N, write_alpha);

    k_res_reduce<<<1024, 256>>>(gbn, N * 128 / 4, stats + 2);
    k_norm<1><<<G(N * 32), 256>>>(r1, n1h, nw1, nb1, stats + 2, 31, N * 32,
                                  1.f / (float)(N * 128));

    // MLP: fp16 GEMMs; MLP2 split BN=64 -> 256 CTAs for full SM fill
    k_hgemm<128,2,4,2><<<dim3(16, N/128), 256, SMH128>>>(n1h, w1h, b1, nullptr,
                                                         (float*)hid16, nullptr, N, 2048, 128);
    k_hgemm<64,4,2,3><<<dim3(2, N/128), 256, SMH64>>>(hid16, w2h, b2, n1h, r2,
                                                      stats + 4, N, 128, 2048);

    k_norm<1><<<G(N * 32), 256>>>(r2, n2h, nw2, nb2, stats + 4, 31, N * 32,
                                  1.f / (float)(N * 128));

    // classifier (fp16, fused stats) + graph_norm 3
    k_hgemm<64,4,2,1><<<dim3(1, N/128), 256, SMH64>>>(n2h, wch, bc, nullptr, cls,
                                                      stats + 6, N, 64, 128);
    k_norm<0><<<G(N * 16), 256>>>(cls, out, nw3, nb3, stats + 6, 15, N * 16,
                                  1.f / (float)(N * 64));
}

// round 13
// speedup vs baseline: 6.6251x; 1.0537x over previous
#include <cuda_runtime.h>
#include <cuda_fp16.h>
#include <math.h>
#include <float.h>

// ---------------------------------------------------------------------------
// SynGNNLayer. R12: fused MLP kernel (GEMM1 C-fragments repacked in registers
// as GEMM2 A-fragments; hid never touches DRAM). Rest as R11.
// ---------------------------------------------------------------------------

#define NMAX 16384
#define EMAX 131072
#define TOTMAX (EMAX + NMAX)

static __device__ __half g_h0h[NMAX * 128];
static __device__ float  g_r1 [NMAX * 128];
static __device__ __half g_n1h[NMAX * 128];
static __device__ float  g_r2 [NMAX * 128];
static __device__ __half g_n2h[NMAX * 128];
static __device__ __half g_xlh[NMAX * 512];
static __device__ __half g_xrh[NMAX * 512];
static __device__ float  g_ea [NMAX * 32];
static __device__ float  g_eat[EMAX * 32];
static __device__ float  g_easum[NMAX * 32];
static __device__ float  g_deg [NMAX];
static __device__ float  g_score[TOTMAX * 4];
static __device__ unsigned g_smax[NMAX * 4];
static __device__ float  g_ssum[NMAX * 4];
static __device__ float  g_agg [NMAX * 128];
static __device__ float  g_cls [NMAX * 64];
static __device__ float  g_stats[8];
static __device__ __half g_wlh[512 * 128];
static __device__ __half g_wrh[512 * 128];
static __device__ float  g_we [512 * 32];
static __device__ __half g_w1h[2048 * 128];
static __device__ __half g_w2h[128 * 2048];
static __device__ __half g_wch[64 * 128];

// ---- helpers --------------------------------------------------------------
__device__ __forceinline__ unsigned f_enc(float f) {
    unsigned u = __float_as_uint(f);
    return (u & 0x80000000u) ? ~u : (u | 0x80000000u);
}
__device__ __forceinline__ float f_dec(unsigned k) {
    return (k & 0x80000000u) ? __uint_as_float(k ^ 0x80000000u)
                             : __uint_as_float(~k);
}
__device__ __forceinline__ unsigned tf32r(float f) {
    unsigned u; asm("cvt.rna.tf32.f32 %0, %1;" : "=r"(u) : "f"(f)); return u;
}
__device__ __forceinline__ float tf32f(float f) {
    return __uint_as_float(tf32r(f));
}
__device__ __forceinline__ uint2 pack4h(float4 v) {
    __half2 h01 = __floats2half2_rn(v.x, v.y);
    __half2 h23 = __floats2half2_rn(v.z, v.w);
    uint2 u;
    u.x = *reinterpret_cast<unsigned*>(&h01);
    u.y = *reinterpret_cast<unsigned*>(&h23);
    return u;
}
__device__ __forceinline__ unsigned packh2(float a, float b) {
    __half2 h = __floats2half2_rn(a, b);
    return *reinterpret_cast<unsigned*>(&h);
}
__device__ __forceinline__ void cp16(void* smem, const void* gmem) {
    unsigned s = (unsigned)__cvta_generic_to_shared(smem);
    asm volatile("cp.async.cg.shared.global [%0], [%1], 16;\n" :: "r"(s), "l"(gmem));
}
#define CP_COMMIT() asm volatile("cp.async.commit_group;\n" ::: "memory")
#define CP_WAIT1()  asm volatile("cp.async.wait_group 1;\n" ::: "memory")
#define MMA_F16(acc, a0,a1,a2,a3, b0,b1) \
    asm volatile( \
        "mma.sync.aligned.m16n8k16.row.col.f32.f16.f16.f32 " \
        "{%0,%1,%2,%3}, {%4,%5,%6,%7}, {%8,%9}, {%0,%1,%2,%3};\n" \
        : "+f"(acc[0]), "+f"(acc[1]), "+f"(acc[2]), "+f"(acc[3]) \
        : "r"(a0), "r"(a1), "r"(a2), "r"(a3), "r"(b0), "r"(b1))

// ---------------------------------------------------------------------------
__global__ void k_init(int N) {
    int i = blockIdx.x * blockDim.x + threadIdx.x;
    if (i < N * 128) g_agg[i] = 0.f;
    if (i < N * 32)  g_easum[i] = 0.f;
    if (i < N * 4)   { g_ssum[i] = 0.f; g_smax[i] = 0x00800000u; }
    if (i < N)       g_deg[i] = 0.f;
    if (i < 8)       g_stats[i] = 0.f;
}

__global__ void k_round_all(const float* __restrict__ ea,
                            const float* __restrict__ Wl, const float* __restrict__ Wr,
                            const float* __restrict__ We, const float* __restrict__ W1,
                            const float* __restrict__ W2, const float* __restrict__ Wc,
                            int E) {
    int i = blockIdx.x * blockDim.x + threadIdx.x;
    int nea = E * 8;
    if (i < nea) {
        float4 v = reinterpret_cast<const float4*>(ea)[i];
        v.x = tf32f(v.x); v.y = tf32f(v.y); v.z = tf32f(v.z); v.w = tf32f(v.w);
        reinterpret_cast<float4*>(g_eat)[i] = v;
        return;
    }
    i -= nea;
    if (i < 16384) {
        reinterpret_cast<uint2*>(g_wlh)[i] = pack4h(reinterpret_cast<const float4*>(Wl)[i]);
        return;
    }
    i -= 16384;
    if (i < 16384) {
        reinterpret_cast<uint2*>(g_wrh)[i] = pack4h(reinterpret_cast<const float4*>(Wr)[i]);
        return;
    }
    i -= 16384;
    if (i < 4096) {
        float4 v = reinterpret_cast<const float4*>(We)[i];
        v.x = tf32f(v.x); v.y = tf32f(v.y); v.z = tf32f(v.z); v.w = tf32f(v.w);
        reinterpret_cast<float4*>(g_we)[i] = v;
        return;
    }
    i -= 4096;
    if (i < 65536) {
        reinterpret_cast<uint2*>(g_w1h)[i] = pack4h(reinterpret_cast<const float4*>(W1)[i]);
        return;
    }
    i -= 65536;
    if (i < 65536) {
        reinterpret_cast<uint2*>(g_w2h)[i] = pack4h(reinterpret_cast<const float4*>(W2)[i]);
        return;
    }
    i -= 65536;
    if (i < 2048)
        reinterpret_cast<uint2*>(g_wch)[i] = pack4h(reinterpret_cast<const float4*>(Wc)[i]);
}

__global__ void k_reduce(const float* __restrict__ x, int n4, float* __restrict__ out) {
    float s = 0.f, ss = 0.f;
    for (int i = blockIdx.x * blockDim.x + threadIdx.x; i < n4; i += gridDim.x * blockDim.x) {
        float4 v = reinterpret_cast<const float4*>(x)[i];
        s  += v.x + v.y + v.z + v.w;
        ss += v.x * v.x + v.y * v.y + v.z * v.z + v.w * v.w;
    }
    #pragma unroll
    for (int o = 16; o > 0; o >>= 1) {
        s  += __shfl_xor_sync(0xffffffffu, s,  o);
        ss += __shfl_xor_sync(0xffffffffu, ss, o);
    }
    __shared__ float shs[8], shss[8];
    int w = threadIdx.x >> 5;
    if ((threadIdx.x & 31) == 0) { shs[w] = s; shss[w] = ss; }
    __syncthreads();
    if (threadIdx.x < 8) {
        s = shs[threadIdx.x]; ss = shss[threadIdx.x];
        #pragma unroll
        for (int o = 4; o > 0; o >>= 1) {
            s  += __shfl_xor_sync(0xffu, s,  o);
            ss += __shfl_xor_sync(0xffu, ss, o);
        }
        if (threadIdx.x == 0) { atomicAdd(out, s); atomicAdd(out + 1, ss); }
    }
}

__global__ void k_res_reduce(const float* __restrict__ gat_bias, int n4,
                             float* __restrict__ out) {
    float s = 0.f, ss = 0.f;
    const float4* b4 = reinterpret_cast<const float4*>(gat_bias);
    for (int i = blockIdx.x * blockDim.x + threadIdx.x; i < n4; i += gridDim.x * blockDim.x) {
        uint2 hu = reinterpret_cast<const uint2*>(g_h0h)[i];
        float2 a01 = __half22float2(*reinterpret_cast<__half2*>(&hu.x));
        float2 a23 = __half22float2(*reinterpret_cast<__half2*>(&hu.y));
        float4 g = reinterpret_cast<const float4*>(g_agg)[i];
        float4 b = b4[i & 31];
        float4 v = { a01.x + g.x + b.x, a01.y + g.y + b.y,
                     a23.x + g.z + b.z, a23.y + g.w + b.w };
        reinterpret_cast<float4*>(g_r1)[i] = v;
        s  += v.x + v.y + v.z + v.w;
        ss += v.x * v.x + v.y * v.y + v.z * v.z + v.w * v.w;
    }
    #pragma unroll
    for (int o = 16; o > 0; o >>= 1) {
        s  += __shfl_xor_sync(0xffffffffu, s,  o);
        ss += __shfl_xor_sync(0xffffffffu, ss, o);
    }
    __shared__ float shs[8], shss[8];
    int w = threadIdx.x >> 5;
    if ((threadIdx.x & 31) == 0) { shs[w] = s; shss[w] = ss; }
    __syncthreads();
    if (threadIdx.x < 8) {
        s = shs[threadIdx.x]; ss = shss[threadIdx.x];
        #pragma unroll
        for (int o = 4; o > 0; o >>= 1) {
            s  += __shfl_xor_sync(0xffu, s,  o);
            ss += __shfl_xor_sync(0xffu, ss, o);
        }
        if (threadIdx.x == 0) { atomicAdd(out, s); atomicAdd(out + 1, ss); }
    }
}

// graph_norm apply. MODE 0: fp32 out; MODE 1: fp16 out.
template <int MODE>
__global__ void k_norm(const float* __restrict__ x, void* __restrict__ y,
                       const float* __restrict__ w, const float* __restrict__ b,
                       const float* __restrict__ st, int DmaskV, int n4, float invn) {
    int i = blockIdx.x * blockDim.x + threadIdx.x;
    if (i >= n4) return;
    float mu  = st[0] * invn;
    float var = st[1] * invn - mu * mu;
    float inv = 1.f / (sqrtf(fmaxf(var, 0.f)) + 1e-5f);
    int c = i & DmaskV;
    float4 xv = reinterpret_cast<const float4*>(x)[i];
    float4 wv = reinterpret_cast<const float4*>(w)[c];
    float4 bv = reinterpret_cast<const float4*>(b)[c];
    float4 r;
    r.x = (xv.x - mu) * inv * wv.x + bv.x;
    r.y = (xv.y - mu) * inv * wv.y + bv.y;
    r.z = (xv.z - mu) * inv * wv.z + bv.z;
    r.w = (xv.w - mu) * inv * wv.w + bv.w;
    if (MODE == 0) reinterpret_cast<float4*>(y)[i] = r;
    else           reinterpret_cast<uint2*>(y)[i] = pack4h(r);
}

// ---------------------------------------------------------------------------
// Unified fp16 tensor GEMM (xl/xr, classifier). EPI: 1 +bias fp32 (+stats),
// 4 +bias half out.
// ---------------------------------------------------------------------------
template<int BN, int WROWS, int WCOLS, int EPI>
__global__ void __launch_bounds__(256, 2)
k_hgemm(const __half* __restrict__ A, const __half* __restrict__ W,
        const float* __restrict__ bias, const __half* __restrict__ res,
        float* __restrict__ C, float* __restrict__ stats_out, int M, int Nn, int K)
{
    constexpr int BM = 128, BKh = 64, LDW = 36, STAGES = 3;
    constexpr int MF = BM / (WROWS * 16);
    constexpr int NF = BN / (WCOLS * 8);
    constexpr int A_CP = (BM * BKh / 8) / 256;
    constexpr int B_CP = (BN * BKh / 8) / 256;

    extern __shared__ float sh[];
    unsigned* As = reinterpret_cast<unsigned*>(sh);
    unsigned* Bs = As + STAGES * BM * LDW;

    const int tid = threadIdx.x;
    const int wid = tid >> 5, lane = tid & 31;
    const int wm = wid / WCOLS, wn = wid % WCOLS;
    const int g = lane >> 2, tg = lane & 3;
    const long m0 = (long)blockIdx.y * BM;
    const int  n0 = blockIdx.x * BN;

    auto issue = [&](int stage, int kk) {
        #pragma unroll
        for (int i = 0; i < A_CP; i++) {
            int idx = tid + i * 256;
            int r = idx >> 3, c8 = idx & 7;
            cp16(&As[stage * BM * LDW + r * LDW + c8 * 4],
                 A + (m0 + r) * K + kk + c8 * 8);
        }
        #pragma unroll
        for (int i = 0; i < B_CP; i++) {
            int idx = tid + i * 256;
            int r = idx >> 3, c8 = idx & 7;
            cp16(&Bs[stage * BN * LDW + r * LDW + c8 * 4],
                 W + (long)(n0 + r) * K + kk + c8 * 8);
        }
        CP_COMMIT();
    };

    const int NT = K / BKh;
    issue(0, 0);
    if (1 < NT) issue(1, BKh); else CP_COMMIT();

    float acc[MF][NF][4] = {};
    for (int kt = 0; kt < NT; kt++) {
        CP_WAIT1();
        __syncthreads();
        if (kt + STAGES - 1 < NT)
            issue((kt + STAGES - 1) % STAGES, (kt + STAGES - 1) * BKh);
        else
            CP_COMMIT();
        const unsigned* Asb = As + (kt % STAGES) * BM * LDW;
        const unsigned* Bsb = Bs + (kt % STAGES) * BN * LDW;
        #pragma unroll
        for (int k16 = 0; k16 < 4; k16++) {
            unsigned af[MF][4], bf[NF][2];
            #pragma unroll
            for (int i = 0; i < MF; i++) {
                int r = wm * (MF * 16) + i * 16 + g;
                const unsigned* p = Asb + r * LDW + k16 * 8;
                af[i][0] = p[tg];
                af[i][1] = p[8 * LDW + tg];
                af[i][2] = p[tg + 4];
                af[i][3] = p[8 * LDW + tg + 4];
            }
            #pragma unroll
            for (int j = 0; j < NF; j++) {
                int c = wn * (NF * 8) + j * 8 + g;
                const unsigned* p = Bsb + c * LDW + k16 * 8;
                bf[j][0] = p[tg];
                bf[j][1] = p[tg + 4];
            }
            #pragma unroll
            for (int i = 0; i < MF; i++)
                #pragma unroll
                for (int j = 0; j < NF; j++)
                    MMA_F16(acc[i][j], af[i][0], af[i][1], af[i][2], af[i][3],
                            bf[j][0], bf[j][1]);
        }
    }

    float s = 0.f, ss = 0.f;
    #pragma unroll
    for (int i = 0; i < MF; i++) {
        long mA = m0 + wm * (MF * 16) + i * 16 + g;
        long mB = mA + 8;
        #pragma unroll
        for (int j = 0; j < NF; j++) {
            int c = n0 + wn * (NF * 8) + j * 8 + tg * 2;
            float b0 = bias[c], b1 = bias[c + 1];
            float v0 = acc[i][j][0] + b0, v1 = acc[i][j][1] + b1;
            float v2 = acc[i][j][2] + b0, v3 = acc[i][j][3] + b1;
            if (EPI == 4) {
                __half* Ch = reinterpret_cast<__half*>(C);
                *reinterpret_cast<__half2*>(Ch + mA * Nn + c) =
                    __floats2half2_rn(v0, v1);
                *reinterpret_cast<__half2*>(Ch + mB * Nn + c) =
                    __floats2half2_rn(v2, v3);
                continue;
            }
            reinterpret_cast<float2*>(C + mA * Nn + c)[0] = make_float2(v0, v1);
            reinterpret_cast<float2*>(C + mB * Nn + c)[0] = make_float2(v2, v3);
            s  += v0 + v1 + v2 + v3;
            ss += v0 * v0 + v1 * v1 + v2 * v2 + v3 * v3;
        }
    }
    if (EPI != 4 && stats_out != nullptr) {
        #pragma unroll
        for (int o = 16; o > 0; o >>= 1) {
            s  += __shfl_xor_sync(0xffffffffu, s,  o);
            ss += __shfl_xor_sync(0xffffffffu, ss, o);
        }
        __syncthreads();
        float* red = sh;
        if (lane == 0) { red[wid] = s; red[8 + wid] = ss; }
        __syncthreads();
        if (tid == 0) {
            float ts = 0.f, tss = 0.f;
            #pragma unroll
            for (int w = 0; w < 8; w++) { ts += red[w]; tss += red[8 + w]; }
            atomicAdd(stats_out, ts);
            atomicAdd(stats_out + 1, tss);
        }
    }
}

// ---------------------------------------------------------------------------
// Fused MLP: r2 = relu(n1@W1^T + b1)@W2^T + b2 + n1, hid never in DRAM.
// CTA: 64 rows, 4 warps x 16 rows; chunk BC=64 hid cols; fragment-repack
// (GEMM1 C -> GEMM2 A) in registers. Fused stats reduction.
// ---------------------------------------------------------------------------
__global__ void __launch_bounds__(128, 2)
k_fused_mlp(const __half* __restrict__ n1, const __half* __restrict__ W1,
            const float* __restrict__ b1, const __half* __restrict__ W2,
            const float* __restrict__ b2, float* __restrict__ r2out,
            float* __restrict__ stats_out)
{
    constexpr int LD1 = 68;    // words/row for 128-half rows (64+4 pad)
    constexpr int LD2 = 36;    // words/row for 64-half rows
    constexpr int N1W = 64 * LD1;           // n1 tile words
    constexpr int W1W = 64 * LD1;           // W1 chunk words
    constexpr int W2W = 128 * LD2;          // W2 chunk words

    extern __shared__ float sh[];
    unsigned* n1s = reinterpret_cast<unsigned*>(sh);
    unsigned* w1s = n1s + N1W;              // [2][64][LD1]
    unsigned* w2s = w1s + 2 * W1W;          // [2][128][LD2]

    const int tid = threadIdx.x;
    const int wid = tid >> 5, lane = tid & 31;
    const int g = lane >> 2, tg = lane & 3;
    const long m0 = (long)blockIdx.x * 64;
    const int row = wid * 16 + g;           // warp-local top row (and row+8)

    auto issueW = [&](int buf, int kc) {
        #pragma unroll
        for (int i = 0; i < 8; i++) {       // W1: 64 rows x 16 chunks
            int idx = tid + i * 128;
            int r = idx >> 4, c16 = idx & 15;
            cp16(&w1s[buf * W1W + r * LD1 + c16 * 4],
                 W1 + (long)(kc + r) * 128 + c16 * 8);
        }
        #pragma unroll
        for (int i = 0; i < 8; i++) {       // W2: 128 rows x 8 chunks
            int idx = tid + i * 128;
            int r = idx >> 3, c8 = idx & 7;
            cp16(&w2s[buf * W2W + r * LD2 + c8 * 4],
                 W2 + (long)r * 2048 + kc + c8 * 8);
        }
        CP_COMMIT();
    };

    // n1 tile (group 0 together with chunk 0)
    #pragma unroll
    for (int i = 0; i < 8; i++) {
        int idx = tid + i * 128;
        int r = idx >> 4, c16 = idx & 15;
        cp16(&n1s[r * LD1 + c16 * 4], n1 + (m0 + r) * 128 + c16 * 8);
    }
    issueW(0, 0);
    issueW(1, 64);

    float acc2[16][4] = {};
    const int NT = 2048 / 64;
    for (int kt = 0; kt < NT; kt++) {
        CP_WAIT1();
        __syncthreads();
        const unsigned* W1b = w1s + (kt & 1) * W1W;
        const unsigned* W2b = w2s + (kt & 1) * W2W;

        // A1 fragments from n1 tile (K=128 -> 8 k16 steps)
        unsigned a1f[8][4];
        #pragma unroll
        for (int t = 0; t < 8; t++) {
            const unsigned* p = n1s + row * LD1 + t * 8;
            a1f[t][0] = p[tg];
            a1f[t][1] = p[8 * LD1 + tg];
            a1f[t][2] = p[tg + 4];
            a1f[t][3] = p[8 * LD1 + tg + 4];
        }
        // GEMM1: hid chunk (16 rows x 64 cols per warp), relu+bias, pack
        unsigned hp[8][2];
        #pragma unroll
        for (int j = 0; j < 8; j++) {
            float acc1[4] = {0.f, 0.f, 0.f, 0.f};
            #pragma unroll
            for (int t = 0; t < 8; t++) {
                const unsigned* p = W1b + (8 * j + g) * LD1 + t * 8;
                MMA_F16(acc1, a1f[t][0], a1f[t][1], a1f[t][2], a1f[t][3],
                        p[tg], p[tg + 4]);
            }
            float2 bb = reinterpret_cast<const float2*>(b1 + kt * 64 + 8 * j + 2 * tg)[0];
            hp[j][0] = packh2(fmaxf(acc1[0] + bb.x, 0.f), fmaxf(acc1[1] + bb.y, 0.f));
            hp[j][1] = packh2(fmaxf(acc1[2] + bb.x, 0.f), fmaxf(acc1[3] + bb.y, 0.f));
        }
        // GEMM2: A frag t2 = {hp[2t2][0], hp[2t2][1], hp[2t2+1][0], hp[2t2+1][1]}
        #pragma unroll
        for (int j2 = 0; j2 < 16; j2++) {
            #pragma unroll
            for (int t2 = 0; t2 < 4; t2++) {
                const unsigned* p = W2b + (8 * j2 + g) * LD2 + t2 * 8;
                MMA_F16(acc2[j2], hp[2 * t2][0], hp[2 * t2][1],
                        hp[2 * t2 + 1][0], hp[2 * t2 + 1][1],
                        p[tg], p[tg + 4]);
            }
        }
        __syncthreads();
        if (kt + 2 < NT) issueW(kt & 1, (kt + 2) * 64);
        else             CP_COMMIT();
    }

    // epilogue: + b2 + n1 residual (from smem tile), write r2, fused stats
    float s = 0.f, ss = 0.f;
    long mA = m0 + row, mB = mA + 8;
    #pragma unroll
    for (int j2 = 0; j2 < 16; j2++) {
        int c = 8 * j2 + 2 * tg;
        float b0 = b2[c], b1v = b2[c + 1];
        unsigned uA = n1s[row * LD1 + 4 * j2 + tg];
        unsigned uB = n1s[(row + 8) * LD1 + 4 * j2 + tg];
        float2 rA = __half22float2(*reinterpret_cast<__half2*>(&uA));
        float2 rB = __half22float2(*reinterpret_cast<__half2*>(&uB));
        float v0 = acc2[j2][0] + b0 + rA.x;
        float v1 = acc2[j2][1] + b1v + rA.y;
        float v2 = acc2[j2][2] + b0 + rB.x;
        float v3 = acc2[j2][3] + b1v + rB.y;
        reinterpret_cast<float2*>(r2out + mA * 128 + c)[0] = make_float2(v0, v1);
        reinterpret_cast<float2*>(r2out + mB * 128 + c)[0] = make_float2(v2, v3);
        s  += v0 + v1 + v2 + v3;
        ss += v0 * v0 + v1 * v1 + v2 * v2 + v3 * v3;
    }
    #pragma unroll
    for (int o = 16; o > 0; o >>= 1) {
        s  += __shfl_xor_sync(0xffffffffu, s,  o);
        ss += __shfl_xor_sync(0xffffffffu, ss, o);
    }
    __syncthreads();
    float* red = sh;
    if (lane == 0) { red[wid] = s; red[4 + wid] = ss; }
    __syncthreads();
    if (tid == 0) {
        float ts = 0.f, tss = 0.f;
        #pragma unroll
        for (int w = 0; w < 4; w++) { ts += red[w]; tss += red[4 + w]; }
        atomicAdd(stats_out, ts);
        atomicAdd(stats_out + 1, tss);
    }
}

// ---------------------------------------------------------------------------
// ef GEMM (tf32) + fused attention score epilogue (xl/xr fp16).
// ---------------------------------------------------------------------------
__global__ void __launch_bounds__(256, 2)
k_gemm_score(const float* __restrict__ A, const float* __restrict__ W,
             const float* __restrict__ att, const int* __restrict__ ei,
             int ebase, int E)
{
    constexpr int BM = 128, BN = 128, BK = 32, LDA = BK + 4;
    constexpr int MF = 4, NF = 4;

    extern __shared__ float shf[];
    float* As = shf;
    float* Bs = shf + BM * LDA;
    float* srow = shf;

    const int tid = threadIdx.x;
    const int wid = tid >> 5, lane = tid & 31;
    const int wm = wid >> 2, wn = wid & 3;
    const int g = lane >> 2, tg = lane & 3;
    const long m0 = (long)blockIdx.y * BM;
    const int  n0 = blockIdx.x * BN;

    #pragma unroll
    for (int t = 0; t < 4; t++) {
        int idx = tid + t * 256;
        int r = idx >> 3, c4 = idx & 7;
        reinterpret_cast<float4*>(&As[r * LDA + c4 * 4])[0] =
            reinterpret_cast<const float4*>(A + (m0 + r) * BK)[c4];
        reinterpret_cast<float4*>(&Bs[r * LDA + c4 * 4])[0] =
            reinterpret_cast<const float4*>(W + (long)(n0 + r) * BK)[c4];
    }
    __syncthreads();

    float acc[MF][NF][4] = {};
    const unsigned* Asu = reinterpret_cast<const unsigned*>(As);
    const unsigned* Bsu = reinterpret_cast<const unsigned*>(Bs);
    #pragma unroll
    for (int k8 = 0; k8 < 4; k8++) {
        unsigned af[MF][4], bf[NF][2];
        #pragma unroll
        for (int i = 0; i < MF; i++) {
            int r = wm * 64 + i * 16 + g;
            const unsigned* p = Asu + r * LDA + k8 * 8;
            af[i][0] = p[tg];
            af[i][1] = p[8 * LDA + tg];
            af[i][2] = p[tg + 4];
            af[i][3] = p[8 * LDA + tg + 4];
        }
        #pragma unroll
        for (int j = 0; j < NF; j++) {
            int c = wn * 32 + j * 8 + g;
            const unsigned* p = Bsu + c * LDA + k8 * 8;
            bf[j][0] = p[tg];
            bf[j][1] = p[tg + 4];
        }
        #pragma unroll
        for (int i = 0; i < MF; i++)
            #pragma unroll
            for (int j = 0; j < NF; j++) {
                asm volatile(
                    "mma.sync.aligned.m16n8k8.row.col.f32.tf32.tf32.f32 "
                    "{%0,%1,%2,%3}, {%4,%5,%6,%7}, {%8,%9}, {%0,%1,%2,%3};\n"
                    : "+f"(acc[i][j][0]), "+f"(acc[i][j][1]),
                      "+f"(acc[i][j][2]), "+f"(acc[i][j][3])
                    : "r"(af[i][0]), "r"(af[i][1]), "r"(af[i][2]), "r"(af[i][3]),
                      "r"(bf[j][0]), "r"(bf[j][1]));
            }
    }

    float part[MF][2] = {};
    #pragma unroll
    for (int i = 0; i < MF; i++) {
        int rA = wm * 64 + i * 16 + g;
        int rB = rA + 8;
        int geA = ebase + (int)m0 + rA;
        int geB = ebase + (int)m0 + rB;
        int sA = (geA < E) ? ei[geA] : (geA - E);
        int dA = (geA < E) ? ei[E + geA] : (geA - E);
        int sB = (geB < E) ? ei[geB] : (geB - E);
        int dB = (geB < E) ? ei[E + geB] : (geB - E);
        const __half* xlA = g_xlh + (long)sA * 512 + n0;
        const __half* xrA = g_xrh + (long)dA * 512 + n0;
        const __half* xlB = g_xlh + (long)sB * 512 + n0;
        const __half* xrB = g_xrh + (long)dB * 512 + n0;
        #pragma unroll
        for (int j = 0; j < NF; j++) {
            int c = wn * 32 + j * 8 + tg * 2;
            float2 a0 = reinterpret_cast<const float2*>(att + n0 + c)[0];
            float2 lA = __half22float2(*reinterpret_cast<const __half2*>(xlA + c));
            float2 rAv= __half22float2(*reinterpret_cast<const __half2*>(xrA + c));
            float2 lB = __half22float2(*reinterpret_cast<const __half2*>(xlB + c));
            float2 rBv= __half22float2(*reinterpret_cast<const __half2*>(xrB + c));
            float z0 = acc[i][j][0] + lA.x + rAv.x; z0 = z0 > 0.f ? z0 : 0.2f * z0;
            float z1 = acc[i][j][1] + lA.y + rAv.y; z1 = z1 > 0.f ? z1 : 0.2f * z1;
            float z2 = acc[i][j][2] + lB.x + rBv.x; z2 = z2 > 0.f ? z2 : 0.2f * z2;
            float z3 = acc[i][j][3] + lB.y + rBv.y; z3 = z3 > 0.f ? z3 : 0.2f * z3;
            part[i][0] += z0 * a0.x + z1 * a0.y;
            part[i][1] += z2 * a0.x + z3 * a0.y;
        }
    }
    #pragma unroll
    for (int i = 0; i < MF; i++) {
        #pragma unroll
        for (int o = 1; o <= 2; o <<= 1) {
            part[i][0] += __shfl_xor_sync(0xffffffffu, part[i][0], o);
            part[i][1] += __shfl_xor_sync(0xffffffffu, part[i][1], o);
        }
    }
    __syncthreads();
    if (tg == 0) {
        #pragma unroll
        for (int i = 0; i < MF; i++) {
            int rA = wm * 64 + i * 16 + g;
            srow[wn * 128 + rA]     = part[i][0];
            srow[wn * 128 + rA + 8] = part[i][1];
        }
    }
    __syncthreads();
    if (tid < 128) {
        float s = srow[tid] + srow[128 + tid] + srow[256 + tid] + srow[384 + tid];
        int ge = ebase + (int)m0 + tid;
        int d  = (ge < E) ? ei[E + ge] : (ge - E);
        int h  = blockIdx.x;
        g_score[(long)ge * 4 + h] = s;
        atomicMax(&g_smax[d * 4 + h], f_enc(s));
    }
}

// ---- edge-side kernels ----------------------------------------------------
__global__ void k_degsum(const float* __restrict__ edge_attr,
                         const int* __restrict__ ei, int E) {
    int i = blockIdx.x * blockDim.x + threadIdx.x;
    if (i >= E * 8) return;
    int e = i >> 3, c4 = i & 7;
    int dst = ei[E + e];
    float4 v = reinterpret_cast<const float4*>(edge_attr + (long)e * 32)[c4];
    atomicAdd(reinterpret_cast<float4*>(&g_easum[dst * 32 + c4 * 4]), v);
    if (c4 == 0) atomicAdd(&g_deg[dst], 1.f);
}

__global__ void k_eamean(int N) {
    int i = blockIdx.x * blockDim.x + threadIdx.x;
    if (i >= N * 32) return;
    int nid = i >> 5;
    float d = fmaxf(g_deg[nid], 1.f);
    g_ea[i] = tf32f(g_easum[i] / d);
}

__global__ void k_exp(const int* __restrict__ ei, int E, int N) {
    int e = blockIdx.x * blockDim.x + threadIdx.x;
    if (e >= E + N) return;
    int d = (e < E) ? ei[E + e] : (e - E);
    uint4 mk = reinterpret_cast<const uint4*>(g_smax)[d];
    float4 sc = reinterpret_cast<const float4*>(g_score)[e];
    float4 ex;
    ex.x = expf(sc.x - f_dec(mk.x));
    ex.y = expf(sc.y - f_dec(mk.y));
    ex.z = expf(sc.z - f_dec(mk.z));
    ex.w = expf(sc.w - f_dec(mk.w));
    reinterpret_cast<float4*>(g_score)[e] = ex;
    atomicAdd(reinterpret_cast<float4*>(&g_ssum[d * 4]), ex);
}

__global__ void k_agg(const int* __restrict__ ei, float* __restrict__ out_alpha,
                      int E, int N, int write_out) {
    int tot = E + N;
    int e = blockIdx.x * 8 + (threadIdx.x >> 5);
    if (e >= tot) return;
    int l = threadIdx.x & 31;
    int s = (e < E) ? ei[e]     : (e - E);
    int d = (e < E) ? ei[E + e] : (e - E);
    float a0 = __fdividef(g_score[(long)e * 4 + 0], g_ssum[d * 4 + 0]);
    float a1 = __fdividef(g_score[(long)e * 4 + 1], g_ssum[d * 4 + 1]);
    float a2 = __fdividef(g_score[(long)e * 4 + 2], g_ssum[d * 4 + 2]);
    float a3 = __fdividef(g_score[(long)e * 4 + 3], g_ssum[d * 4 + 3]);
    if (write_out && l < 4) {
        float a = (l == 0) ? a0 : (l == 1) ? a1 : (l == 2) ? a2 : a3;
        out_alpha[(long)e * 4 + l] = a;
    }
    a0 *= 0.25f; a1 *= 0.25f; a2 *= 0.25f; a3 *= 0.25f;
    const uint2* xl2 = reinterpret_cast<const uint2*>(g_xlh + (long)s * 512);
    float4 r = {0.f, 0.f, 0.f, 0.f};
    float av[4] = {a0, a1, a2, a3};
    #pragma unroll
    for (int h = 0; h < 4; h++) {
        uint2 hu = xl2[h * 32 + l];
        float2 v01 = __half22float2(*reinterpret_cast<__half2*>(&hu.x));
        float2 v23 = __half22float2(*reinterpret_cast<__half2*>(&hu.y));
        r.x += av[h] * v01.x;
        r.y += av[h] * v01.y;
        r.z += av[h] * v23.x;
        r.w += av[h] * v23.y;
    }
    atomicAdd(reinterpret_cast<float4*>(g_agg + d * 128 + 4 * l), r);
}

// ---------------------------------------------------------------------------
static inline int G(int n) { return (n + 255) / 256; }

extern "C" void kernel_launch(void* const* d_in, const int* in_sizes, int n_in,
                              void* d_out, int out_size) {
    const float* x         = (const float*)d_in[0];
    const int*   ei        = (const int*)  d_in[1];
    const float* edge_attr = (const float*)d_in[2];
    const float* Wl  = (const float*)d_in[4];
    const float* bl  = (const float*)d_in[5];
    const float* Wr  = (const float*)d_in[6];
    const float* br  = (const float*)d_in[7];
    const float* We  = (const float*)d_in[8];
    const float* att = (const float*)d_in[9];
    const float* gbn = (const float*)d_in[10];
    const float* W1  = (const float*)d_in[11];
    const float* b1  = (const float*)d_in[12];
    const float* W2  = (const float*)d_in[13];
    const float* b2  = (const float*)d_in[14];
    const float* Wc  = (const float*)d_in[15];
    const float* bc  = (const float*)d_in[16];
    const float* nw0 = (const float*)d_in[17];
    const float* nb0 = (const float*)d_in[18];
    const float* nw1 = (const float*)d_in[19];
    const float* nb1 = (const float*)d_in[20];
    const float* nw2 = (const float*)d_in[21];
    const float* nb2 = (const float*)d_in[22];
    const float* nw3 = (const float*)d_in[23];
    const float* nb3 = (const float*)d_in[24];

    int N = in_sizes[0] / 128;
    int E = in_sizes[1] / 2;
    int TOT = E + N;
    float* out = (float*)d_out;
    int write_alpha = (out_size >= N * 64 + TOT * 4) ? 1 : 0;
    float* out_alpha = out + (size_t)N * 64;

    float *r1, *r2, *ea, *eat, *cls, *stats, *we;
    __half *h0h, *n1h, *n2h, *wlh, *wrh, *w1h, *w2h, *wch, *xlh, *xrh;
    cudaGetSymbolAddress((void**)&h0h,   g_h0h);
    cudaGetSymbolAddress((void**)&r1,    g_r1);
    cudaGetSymbolAddress((void**)&n1h,   g_n1h);
    cudaGetSymbolAddress((void**)&r2,    g_r2);
    cudaGetSymbolAddress((void**)&n2h,   g_n2h);
    cudaGetSymbolAddress((void**)&ea,    g_ea);
    cudaGetSymbolAddress((void**)&eat,   g_eat);
    cudaGetSymbolAddress((void**)&cls,   g_cls);
    cudaGetSymbolAddress((void**)&stats, g_stats);
    cudaGetSymbolAddress((void**)&wlh,   g_wlh);
    cudaGetSymbolAddress((void**)&wrh,   g_wrh);
    cudaGetSymbolAddress((void**)&we,    g_we);
    cudaGetSymbolAddress((void**)&w1h,   g_w1h);
    cudaGetSymbolAddress((void**)&w2h,   g_w2h);
    cudaGetSymbolAddress((void**)&wch,   g_wch);
    cudaGetSymbolAddress((void**)&xlh,   g_xlh);
    cudaGetSymbolAddress((void**)&xrh,   g_xrh);

    const int SMH128 = 3 * (128 + 128) * 36 * 4;            // 110592 B
    const int SMH64  = 3 * (128 +  64) * 36 * 4;            // 82944 B
    const int SMSC   = (128 * 36 + 128 * 36) * 4;           // 36864 B
    const int SMF    = (64*68 + 2*64*68 + 2*128*36) * 4;    // 89088 B
    cudaFuncSetAttribute(k_hgemm<128,2,4,4>, cudaFuncAttributeMaxDynamicSharedMemorySize, SMH128);
    cudaFuncSetAttribute(k_hgemm<64,4,2,1>,  cudaFuncAttributeMaxDynamicSharedMemorySize, SMH64);
    cudaFuncSetAttribute(k_fused_mlp,        cudaFuncAttributeMaxDynamicSharedMemorySize, SMF);
    cudaFuncSetAttribute(k_gemm_score,       cudaFuncAttributeMaxDynamicSharedMemorySize, SMSC);

    k_init<<<G(N * 128), 256>>>(N);
    int nround = E * 8 + 16384 + 16384 + 4096 + 65536 + 65536 + 2048;
    k_round_all<<<G(nround), 256>>>(edge_attr, Wl, Wr, We, W1, W2, Wc, E);
    k_reduce<<<1024, 256>>>(x, N * 128 / 4, stats + 0);
    k_norm<1><<<G(N * 32), 256>>>(x, h0h, nw0, nb0, stats + 0, 31, N * 32,
                                  1.f / (float)(N * 128));

    // GATv2 linear transforms (launch 5 = profiled)
    k_hgemm<128,2,4,4><<<dim3(4, N/128), 256, SMH128>>>(h0h, wlh, bl, nullptr, (float*)xlh, nullptr, N, 512, 128);
    k_hgemm<128,2,4,4><<<dim3(4, N/128), 256, SMH128>>>(h0h, wrh, br, nullptr, (float*)xrh, nullptr, N, 512, 128);

    k_degsum<<<G(E * 8), 256>>>(edge_attr, ei, E);
    k_eamean<<<G(N * 32), 256>>>(N);

    k_gemm_score<<<dim3(4, E/128), 256, SMSC>>>(eat, we, att, ei, 0, E);
    k_gemm_score<<<dim3(4, N/128), 256, SMSC>>>(ea, we, att, ei, E, E);

    k_exp<<<G(TOT), 256>>>(ei, E, N);
    k_agg<<<(TOT + 7) / 8, 256>>>(ei, out_alpha, E, N, write_alpha);

    k_res_reduce<<<1024, 256>>>(gbn, N * 128 / 4, stats + 2);
    k_norm<1><<<G(N * 32), 256>>>(r1, n1h, nw1, nb1, stats + 2, 31, N * 32,
                                  1.f / (float)(N * 128));

    // fused MLP (hid never in DRAM) with fused stats4
    k_fused_mlp<<<N/64, 128, SMF>>>(n1h, w1h, b1, w2h, b2, r2, stats + 4);

    k_norm<1><<<G(N * 32), 256>>>(r2, n2h, nw2, nb2, stats + 4, 31, N * 32,
                                  1.f / (float)(N * 128));

    // classifier (fp16, fused stats) + graph_norm 3
    k_hgemm<64,4,2,1><<<dim3(1, N/128), 256, SMH64>>>(n2h, wch, bc, nullptr, cls,
                                                      stats + 6, N, 64, 128);
    k_norm<0><<<G(N * 16), 256>>>(cls, out, nw3, nb3, stats + 6, 15, N * 16,
                                  1.f / (float)(N * 64));
}